// round 1
// baseline (speedup 1.0000x reference)
#include <cuda_runtime.h>
#include <cuda_bf16.h>
#include <math.h>

#define B_   2
#define S_   2048
#define D_   4096
#define HQ_  32
#define HKV_ 8
#define HD_  128

// ---------------- scratch (static device globals; no allocations) ----------
__device__ float g_q[(size_t)B_ * HQ_ * S_ * HD_];     // [B,HQ,S,HD]
__device__ float g_k[(size_t)B_ * HKV_ * S_ * HD_];    // [B,HKV,S,HD]
__device__ float g_v[(size_t)B_ * HKV_ * S_ * HD_];    // [B,HKV,S,HD]
__device__ float g_att[(size_t)B_ * S_ * HQ_ * HD_];   // [B,S,HQ,HD]

// ---------------------------------------------------------------------------
// SGEMM (NT): C[m,n] = sum_k A[m,k] * B[n,k]
// A: [M,K] row-major, B: [N,K] row-major. 128x128x16 tile, 8x8 micro-tile.
// head_layout: write C[m, n] to ((b*H + h)*S_ + s)*HD_ + d with
//   b = m / S_, s = m % S_, h = n / HD_, d = n % HD_.
// ---------------------------------------------------------------------------
__global__ __launch_bounds__(256) void sgemm_nt(
    const float* __restrict__ A, const float* __restrict__ Bm,
    float* __restrict__ C, int M, int N, int K, int head_layout, int H)
{
    const int BK = 16;
    __shared__ float As[BK][128 + 4];
    __shared__ float Bs[BK][128 + 4];

    const int tid = threadIdx.x;
    const int bm = blockIdx.y * 128;
    const int bn = blockIdx.x * 128;
    const int ty = tid >> 4;       // 0..15
    const int tx = tid & 15;       // 0..15

    float acc[8][8];
#pragma unroll
    for (int i = 0; i < 8; i++)
#pragma unroll
        for (int j = 0; j < 8; j++) acc[i][j] = 0.f;

    const int lrow = tid >> 2;            // 0..63
    const int lcol = (tid & 3) << 2;      // 0,4,8,12

    const float* Aptr = A + (size_t)(bm + lrow) * K + lcol;
    const float* Bptr = Bm + (size_t)(bn + lrow) * K + lcol;

    for (int k0 = 0; k0 < K; k0 += BK) {
#pragma unroll
        for (int i = 0; i < 2; i++) {
            float4 va = *(const float4*)(Aptr + (size_t)(i * 64) * K + k0);
            As[lcol + 0][lrow + i * 64] = va.x;
            As[lcol + 1][lrow + i * 64] = va.y;
            As[lcol + 2][lrow + i * 64] = va.z;
            As[lcol + 3][lrow + i * 64] = va.w;
            float4 vb = *(const float4*)(Bptr + (size_t)(i * 64) * K + k0);
            Bs[lcol + 0][lrow + i * 64] = vb.x;
            Bs[lcol + 1][lrow + i * 64] = vb.y;
            Bs[lcol + 2][lrow + i * 64] = vb.z;
            Bs[lcol + 3][lrow + i * 64] = vb.w;
        }
        __syncthreads();
#pragma unroll
        for (int k = 0; k < BK; k++) {
            float a[8], b[8];
            float4 a0 = *(const float4*)&As[k][ty * 8];
            float4 a1 = *(const float4*)&As[k][ty * 8 + 4];
            float4 b0 = *(const float4*)&Bs[k][tx * 8];
            float4 b1 = *(const float4*)&Bs[k][tx * 8 + 4];
            a[0] = a0.x; a[1] = a0.y; a[2] = a0.z; a[3] = a0.w;
            a[4] = a1.x; a[5] = a1.y; a[6] = a1.z; a[7] = a1.w;
            b[0] = b0.x; b[1] = b0.y; b[2] = b0.z; b[3] = b0.w;
            b[4] = b1.x; b[5] = b1.y; b[6] = b1.z; b[7] = b1.w;
#pragma unroll
            for (int i = 0; i < 8; i++)
#pragma unroll
                for (int j = 0; j < 8; j++)
                    acc[i][j] += a[i] * b[j];
        }
        __syncthreads();
    }

#pragma unroll
    for (int i = 0; i < 8; i++) {
        int m = bm + ty * 8 + i;
        float4 c0 = make_float4(acc[i][0], acc[i][1], acc[i][2], acc[i][3]);
        float4 c1 = make_float4(acc[i][4], acc[i][5], acc[i][6], acc[i][7]);
        if (!head_layout) {
            float* p = C + (size_t)m * N + bn + tx * 8;
            *(float4*)p = c0;
            *(float4*)(p + 4) = c1;
        } else {
            int b = m >> 11;            // m / S_
            int s = m & (S_ - 1);
            int n0 = bn + tx * 8;
            int h = n0 >> 7;            // n0 / HD_
            int d = n0 & (HD_ - 1);
            float* p = C + (((size_t)b * H + h) * S_ + s) * HD_ + d;
            *(float4*)p = c0;
            *(float4*)(p + 4) = c1;
        }
    }
}

// ---------------------------------------------------------------------------
// RoPE in place on g_q ([B,HQ,S,HD]) and g_k ([B,HKV,S,HD]).
// pair (2i, 2i+1), angle from freqs[s, i].
// ---------------------------------------------------------------------------
__global__ void rope_kernel(float* __restrict__ q, float* __restrict__ k,
                            const float* __restrict__ fcos,
                            const float* __restrict__ fsin)
{
    long id = (long)blockIdx.x * blockDim.x + threadIdx.x;
    // total = B_ * (HQ_+HKV_) * S_ * (HD_/2)
    int i = (int)(id & 63);
    long t = id >> 6;
    int s = (int)(t & (S_ - 1));
    t >>= 11;
    int hh = (int)(t % (HQ_ + HKV_));
    int b  = (int)(t / (HQ_ + HKV_));
    if (b >= B_) return;

    float c  = fcos[s * (HD_ / 2) + i];
    float sn = fsin[s * (HD_ / 2) + i];

    float* base;
    size_t off;
    if (hh < HQ_) {
        base = q;
        off = (((size_t)b * HQ_ + hh) * S_ + s) * HD_ + 2 * i;
    } else {
        base = k;
        off = (((size_t)b * HKV_ + (hh - HQ_)) * S_ + s) * HD_ + 2 * i;
    }
    float2 v = *(float2*)(base + off);
    float x0 = v.x, x1 = v.y;
    v.x = x0 * c - x1 * sn;
    v.y = x0 * sn + x1 * c;
    *(float2*)(base + off) = v;
}

// ---------------------------------------------------------------------------
// Flash attention, fp32, no mask. 64 queries x 64 keys per tile, HD=128.
// Block: 256 threads. Grid: (S/64, B*HQ).
// smem: Qs/Ks/Vs [64][132], Ps [64][68]  -> 118784 bytes (dynamic).
// Thread (ty=tid/16, tx=tid&15):
//   phase1 scores: rows ty*4+r, cols tx+16*c
//   phase2 PV:     rows ty*4+r, cols tx*8..tx*8+7
// ---------------------------------------------------------------------------
#define KSTR 132
#define PSTR 68
#define ATT_SMEM ((3 * 64 * KSTR + 64 * PSTR) * 4)

__global__ __launch_bounds__(256) void attn_kernel(
    const float* __restrict__ Q, const float* __restrict__ Kg,
    const float* __restrict__ Vg, float* __restrict__ O)
{
    extern __shared__ float sm[];
    float* Qs = sm;
    float* Ks = Qs + 64 * KSTR;
    float* Vs = Ks + 64 * KSTR;
    float* Ps = Vs + 64 * KSTR;

    const int bh = blockIdx.y;
    const int b = bh >> 5;          // / HQ_
    const int h = bh & (HQ_ - 1);
    const int kvh = h >> 2;         // GQA: REPEAT = 4
    const int q0 = blockIdx.x * 64;
    const int tid = threadIdx.x;
    const int ty = tid >> 4;
    const int tx = tid & 15;

    const float* Qbase = Q + (((size_t)b * HQ_ + h) * S_ + q0) * HD_;
    const float* Kbase = Kg + (((size_t)b * HKV_ + kvh) * S_) * HD_;
    const float* Vbase = Vg + (((size_t)b * HKV_ + kvh) * S_) * HD_;

    // stage Q tile
    {
        int r = tid >> 2;
        int c4 = (tid & 3) * 4;
#pragma unroll
        for (int it = 0; it < 8; it++) {
            float4 v = *(const float4*)(Qbase + (size_t)r * HD_ + c4 + it * 16);
            *(float4*)(Qs + r * KSTR + c4 + it * 16) = v;
        }
    }

    float m[4], l[4], o[4][8];
#pragma unroll
    for (int r = 0; r < 4; r++) {
        m[r] = -1e30f;
        l[r] = 0.f;
#pragma unroll
        for (int c = 0; c < 8; c++) o[r][c] = 0.f;
    }

    const float scale = 0.08838834764831845f;  // 1/sqrt(128)

    for (int t0 = 0; t0 < S_; t0 += 64) {
        __syncthreads();  // protect Ks/Vs/Ps reuse (and ensure Qs staged, iter 0)
        {
            int r = tid >> 2;
            int c4 = (tid & 3) * 4;
#pragma unroll
            for (int it = 0; it < 8; it++) {
                *(float4*)(Ks + r * KSTR + c4 + it * 16) =
                    *(const float4*)(Kbase + (size_t)(t0 + r) * HD_ + c4 + it * 16);
                *(float4*)(Vs + r * KSTR + c4 + it * 16) =
                    *(const float4*)(Vbase + (size_t)(t0 + r) * HD_ + c4 + it * 16);
            }
        }
        __syncthreads();

        // ---- phase 1: S = Q K^T for this tile ----
        float sc[4][4];
#pragma unroll
        for (int r = 0; r < 4; r++)
#pragma unroll
            for (int c = 0; c < 4; c++) sc[r][c] = 0.f;

#pragma unroll 4
        for (int d = 0; d < HD_; d += 4) {
            float4 kk0 = *(const float4*)(Ks + (tx)*KSTR + d);
            float4 kk1 = *(const float4*)(Ks + (tx + 16) * KSTR + d);
            float4 kk2 = *(const float4*)(Ks + (tx + 32) * KSTR + d);
            float4 kk3 = *(const float4*)(Ks + (tx + 48) * KSTR + d);
#pragma unroll
            for (int r = 0; r < 4; r++) {
                float4 qq = *(const float4*)(Qs + (ty * 4 + r) * KSTR + d);
                sc[r][0] += qq.x * kk0.x + qq.y * kk0.y + qq.z * kk0.z + qq.w * kk0.w;
                sc[r][1] += qq.x * kk1.x + qq.y * kk1.y + qq.z * kk1.z + qq.w * kk1.w;
                sc[r][2] += qq.x * kk2.x + qq.y * kk2.y + qq.z * kk2.z + qq.w * kk2.w;
                sc[r][3] += qq.x * kk3.x + qq.y * kk3.y + qq.z * kk3.z + qq.w * kk3.w;
            }
        }

        // ---- online softmax (row groups = 16 lanes sharing ty) ----
#pragma unroll
        for (int r = 0; r < 4; r++) {
#pragma unroll
            for (int c = 0; c < 4; c++) sc[r][c] *= scale;
            float mx = fmaxf(fmaxf(sc[r][0], sc[r][1]), fmaxf(sc[r][2], sc[r][3]));
#pragma unroll
            for (int off = 8; off >= 1; off >>= 1)
                mx = fmaxf(mx, __shfl_xor_sync(0xffffffffu, mx, off, 16));
            float mnew = fmaxf(m[r], mx);
            float alpha = __expf(m[r] - mnew);
            float rs = 0.f;
#pragma unroll
            for (int c = 0; c < 4; c++) {
                float p = __expf(sc[r][c] - mnew);
                sc[r][c] = p;
                rs += p;
            }
#pragma unroll
            for (int off = 8; off >= 1; off >>= 1)
                rs += __shfl_xor_sync(0xffffffffu, rs, off, 16);
            l[r] = l[r] * alpha + rs;
            m[r] = mnew;
#pragma unroll
            for (int c = 0; c < 8; c++) o[r][c] *= alpha;
#pragma unroll
            for (int c = 0; c < 4; c++)
                Ps[(ty * 4 + r) * PSTR + tx + 16 * c] = sc[r][c];
        }
        __syncthreads();

        // ---- phase 2: O += P V ----
#pragma unroll 4
        for (int j = 0; j < 64; j++) {
            float4 v0 = *(const float4*)(Vs + j * KSTR + tx * 8);
            float4 v1 = *(const float4*)(Vs + j * KSTR + tx * 8 + 4);
#pragma unroll
            for (int r = 0; r < 4; r++) {
                float p = Ps[(ty * 4 + r) * PSTR + j];
                o[r][0] += p * v0.x;
                o[r][1] += p * v0.y;
                o[r][2] += p * v0.z;
                o[r][3] += p * v0.w;
                o[r][4] += p * v1.x;
                o[r][5] += p * v1.y;
                o[r][6] += p * v1.z;
                o[r][7] += p * v1.w;
            }
        }
    }

    // epilogue: write to g_att [B,S,HQ,HD]
#pragma unroll
    for (int r = 0; r < 4; r++) {
        int s = q0 + ty * 4 + r;
        float inv = 1.0f / l[r];
        float* p = O + (((size_t)b * S_ + s) * HQ_ + h) * HD_ + tx * 8;
        float4 w0 = make_float4(o[r][0] * inv, o[r][1] * inv, o[r][2] * inv, o[r][3] * inv);
        float4 w1 = make_float4(o[r][4] * inv, o[r][5] * inv, o[r][6] * inv, o[r][7] * inv);
        *(float4*)p = w0;
        *(float4*)(p + 4) = w1;
    }
}

// ---------------------------------------------------------------------------
extern "C" void kernel_launch(void* const* d_in, const int* in_sizes, int n_in,
                              void* d_out, int out_size)
{
    const float* x  = (const float*)d_in[0];
    const float* wq = (const float*)d_in[1];
    const float* wk = (const float*)d_in[2];
    const float* wv = (const float*)d_in[3];
    const float* wo = (const float*)d_in[4];
    const float* fc = (const float*)d_in[5];
    const float* fs = (const float*)d_in[6];
    float* out = (float*)d_out;

    float *gq, *gk, *gv, *ga;
    cudaGetSymbolAddress((void**)&gq, g_q);
    cudaGetSymbolAddress((void**)&gk, g_k);
    cudaGetSymbolAddress((void**)&gv, g_v);
    cudaGetSymbolAddress((void**)&ga, g_att);

    const int M = B_ * S_;  // 4096

    // QKV projections (write head-split layouts)
    sgemm_nt<<<dim3((HQ_ * HD_) / 128, M / 128), 256>>>(x, wq, gq, M, HQ_ * HD_, D_, 1, HQ_);
    sgemm_nt<<<dim3((HKV_ * HD_) / 128, M / 128), 256>>>(x, wk, gk, M, HKV_ * HD_, D_, 1, HKV_);
    sgemm_nt<<<dim3((HKV_ * HD_) / 128, M / 128), 256>>>(x, wv, gv, M, HKV_ * HD_, D_, 1, HKV_);

    // RoPE on Q and K
    long npairs = (long)B_ * (HQ_ + HKV_) * S_ * (HD_ / 2);
    rope_kernel<<<(unsigned)((npairs + 255) / 256), 256>>>(gq, gk, fc, fs);

    // attention
    cudaFuncSetAttribute(attn_kernel, cudaFuncAttributeMaxDynamicSharedMemorySize, ATT_SMEM);
    attn_kernel<<<dim3(S_ / 64, B_ * HQ_), 256, ATT_SMEM>>>(gq, gk, gv, ga);

    // output projection -> d_out
    sgemm_nt<<<dim3(D_ / 128, M / 128), 256>>>(ga, wo, out, M, D_, D_, 0, 0);
}

// round 2
// speedup vs baseline: 1.0322x; 1.0322x over previous
#include <cuda_runtime.h>
#include <cuda_bf16.h>
#include <math.h>

#define B_   2
#define S_   2048
#define D_   4096
#define HQ_  32
#define HKV_ 8
#define HD_  128

typedef unsigned long long u64;

// ---------------- packed f32x2 helpers (Blackwell sm_103a) -----------------
__device__ __forceinline__ u64 pack2(float x) {
    u64 r;
    asm("mov.b64 %0, {%1, %1};" : "=l"(r) : "f"(x));
    return r;
}
__device__ __forceinline__ void fma2(u64& d, u64 a, u64 b) {
    asm("fma.rn.f32x2 %0, %1, %2, %0;" : "+l"(d) : "l"(a), "l"(b));
}
__device__ __forceinline__ void mul2(u64& d, u64 a) {
    asm("mul.rn.f32x2 %0, %0, %1;" : "+l"(d) : "l"(a));
}
__device__ __forceinline__ float2 unpack2(u64 v) {
    float2 f;
    asm("mov.b64 {%0, %1}, %2;" : "=f"(f.x), "=f"(f.y) : "l"(v));
    return f;
}

// ---------------- scratch (static device globals; no allocations) ----------
__device__ float g_q[(size_t)B_ * HQ_ * S_ * HD_];     // [B,HQ,S,HD]
__device__ float g_k[(size_t)B_ * HKV_ * S_ * HD_];    // [B,HKV,S,HD]
__device__ float g_v[(size_t)B_ * HKV_ * S_ * HD_];    // [B,HKV,S,HD]
__device__ float g_att[(size_t)B_ * S_ * HQ_ * HD_];   // [B,S,HQ,HD]

// ---------------------------------------------------------------------------
// SGEMM (NT): C[m,n] = sum_k A[m,k] * B[n,k], fp32 with packed f32x2 math.
// A: [M,K] row-major, B: [N,K] row-major. 128x128x16 tile, 8x8 micro-tile.
// head_layout: write C[m, n] to ((b*H + h)*S_ + s)*HD_ + d.
// ---------------------------------------------------------------------------
__global__ __launch_bounds__(256) void sgemm_nt(
    const float* __restrict__ A, const float* __restrict__ Bm,
    float* __restrict__ C, int M, int N, int K, int head_layout, int H)
{
    const int BK = 16;
    __shared__ float As[BK][128 + 4];
    __shared__ float Bs[BK][128 + 4];

    const int tid = threadIdx.x;
    const int bm = blockIdx.y * 128;
    const int bn = blockIdx.x * 128;
    const int ty = tid >> 4;       // 0..15
    const int tx = tid & 15;       // 0..15

    u64 acc2[8][4];
#pragma unroll
    for (int i = 0; i < 8; i++)
#pragma unroll
        for (int j = 0; j < 4; j++) acc2[i][j] = 0ULL;

    const int lrow = tid >> 2;            // 0..63
    const int lcol = (tid & 3) << 2;      // 0,4,8,12

    const float* Aptr = A + (size_t)(bm + lrow) * K + lcol;
    const float* Bptr = Bm + (size_t)(bn + lrow) * K + lcol;

    for (int k0 = 0; k0 < K; k0 += BK) {
#pragma unroll
        for (int i = 0; i < 2; i++) {
            float4 va = *(const float4*)(Aptr + (size_t)(i * 64) * K + k0);
            As[lcol + 0][lrow + i * 64] = va.x;
            As[lcol + 1][lrow + i * 64] = va.y;
            As[lcol + 2][lrow + i * 64] = va.z;
            As[lcol + 3][lrow + i * 64] = va.w;
            float4 vb = *(const float4*)(Bptr + (size_t)(i * 64) * K + k0);
            Bs[lcol + 0][lrow + i * 64] = vb.x;
            Bs[lcol + 1][lrow + i * 64] = vb.y;
            Bs[lcol + 2][lrow + i * 64] = vb.z;
            Bs[lcol + 3][lrow + i * 64] = vb.w;
        }
        __syncthreads();
#pragma unroll
        for (int k = 0; k < BK; k++) {
            float4 a0 = *(const float4*)&As[k][ty * 8];
            float4 a1 = *(const float4*)&As[k][ty * 8 + 4];
            const ulonglong2* pb = (const ulonglong2*)&Bs[k][tx * 8];
            ulonglong2 bb0 = pb[0];
            ulonglong2 bb1 = pb[1];
            u64 b2[4];
            b2[0] = bb0.x; b2[1] = bb0.y; b2[2] = bb1.x; b2[3] = bb1.y;
            u64 ab[8];
            ab[0] = pack2(a0.x); ab[1] = pack2(a0.y);
            ab[2] = pack2(a0.z); ab[3] = pack2(a0.w);
            ab[4] = pack2(a1.x); ab[5] = pack2(a1.y);
            ab[6] = pack2(a1.z); ab[7] = pack2(a1.w);
#pragma unroll
            for (int i = 0; i < 8; i++)
#pragma unroll
                for (int j = 0; j < 4; j++)
                    fma2(acc2[i][j], ab[i], b2[j]);
        }
        __syncthreads();
    }

#pragma unroll
    for (int i = 0; i < 8; i++) {
        int m = bm + ty * 8 + i;
        ulonglong2 c0 = make_ulonglong2(acc2[i][0], acc2[i][1]);
        ulonglong2 c1 = make_ulonglong2(acc2[i][2], acc2[i][3]);
        if (!head_layout) {
            float* p = C + (size_t)m * N + bn + tx * 8;
            *(ulonglong2*)p = c0;
            *(ulonglong2*)(p + 4) = c1;
        } else {
            int b = m >> 11;            // m / S_
            int s = m & (S_ - 1);
            int n0 = bn + tx * 8;
            int h = n0 >> 7;            // n0 / HD_
            int d = n0 & (HD_ - 1);
            float* p = C + (((size_t)b * H + h) * S_ + s) * HD_ + d;
            *(ulonglong2*)p = c0;
            *(ulonglong2*)(p + 4) = c1;
        }
    }
}

// ---------------------------------------------------------------------------
// RoPE in place on g_q ([B,HQ,S,HD]) and g_k ([B,HKV,S,HD]).
// ---------------------------------------------------------------------------
__global__ void rope_kernel(float* __restrict__ q, float* __restrict__ k,
                            const float* __restrict__ fcos,
                            const float* __restrict__ fsin)
{
    long id = (long)blockIdx.x * blockDim.x + threadIdx.x;
    int i = (int)(id & 63);
    long t = id >> 6;
    int s = (int)(t & (S_ - 1));
    t >>= 11;
    int hh = (int)(t % (HQ_ + HKV_));
    int b  = (int)(t / (HQ_ + HKV_));
    if (b >= B_) return;

    float c  = fcos[s * (HD_ / 2) + i];
    float sn = fsin[s * (HD_ / 2) + i];

    float* base;
    size_t off;
    if (hh < HQ_) {
        base = q;
        off = (((size_t)b * HQ_ + hh) * S_ + s) * HD_ + 2 * i;
    } else {
        base = k;
        off = (((size_t)b * HKV_ + (hh - HQ_)) * S_ + s) * HD_ + 2 * i;
    }
    float2 v = *(float2*)(base + off);
    float x0 = v.x, x1 = v.y;
    v.x = x0 * c - x1 * sn;
    v.y = x0 * sn + x1 * c;
    *(float2*)(base + off) = v;
}

// ---------------------------------------------------------------------------
// Flash attention, fp32 with f32x2 math. 64 queries x 64 keys per tile, HD=128.
// Block: 256 threads. Grid: (S/64, B*HQ).
// K tile stored TRANSPOSED in smem (KsT[d][n], stride 66) so adjacent key
// columns pack naturally into f32x2 operands.
// Thread (ty=tid/16, tx=tid&15):
//   phase1 scores: rows ty*4+r, cols {2tx, 2tx+1, 2tx+32, 2tx+33}
//   phase2 PV:     rows ty*4+r, cols tx*8..tx*8+7
// ---------------------------------------------------------------------------
#define KSTR 132
#define KST  66
#define PSTR 68
#define ATT_SMEM ((2 * 64 * KSTR + 128 * KST + 64 * PSTR) * 4)

__global__ __launch_bounds__(256) void attn_kernel(
    const float* __restrict__ Q, const float* __restrict__ Kg,
    const float* __restrict__ Vg, float* __restrict__ O)
{
    extern __shared__ float sm[];
    float* Qs  = sm;                       // [64][KSTR]
    float* KsT = Qs + 64 * KSTR;           // [128][KST]  (transposed K tile)
    float* Vs  = KsT + 128 * KST;          // [64][KSTR]
    float* Ps  = Vs + 64 * KSTR;           // [64][PSTR]

    const int bh = blockIdx.y;
    const int b = bh >> 5;          // / HQ_
    const int h = bh & (HQ_ - 1);
    const int kvh = h >> 2;         // GQA: REPEAT = 4
    const int q0 = blockIdx.x * 64;
    const int tid = threadIdx.x;
    const int ty = tid >> 4;
    const int tx = tid & 15;

    const float* Qbase = Q + (((size_t)b * HQ_ + h) * S_ + q0) * HD_;
    const float* Kbase = Kg + (((size_t)b * HKV_ + kvh) * S_) * HD_;
    const float* Vbase = Vg + (((size_t)b * HKV_ + kvh) * S_) * HD_;

    // stage Q tile
    {
        int r = tid >> 2;
        int c4 = (tid & 3) * 4;
#pragma unroll
        for (int it = 0; it < 8; it++) {
            float4 v = *(const float4*)(Qbase + (size_t)r * HD_ + c4 + it * 16);
            *(float4*)(Qs + r * KSTR + c4 + it * 16) = v;
        }
    }

    float m[4], l[4];
    u64 o2[4][4];
#pragma unroll
    for (int r = 0; r < 4; r++) {
        m[r] = -1e30f;
        l[r] = 0.f;
#pragma unroll
        for (int c = 0; c < 4; c++) o2[r][c] = 0ULL;
    }

    const float scale = 0.08838834764831845f;  // 1/sqrt(128)

    for (int t0 = 0; t0 < S_; t0 += 64) {
        __syncthreads();  // protect KsT/Vs/Ps reuse (and ensure Qs staged, iter 0)
        {
            int n = tid >> 2;
            int c4 = (tid & 3) * 4;
#pragma unroll
            for (int it = 0; it < 8; it++) {
                int d0 = c4 + it * 16;
                float4 kv = *(const float4*)(Kbase + (size_t)(t0 + n) * HD_ + d0);
                KsT[(d0 + 0) * KST + n] = kv.x;
                KsT[(d0 + 1) * KST + n] = kv.y;
                KsT[(d0 + 2) * KST + n] = kv.z;
                KsT[(d0 + 3) * KST + n] = kv.w;
                *(float4*)(Vs + n * KSTR + d0) =
                    *(const float4*)(Vbase + (size_t)(t0 + n) * HD_ + d0);
            }
        }
        __syncthreads();

        // ---- phase 1: S = Q K^T for this tile (f32x2) ----
        u64 s2[4][2];
#pragma unroll
        for (int r = 0; r < 4; r++) { s2[r][0] = 0ULL; s2[r][1] = 0ULL; }

#pragma unroll 4
        for (int d4 = 0; d4 < HD_; d4 += 4) {
            float qa[4][4];
#pragma unroll
            for (int r = 0; r < 4; r++) {
                float4 t = *(const float4*)(Qs + (ty * 4 + r) * KSTR + d4);
                qa[r][0] = t.x; qa[r][1] = t.y; qa[r][2] = t.z; qa[r][3] = t.w;
            }
#pragma unroll
            for (int dd = 0; dd < 4; dd++) {
                u64 k01 = *(const u64*)(KsT + (d4 + dd) * KST + 2 * tx);
                u64 k23 = *(const u64*)(KsT + (d4 + dd) * KST + 2 * tx + 32);
#pragma unroll
                for (int r = 0; r < 4; r++) {
                    u64 qb = pack2(qa[r][dd]);
                    fma2(s2[r][0], qb, k01);
                    fma2(s2[r][1], qb, k23);
                }
            }
        }

        // ---- online softmax (row groups = 16 lanes sharing ty) ----
#pragma unroll
        for (int r = 0; r < 4; r++) {
            float2 p0 = unpack2(s2[r][0]);
            float2 p1 = unpack2(s2[r][1]);
            float sc0 = p0.x * scale, sc1 = p0.y * scale;
            float sc2v = p1.x * scale, sc3 = p1.y * scale;
            float mx = fmaxf(fmaxf(sc0, sc1), fmaxf(sc2v, sc3));
#pragma unroll
            for (int off = 8; off >= 1; off >>= 1)
                mx = fmaxf(mx, __shfl_xor_sync(0xffffffffu, mx, off, 16));
            float mnew = fmaxf(m[r], mx);
            float alpha = __expf(m[r] - mnew);
            float e0 = __expf(sc0 - mnew);
            float e1 = __expf(sc1 - mnew);
            float e2 = __expf(sc2v - mnew);
            float e3 = __expf(sc3 - mnew);
            float rs = e0 + e1 + e2 + e3;
#pragma unroll
            for (int off = 8; off >= 1; off >>= 1)
                rs += __shfl_xor_sync(0xffffffffu, rs, off, 16);
            l[r] = l[r] * alpha + rs;
            m[r] = mnew;
            u64 ap = pack2(alpha);
#pragma unroll
            for (int c = 0; c < 4; c++) mul2(o2[r][c], ap);
            int row = (ty * 4 + r) * PSTR;
            Ps[row + 2 * tx]      = e0;
            Ps[row + 2 * tx + 1]  = e1;
            Ps[row + 2 * tx + 32] = e2;
            Ps[row + 2 * tx + 33] = e3;
        }
        __syncthreads();

        // ---- phase 2: O += P V (f32x2) ----
#pragma unroll 4
        for (int j = 0; j < 64; j++) {
            const ulonglong2* pv = (const ulonglong2*)(Vs + j * KSTR + tx * 8);
            ulonglong2 v0 = pv[0];
            ulonglong2 v1 = pv[1];
#pragma unroll
            for (int r = 0; r < 4; r++) {
                u64 pb = pack2(Ps[(ty * 4 + r) * PSTR + j]);
                fma2(o2[r][0], pb, v0.x);
                fma2(o2[r][1], pb, v0.y);
                fma2(o2[r][2], pb, v1.x);
                fma2(o2[r][3], pb, v1.y);
            }
        }
    }

    // epilogue: write to g_att [B,S,HQ,HD]
#pragma unroll
    for (int r = 0; r < 4; r++) {
        int s = q0 + ty * 4 + r;
        u64 ip = pack2(1.0f / l[r]);
#pragma unroll
        for (int c = 0; c < 4; c++) mul2(o2[r][c], ip);
        float* p = O + (((size_t)b * S_ + s) * HQ_ + h) * HD_ + tx * 8;
        *(ulonglong2*)p = make_ulonglong2(o2[r][0], o2[r][1]);
        *(ulonglong2*)(p + 4) = make_ulonglong2(o2[r][2], o2[r][3]);
    }
}

// ---------------------------------------------------------------------------
extern "C" void kernel_launch(void* const* d_in, const int* in_sizes, int n_in,
                              void* d_out, int out_size)
{
    const float* x  = (const float*)d_in[0];
    const float* wq = (const float*)d_in[1];
    const float* wk = (const float*)d_in[2];
    const float* wv = (const float*)d_in[3];
    const float* wo = (const float*)d_in[4];
    const float* fc = (const float*)d_in[5];
    const float* fs = (const float*)d_in[6];
    float* out = (float*)d_out;

    float *gq, *gk, *gv, *ga;
    cudaGetSymbolAddress((void**)&gq, g_q);
    cudaGetSymbolAddress((void**)&gk, g_k);
    cudaGetSymbolAddress((void**)&gv, g_v);
    cudaGetSymbolAddress((void**)&ga, g_att);

    const int M = B_ * S_;  // 4096

    // QKV projections (write head-split layouts)
    sgemm_nt<<<dim3((HQ_ * HD_) / 128, M / 128), 256>>>(x, wq, gq, M, HQ_ * HD_, D_, 1, HQ_);
    sgemm_nt<<<dim3((HKV_ * HD_) / 128, M / 128), 256>>>(x, wk, gk, M, HKV_ * HD_, D_, 1, HKV_);
    sgemm_nt<<<dim3((HKV_ * HD_) / 128, M / 128), 256>>>(x, wv, gv, M, HKV_ * HD_, D_, 1, HKV_);

    // RoPE on Q and K
    long npairs = (long)B_ * (HQ_ + HKV_) * S_ * (HD_ / 2);
    rope_kernel<<<(unsigned)((npairs + 255) / 256), 256>>>(gq, gk, fc, fs);

    // attention
    cudaFuncSetAttribute(attn_kernel, cudaFuncAttributeMaxDynamicSharedMemorySize, ATT_SMEM);
    attn_kernel<<<dim3(S_ / 64, B_ * HQ_), 256, ATT_SMEM>>>(gq, gk, gv, ga);

    // output projection -> d_out
    sgemm_nt<<<dim3(D_ / 128, M / 128), 256>>>(ga, wo, out, M, D_, D_, 0, 0);
}

// round 4
// speedup vs baseline: 1.5354x; 1.4875x over previous
#include <cuda_runtime.h>
#include <cuda_bf16.h>
#include <cstdint>
#include <math.h>

#define B_   2
#define S_   2048
#define D_   4096
#define HQ_  32
#define HKV_ 8
#define HD_  128

typedef unsigned long long u64;

// ---------------- scratch (static device globals; no allocations) ----------
__device__ float g_q[(size_t)B_ * HQ_ * S_ * HD_];     // [B,HQ,S,HD]
__device__ float g_k[(size_t)B_ * HKV_ * S_ * HD_];    // [B,HKV,S,HD]
__device__ float g_v[(size_t)B_ * HKV_ * S_ * HD_];    // [B,HKV,S,HD]
__device__ float g_att[(size_t)B_ * S_ * HQ_ * HD_];   // [B,S,HQ,HD]

// bf16 hi/lo split scratch
__device__ __nv_bfloat16 g_xh[(size_t)B_ * S_ * D_];
__device__ __nv_bfloat16 g_xl[(size_t)B_ * S_ * D_];
__device__ __nv_bfloat16 g_wqh[(size_t)HQ_ * HD_ * D_];
__device__ __nv_bfloat16 g_wql[(size_t)HQ_ * HD_ * D_];
__device__ __nv_bfloat16 g_wkh[(size_t)HKV_ * HD_ * D_];
__device__ __nv_bfloat16 g_wkl[(size_t)HKV_ * HD_ * D_];
__device__ __nv_bfloat16 g_wvh[(size_t)HKV_ * HD_ * D_];
__device__ __nv_bfloat16 g_wvl[(size_t)HKV_ * HD_ * D_];
__device__ __nv_bfloat16 g_woh[(size_t)D_ * HQ_ * HD_];
__device__ __nv_bfloat16 g_wol[(size_t)D_ * HQ_ * HD_];
__device__ __nv_bfloat16 g_ah[(size_t)B_ * S_ * HQ_ * HD_];
__device__ __nv_bfloat16 g_al[(size_t)B_ * S_ * HQ_ * HD_];

// ---------------- PTX helpers (family-portable only) -----------------------
__device__ __forceinline__ uint32_t smem_u32(const void* p) {
    uint32_t a;
    asm("{ .reg .u64 t; cvta.to.shared.u64 t, %1; cvt.u32.u64 %0, t; }" : "=r"(a) : "l"(p));
    return a;
}
__device__ __forceinline__ void cp16(uint32_t s, const void* g) {
    asm volatile("cp.async.cg.shared.global [%0], [%1], 16;" :: "r"(s), "l"(g));
}
__device__ __forceinline__ void cp_commit() {
    asm volatile("cp.async.commit_group;" ::: "memory");
}
__device__ __forceinline__ void ldm_x4(uint32_t a, uint32_t& r0, uint32_t& r1,
                                       uint32_t& r2, uint32_t& r3) {
    asm volatile("ldmatrix.sync.aligned.m8n8.x4.shared.b16 {%0,%1,%2,%3}, [%4];"
                 : "=r"(r0), "=r"(r1), "=r"(r2), "=r"(r3) : "r"(a));
}
__device__ __forceinline__ void mma_bf16(float& d0, float& d1, float& d2, float& d3,
                                         uint32_t a0, uint32_t a1, uint32_t a2, uint32_t a3,
                                         uint32_t b0, uint32_t b1) {
    asm volatile("mma.sync.aligned.m16n8k16.row.col.f32.bf16.bf16.f32 "
                 "{%0,%1,%2,%3}, {%4,%5,%6,%7}, {%8,%9}, {%0,%1,%2,%3};"
                 : "+f"(d0), "+f"(d1), "+f"(d2), "+f"(d3)
                 : "r"(a0), "r"(a1), "r"(a2), "r"(a3), "r"(b0), "r"(b1));
}

// ---------------------------------------------------------------------------
// split fp32 -> bf16 hi + bf16 lo
// ---------------------------------------------------------------------------
__global__ void split_kernel(const float* __restrict__ in,
                             __nv_bfloat16* __restrict__ hi,
                             __nv_bfloat16* __restrict__ lo, int n4)
{
    int i = blockIdx.x * blockDim.x + threadIdx.x;
    if (i >= n4) return;
    float4 v = ((const float4*)in)[i];
    __nv_bfloat16 h0 = __float2bfloat16_rn(v.x);
    __nv_bfloat16 h1 = __float2bfloat16_rn(v.y);
    __nv_bfloat16 h2 = __float2bfloat16_rn(v.z);
    __nv_bfloat16 h3 = __float2bfloat16_rn(v.w);
    __nv_bfloat16 l0 = __float2bfloat16_rn(v.x - __bfloat162float(h0));
    __nv_bfloat16 l1 = __float2bfloat16_rn(v.y - __bfloat162float(h1));
    __nv_bfloat16 l2 = __float2bfloat16_rn(v.z - __bfloat162float(h2));
    __nv_bfloat16 l3 = __float2bfloat16_rn(v.w - __bfloat162float(h3));
    __nv_bfloat162* hp = (__nv_bfloat162*)(hi + 4 * (size_t)i);
    __nv_bfloat162* lp = (__nv_bfloat162*)(lo + 4 * (size_t)i);
    hp[0] = __halves2bfloat162(h0, h1);
    hp[1] = __halves2bfloat162(h2, h3);
    lp[0] = __halves2bfloat162(l0, l1);
    lp[1] = __halves2bfloat162(l2, l3);
}

// ---------------------------------------------------------------------------
// bf16x3 GEMM (NT) via mma.sync: C[m,n] = sum_k A[m,k]*B[n,k], ~fp32 accuracy.
// CTA 128x128, K-chunk 32, 8 warps (2x4), warp tile 64x32.
// smem rows padded to 40 bf16 (80B) -> conflict-free ldmatrix.
// Double-buffered cp.async pipeline.
// ---------------------------------------------------------------------------
#define RSTR   40                     // bf16 per smem row (32 data + 8 pad)
#define TILE_B (128 * RSTR * 2)       // 10240 bytes: one 128x32 bf16 tile
#define STG_B  (4 * TILE_B)           // Ah, Al, Bh, Bl
#define GSMEM  (2 * STG_B)            // 81920 bytes

__global__ __launch_bounds__(256, 1) void gemm_bf16x3(
    const __nv_bfloat16* __restrict__ Ah, const __nv_bfloat16* __restrict__ Al,
    const __nv_bfloat16* __restrict__ Bh, const __nv_bfloat16* __restrict__ Bl,
    float* __restrict__ C, int M, int N, int K, int head_layout, int H)
{
    extern __shared__ char smem[];
    const uint32_t sb = smem_u32(smem);
    const int tid = threadIdx.x;
    const int lane = tid & 31;
    const int wid = tid >> 5;
    const int wm = wid >> 2;        // 0..1  (m direction, 64 rows each)
    const int wn = wid & 3;         // 0..3  (n direction, 32 cols each)
    const int bm = blockIdx.y * 128;
    const int bn = blockIdx.x * 128;

    float acc[4][4][4];
#pragma unroll
    for (int i = 0; i < 4; i++)
#pragma unroll
        for (int j = 0; j < 4; j++)
#pragma unroll
            for (int c = 0; c < 4; c++) acc[i][j][c] = 0.f;

    const int iters = K >> 5;
    const int row0 = tid >> 2;            // 0..63
    const int col0 = tid & 3;             // 0..3 (16B units)

#define PREFETCH(it_) do {                                                    \
    const int st_ = (it_) & 1;                                                \
    const int k0_ = (it_) << 5;                                               \
    const uint32_t sob_ = sb + st_ * STG_B;                                   \
    _Pragma("unroll")                                                         \
    for (int j_ = 0; j_ < 2; j_++) {                                          \
        int row_ = row0 + j_ * 64;                                            \
        uint32_t so_ = sob_ + row_ * (RSTR * 2) + col0 * 16;                  \
        size_t ga_ = (size_t)(bm + row_) * K + k0_ + col0 * 8;                \
        size_t gb_ = (size_t)(bn + row_) * K + k0_ + col0 * 8;                \
        cp16(so_ + 0 * TILE_B, Ah + ga_);                                     \
        cp16(so_ + 1 * TILE_B, Al + ga_);                                     \
        cp16(so_ + 2 * TILE_B, Bh + gb_);                                     \
        cp16(so_ + 3 * TILE_B, Bl + gb_);                                     \
    }                                                                         \
    cp_commit();                                                              \
} while (0)

    PREFETCH(0);
    if (iters > 1) PREFETCH(1);

    for (int it = 0; it < iters; it++) {
        if (it + 1 < iters) {
            asm volatile("cp.async.wait_group 1;" ::: "memory");
        } else {
            asm volatile("cp.async.wait_group 0;" ::: "memory");
        }
        __syncthreads();

        const uint32_t base = sb + (it & 1) * STG_B;
        const uint32_t a_h = base;
        const uint32_t a_l = base + TILE_B;
        const uint32_t b_h = base + 2 * TILE_B;
        const uint32_t b_l = base + 3 * TILE_B;

#pragma unroll
        for (int kk = 0; kk < 2; kk++) {
            const int kc = kk * 16 + (lane >> 4) * 8;
            uint32_t a[4][4], bhf[4][2], blf[4][2];
#pragma unroll
            for (int nq = 0; nq < 2; nq++) {
                int row = wn * 32 + nq * 16 + (lane & 15);
                uint32_t off = row * (RSTR * 2) + kc * 2;
                uint32_t r0, r1, r2, r3;
                ldm_x4(b_h + off, r0, r1, r2, r3);
                bhf[nq * 2][0] = r0; bhf[nq * 2][1] = r2;
                bhf[nq * 2 + 1][0] = r1; bhf[nq * 2 + 1][1] = r3;
                ldm_x4(b_l + off, r0, r1, r2, r3);
                blf[nq * 2][0] = r0; blf[nq * 2][1] = r2;
                blf[nq * 2 + 1][0] = r1; blf[nq * 2 + 1][1] = r3;
            }
#pragma unroll
            for (int mf = 0; mf < 4; mf++) {
                int row = wm * 64 + mf * 16 + (lane & 15);
                ldm_x4(a_h + row * (RSTR * 2) + kc * 2,
                       a[mf][0], a[mf][1], a[mf][2], a[mf][3]);
            }
#pragma unroll
            for (int mf = 0; mf < 4; mf++)
#pragma unroll
                for (int nf = 0; nf < 4; nf++) {
                    mma_bf16(acc[mf][nf][0], acc[mf][nf][1], acc[mf][nf][2], acc[mf][nf][3],
                             a[mf][0], a[mf][1], a[mf][2], a[mf][3],
                             bhf[nf][0], bhf[nf][1]);
                    mma_bf16(acc[mf][nf][0], acc[mf][nf][1], acc[mf][nf][2], acc[mf][nf][3],
                             a[mf][0], a[mf][1], a[mf][2], a[mf][3],
                             blf[nf][0], blf[nf][1]);
                }
#pragma unroll
            for (int mf = 0; mf < 4; mf++) {
                int row = wm * 64 + mf * 16 + (lane & 15);
                ldm_x4(a_l + row * (RSTR * 2) + kc * 2,
                       a[mf][0], a[mf][1], a[mf][2], a[mf][3]);
            }
#pragma unroll
            for (int mf = 0; mf < 4; mf++)
#pragma unroll
                for (int nf = 0; nf < 4; nf++)
                    mma_bf16(acc[mf][nf][0], acc[mf][nf][1], acc[mf][nf][2], acc[mf][nf][3],
                             a[mf][0], a[mf][1], a[mf][2], a[mf][3],
                             bhf[nf][0], bhf[nf][1]);
        }

        __syncthreads();
        if (it + 2 < iters) PREFETCH(it + 2);
    }

    // epilogue
    const int qr = lane >> 2;
    const int qc = lane & 3;
#pragma unroll
    for (int mf = 0; mf < 4; mf++) {
#pragma unroll
        for (int half = 0; half < 2; half++) {
            int m = bm + wm * 64 + mf * 16 + qr + half * 8;
            float* dst;
            if (!head_layout) {
                dst = C + (size_t)m * N + bn;
            } else {
                int b = m >> 11;
                int s = m & (S_ - 1);
                int h = bn >> 7;
                dst = C + (((size_t)b * H + h) * S_ + s) * HD_;
            }
#pragma unroll
            for (int nf = 0; nf < 4; nf++) {
                int n = wn * 32 + nf * 8 + 2 * qc;
                float2 w = half ? make_float2(acc[mf][nf][2], acc[mf][nf][3])
                                : make_float2(acc[mf][nf][0], acc[mf][nf][1]);
                *(float2*)(dst + n) = w;
            }
        }
    }
#undef PREFETCH
}

// ---------------------------------------------------------------------------
// RoPE in place on g_q ([B,HQ,S,HD]) and g_k ([B,HKV,S,HD]).
// ---------------------------------------------------------------------------
__global__ void rope_kernel(float* __restrict__ q, float* __restrict__ k,
                            const float* __restrict__ fcos,
                            const float* __restrict__ fsin)
{
    long id = (long)blockIdx.x * blockDim.x + threadIdx.x;
    int i = (int)(id & 63);
    long t = id >> 6;
    int s = (int)(t & (S_ - 1));
    t >>= 11;
    int hh = (int)(t % (HQ_ + HKV_));
    int b  = (int)(t / (HQ_ + HKV_));
    if (b >= B_) return;

    float c  = fcos[s * (HD_ / 2) + i];
    float sn = fsin[s * (HD_ / 2) + i];

    float* base;
    size_t off;
    if (hh < HQ_) {
        base = q;
        off = (((size_t)b * HQ_ + hh) * S_ + s) * HD_ + 2 * i;
    } else {
        base = k;
        off = (((size_t)b * HKV_ + (hh - HQ_)) * S_ + s) * HD_ + 2 * i;
    }
    float2 v = *(float2*)(base + off);
    float x0 = v.x, x1 = v.y;
    v.x = x0 * c - x1 * sn;
    v.y = x0 * sn + x1 * c;
    *(float2*)(base + off) = v;
}

// ---------------------------------------------------------------------------
// Flash attention, fp32 (f32x2 packed math). Unchanged from round 2.
// ---------------------------------------------------------------------------
__device__ __forceinline__ u64 pack2(float x) {
    u64 r;
    asm("mov.b64 %0, {%1, %1};" : "=l"(r) : "f"(x));
    return r;
}
__device__ __forceinline__ void fma2(u64& d, u64 a, u64 b) {
    asm("fma.rn.f32x2 %0, %1, %2, %0;" : "+l"(d) : "l"(a), "l"(b));
}
__device__ __forceinline__ void mul2(u64& d, u64 a) {
    asm("mul.rn.f32x2 %0, %0, %1;" : "+l"(d) : "l"(a));
}
__device__ __forceinline__ float2 unpack2(u64 v) {
    float2 f;
    asm("mov.b64 {%0, %1}, %2;" : "=f"(f.x), "=f"(f.y) : "l"(v));
    return f;
}

#define KSTR 132
#define KST  66
#define PSTR 68
#define ATT_SMEM ((2 * 64 * KSTR + 128 * KST + 64 * PSTR) * 4)

__global__ __launch_bounds__(256) void attn_kernel(
    const float* __restrict__ Q, const float* __restrict__ Kg,
    const float* __restrict__ Vg, float* __restrict__ O)
{
    extern __shared__ float sm[];
    float* Qs  = sm;
    float* KsT = Qs + 64 * KSTR;
    float* Vs  = KsT + 128 * KST;
    float* Ps  = Vs + 64 * KSTR;

    const int bh = blockIdx.y;
    const int b = bh >> 5;
    const int h = bh & (HQ_ - 1);
    const int kvh = h >> 2;
    const int q0 = blockIdx.x * 64;
    const int tid = threadIdx.x;
    const int ty = tid >> 4;
    const int tx = tid & 15;

    const float* Qbase = Q + (((size_t)b * HQ_ + h) * S_ + q0) * HD_;
    const float* Kbase = Kg + (((size_t)b * HKV_ + kvh) * S_) * HD_;
    const float* Vbase = Vg + (((size_t)b * HKV_ + kvh) * S_) * HD_;

    {
        int r = tid >> 2;
        int c4 = (tid & 3) * 4;
#pragma unroll
        for (int it = 0; it < 8; it++) {
            float4 v = *(const float4*)(Qbase + (size_t)r * HD_ + c4 + it * 16);
            *(float4*)(Qs + r * KSTR + c4 + it * 16) = v;
        }
    }

    float m[4], l[4];
    u64 o2[4][4];
#pragma unroll
    for (int r = 0; r < 4; r++) {
        m[r] = -1e30f;
        l[r] = 0.f;
#pragma unroll
        for (int c = 0; c < 4; c++) o2[r][c] = 0ULL;
    }

    const float scale = 0.08838834764831845f;

    for (int t0 = 0; t0 < S_; t0 += 64) {
        __syncthreads();
        {
            int n = tid >> 2;
            int c4 = (tid & 3) * 4;
#pragma unroll
            for (int it = 0; it < 8; it++) {
                int d0 = c4 + it * 16;
                float4 kv = *(const float4*)(Kbase + (size_t)(t0 + n) * HD_ + d0);
                KsT[(d0 + 0) * KST + n] = kv.x;
                KsT[(d0 + 1) * KST + n] = kv.y;
                KsT[(d0 + 2) * KST + n] = kv.z;
                KsT[(d0 + 3) * KST + n] = kv.w;
                *(float4*)(Vs + n * KSTR + d0) =
                    *(const float4*)(Vbase + (size_t)(t0 + n) * HD_ + d0);
            }
        }
        __syncthreads();

        u64 s2[4][2];
#pragma unroll
        for (int r = 0; r < 4; r++) { s2[r][0] = 0ULL; s2[r][1] = 0ULL; }

#pragma unroll 4
        for (int d4 = 0; d4 < HD_; d4 += 4) {
            float qa[4][4];
#pragma unroll
            for (int r = 0; r < 4; r++) {
                float4 t = *(const float4*)(Qs + (ty * 4 + r) * KSTR + d4);
                qa[r][0] = t.x; qa[r][1] = t.y; qa[r][2] = t.z; qa[r][3] = t.w;
            }
#pragma unroll
            for (int dd = 0; dd < 4; dd++) {
                u64 k01 = *(const u64*)(KsT + (d4 + dd) * KST + 2 * tx);
                u64 k23 = *(const u64*)(KsT + (d4 + dd) * KST + 2 * tx + 32);
#pragma unroll
                for (int r = 0; r < 4; r++) {
                    u64 qb = pack2(qa[r][dd]);
                    fma2(s2[r][0], qb, k01);
                    fma2(s2[r][1], qb, k23);
                }
            }
        }

#pragma unroll
        for (int r = 0; r < 4; r++) {
            float2 p0 = unpack2(s2[r][0]);
            float2 p1 = unpack2(s2[r][1]);
            float sc0 = p0.x * scale, sc1 = p0.y * scale;
            float sc2v = p1.x * scale, sc3 = p1.y * scale;
            float mx = fmaxf(fmaxf(sc0, sc1), fmaxf(sc2v, sc3));
#pragma unroll
            for (int off = 8; off >= 1; off >>= 1)
                mx = fmaxf(mx, __shfl_xor_sync(0xffffffffu, mx, off, 16));
            float mnew = fmaxf(m[r], mx);
            float alpha = __expf(m[r] - mnew);
            float e0 = __expf(sc0 - mnew);
            float e1 = __expf(sc1 - mnew);
            float e2 = __expf(sc2v - mnew);
            float e3 = __expf(sc3 - mnew);
            float rs = e0 + e1 + e2 + e3;
#pragma unroll
            for (int off = 8; off >= 1; off >>= 1)
                rs += __shfl_xor_sync(0xffffffffu, rs, off, 16);
            l[r] = l[r] * alpha + rs;
            m[r] = mnew;
            u64 ap = pack2(alpha);
#pragma unroll
            for (int c = 0; c < 4; c++) mul2(o2[r][c], ap);
            int row = (ty * 4 + r) * PSTR;
            Ps[row + 2 * tx]      = e0;
            Ps[row + 2 * tx + 1]  = e1;
            Ps[row + 2 * tx + 32] = e2;
            Ps[row + 2 * tx + 33] = e3;
        }
        __syncthreads();

#pragma unroll 4
        for (int j = 0; j < 64; j++) {
            const ulonglong2* pv = (const ulonglong2*)(Vs + j * KSTR + tx * 8);
            ulonglong2 v0 = pv[0];
            ulonglong2 v1 = pv[1];
#pragma unroll
            for (int r = 0; r < 4; r++) {
                u64 pb = pack2(Ps[(ty * 4 + r) * PSTR + j]);
                fma2(o2[r][0], pb, v0.x);
                fma2(o2[r][1], pb, v0.y);
                fma2(o2[r][2], pb, v1.x);
                fma2(o2[r][3], pb, v1.y);
            }
        }
    }

#pragma unroll
    for (int r = 0; r < 4; r++) {
        int s = q0 + ty * 4 + r;
        u64 ip = pack2(1.0f / l[r]);
#pragma unroll
        for (int c = 0; c < 4; c++) mul2(o2[r][c], ip);
        float* p = O + (((size_t)b * S_ + s) * HQ_ + h) * HD_ + tx * 8;
        *(ulonglong2*)p = make_ulonglong2(o2[r][0], o2[r][1]);
        *(ulonglong2*)(p + 4) = make_ulonglong2(o2[r][2], o2[r][3]);
    }
}

// ---------------------------------------------------------------------------
extern "C" void kernel_launch(void* const* d_in, const int* in_sizes, int n_in,
                              void* d_out, int out_size)
{
    const float* x  = (const float*)d_in[0];
    const float* wq = (const float*)d_in[1];
    const float* wk = (const float*)d_in[2];
    const float* wv = (const float*)d_in[3];
    const float* wo = (const float*)d_in[4];
    const float* fc = (const float*)d_in[5];
    const float* fs = (const float*)d_in[6];
    float* out = (float*)d_out;

    float *gq, *gk, *gv, *ga;
    cudaGetSymbolAddress((void**)&gq, g_q);
    cudaGetSymbolAddress((void**)&gk, g_k);
    cudaGetSymbolAddress((void**)&gv, g_v);
    cudaGetSymbolAddress((void**)&ga, g_att);
    __nv_bfloat16 *xh, *xl, *wqh, *wql, *wkh, *wkl, *wvh, *wvl, *woh, *wol, *ah, *al;
    cudaGetSymbolAddress((void**)&xh, g_xh);   cudaGetSymbolAddress((void**)&xl, g_xl);
    cudaGetSymbolAddress((void**)&wqh, g_wqh); cudaGetSymbolAddress((void**)&wql, g_wql);
    cudaGetSymbolAddress((void**)&wkh, g_wkh); cudaGetSymbolAddress((void**)&wkl, g_wkl);
    cudaGetSymbolAddress((void**)&wvh, g_wvh); cudaGetSymbolAddress((void**)&wvl, g_wvl);
    cudaGetSymbolAddress((void**)&woh, g_woh); cudaGetSymbolAddress((void**)&wol, g_wol);
    cudaGetSymbolAddress((void**)&ah, g_ah);   cudaGetSymbolAddress((void**)&al, g_al);

    const int M = B_ * S_;  // 4096

    // splits
    int n4x = (B_ * S_ * D_) / 4;
    split_kernel<<<(n4x + 255) / 256, 256>>>(x, xh, xl, n4x);
    int n4q = (HQ_ * HD_ * D_) / 4;
    split_kernel<<<(n4q + 255) / 256, 256>>>(wq, wqh, wql, n4q);
    int n4k = (HKV_ * HD_ * D_) / 4;
    split_kernel<<<(n4k + 255) / 256, 256>>>(wk, wkh, wkl, n4k);
    split_kernel<<<(n4k + 255) / 256, 256>>>(wv, wvh, wvl, n4k);
    int n4o = (D_ * HQ_ * HD_) / 4;
    split_kernel<<<(n4o + 255) / 256, 256>>>(wo, woh, wol, n4o);

    cudaFuncSetAttribute(gemm_bf16x3, cudaFuncAttributeMaxDynamicSharedMemorySize, GSMEM);

    // QKV projections (write head-split fp32 layouts)
    gemm_bf16x3<<<dim3((HQ_ * HD_) / 128, M / 128), 256, GSMEM>>>(
        xh, xl, wqh, wql, gq, M, HQ_ * HD_, D_, 1, HQ_);
    gemm_bf16x3<<<dim3((HKV_ * HD_) / 128, M / 128), 256, GSMEM>>>(
        xh, xl, wkh, wkl, gk, M, HKV_ * HD_, D_, 1, HKV_);
    gemm_bf16x3<<<dim3((HKV_ * HD_) / 128, M / 128), 256, GSMEM>>>(
        xh, xl, wvh, wvl, gv, M, HKV_ * HD_, D_, 1, HKV_);

    // RoPE on Q and K
    long npairs = (long)B_ * (HQ_ + HKV_) * S_ * (HD_ / 2);
    rope_kernel<<<(unsigned)((npairs + 255) / 256), 256>>>(gq, gk, fc, fs);

    // attention
    cudaFuncSetAttribute(attn_kernel, cudaFuncAttributeMaxDynamicSharedMemorySize, ATT_SMEM);
    attn_kernel<<<dim3(S_ / 64, B_ * HQ_), 256, ATT_SMEM>>>(gq, gk, gv, ga);

    // split attention output, then output projection -> d_out
    int n4a = (B_ * S_ * HQ_ * HD_) / 4;
    split_kernel<<<(n4a + 255) / 256, 256>>>(ga, ah, al, n4a);
    gemm_bf16x3<<<dim3(D_ / 128, M / 128), 256, GSMEM>>>(
        ah, al, woh, wol, out, M, D_, D_, 0, 0);
}

// round 5
// speedup vs baseline: 1.7542x; 1.1425x over previous
#include <cuda_runtime.h>
#include <cuda_bf16.h>
#include <cstdint>
#include <math.h>

#define B_   2
#define S_   2048
#define D_   4096
#define HQ_  32
#define HKV_ 8
#define HD_  128

typedef unsigned long long u64;

// ---------------- scratch (static device globals; no allocations) ----------
__device__ float g_q[(size_t)B_ * HQ_ * S_ * HD_];     // [B,HQ,S,HD]
__device__ float g_k[(size_t)B_ * HKV_ * S_ * HD_];    // [B,HKV,S,HD]
__device__ float g_v[(size_t)B_ * HKV_ * S_ * HD_];    // [B,HKV,S,HD]
__device__ float g_att[(size_t)B_ * S_ * HQ_ * HD_];   // [B,S,HQ,HD]

// bf16 hi/lo split scratch
__device__ __nv_bfloat16 g_xh[(size_t)B_ * S_ * D_];
__device__ __nv_bfloat16 g_xl[(size_t)B_ * S_ * D_];
__device__ __nv_bfloat16 g_wqh[(size_t)HQ_ * HD_ * D_];
__device__ __nv_bfloat16 g_wql[(size_t)HQ_ * HD_ * D_];
__device__ __nv_bfloat16 g_wkh[(size_t)HKV_ * HD_ * D_];
__device__ __nv_bfloat16 g_wkl[(size_t)HKV_ * HD_ * D_];
__device__ __nv_bfloat16 g_wvh[(size_t)HKV_ * HD_ * D_];
__device__ __nv_bfloat16 g_wvl[(size_t)HKV_ * HD_ * D_];
__device__ __nv_bfloat16 g_woh[(size_t)D_ * HQ_ * HD_];
__device__ __nv_bfloat16 g_wol[(size_t)D_ * HQ_ * HD_];
__device__ __nv_bfloat16 g_ah[(size_t)B_ * S_ * HQ_ * HD_];
__device__ __nv_bfloat16 g_al[(size_t)B_ * S_ * HQ_ * HD_];

// ---------------- PTX helpers (family-portable only) -----------------------
__device__ __forceinline__ uint32_t smem_u32(const void* p) {
    uint32_t a;
    asm("{ .reg .u64 t; cvta.to.shared.u64 t, %1; cvt.u32.u64 %0, t; }" : "=r"(a) : "l"(p));
    return a;
}
__device__ __forceinline__ void cp16(uint32_t s, const void* g) {
    asm volatile("cp.async.cg.shared.global [%0], [%1], 16;" :: "r"(s), "l"(g));
}
__device__ __forceinline__ void cp_commit() {
    asm volatile("cp.async.commit_group;" ::: "memory");
}
__device__ __forceinline__ void ldm_x4(uint32_t a, uint32_t& r0, uint32_t& r1,
                                       uint32_t& r2, uint32_t& r3) {
    asm volatile("ldmatrix.sync.aligned.m8n8.x4.shared.b16 {%0,%1,%2,%3}, [%4];"
                 : "=r"(r0), "=r"(r1), "=r"(r2), "=r"(r3) : "r"(a));
}
__device__ __forceinline__ void mma_bf16(float& d0, float& d1, float& d2, float& d3,
                                         uint32_t a0, uint32_t a1, uint32_t a2, uint32_t a3,
                                         uint32_t b0, uint32_t b1) {
    asm volatile("mma.sync.aligned.m16n8k16.row.col.f32.bf16.bf16.f32 "
                 "{%0,%1,%2,%3}, {%4,%5,%6,%7}, {%8,%9}, {%0,%1,%2,%3};"
                 : "+f"(d0), "+f"(d1), "+f"(d2), "+f"(d3)
                 : "r"(a0), "r"(a1), "r"(a2), "r"(a3), "r"(b0), "r"(b1));
}
__device__ __forceinline__ uint32_t packbf(float lo, float hi) {
    __nv_bfloat162 t = __floats2bfloat162_rn(lo, hi);
    return *(uint32_t*)&t;
}

// ---------------------------------------------------------------------------
// split fp32 -> bf16 hi + bf16 lo
// ---------------------------------------------------------------------------
__global__ void split_kernel(const float* __restrict__ in,
                             __nv_bfloat16* __restrict__ hi,
                             __nv_bfloat16* __restrict__ lo, int n4)
{
    int i = blockIdx.x * blockDim.x + threadIdx.x;
    if (i >= n4) return;
    float4 v = ((const float4*)in)[i];
    __nv_bfloat16 h0 = __float2bfloat16_rn(v.x);
    __nv_bfloat16 h1 = __float2bfloat16_rn(v.y);
    __nv_bfloat16 h2 = __float2bfloat16_rn(v.z);
    __nv_bfloat16 h3 = __float2bfloat16_rn(v.w);
    __nv_bfloat16 l0 = __float2bfloat16_rn(v.x - __bfloat162float(h0));
    __nv_bfloat16 l1 = __float2bfloat16_rn(v.y - __bfloat162float(h1));
    __nv_bfloat16 l2 = __float2bfloat16_rn(v.z - __bfloat162float(h2));
    __nv_bfloat16 l3 = __float2bfloat16_rn(v.w - __bfloat162float(h3));
    __nv_bfloat162* hp = (__nv_bfloat162*)(hi + 4 * (size_t)i);
    __nv_bfloat162* lp = (__nv_bfloat162*)(lo + 4 * (size_t)i);
    hp[0] = __halves2bfloat162(h0, h1);
    hp[1] = __halves2bfloat162(h2, h3);
    lp[0] = __halves2bfloat162(l0, l1);
    lp[1] = __halves2bfloat162(l2, l3);
}

// ---------------------------------------------------------------------------
// bf16x3 GEMM (NT) via mma.sync (unchanged from round 4).
// ---------------------------------------------------------------------------
#define RSTR   40
#define TILE_B (128 * RSTR * 2)
#define STG_B  (4 * TILE_B)
#define GSMEM  (2 * STG_B)

__global__ __launch_bounds__(256, 1) void gemm_bf16x3(
    const __nv_bfloat16* __restrict__ Ah, const __nv_bfloat16* __restrict__ Al,
    const __nv_bfloat16* __restrict__ Bh, const __nv_bfloat16* __restrict__ Bl,
    float* __restrict__ C, int M, int N, int K, int head_layout, int H)
{
    extern __shared__ char smem[];
    const uint32_t sb = smem_u32(smem);
    const int tid = threadIdx.x;
    const int lane = tid & 31;
    const int wid = tid >> 5;
    const int wm = wid >> 2;
    const int wn = wid & 3;
    const int bm = blockIdx.y * 128;
    const int bn = blockIdx.x * 128;

    float acc[4][4][4];
#pragma unroll
    for (int i = 0; i < 4; i++)
#pragma unroll
        for (int j = 0; j < 4; j++)
#pragma unroll
            for (int c = 0; c < 4; c++) acc[i][j][c] = 0.f;

    const int iters = K >> 5;
    const int row0 = tid >> 2;
    const int col0 = tid & 3;

#define PREFETCH(it_) do {                                                    \
    const int st_ = (it_) & 1;                                                \
    const int k0_ = (it_) << 5;                                               \
    const uint32_t sob_ = sb + st_ * STG_B;                                   \
    _Pragma("unroll")                                                         \
    for (int j_ = 0; j_ < 2; j_++) {                                          \
        int row_ = row0 + j_ * 64;                                            \
        uint32_t so_ = sob_ + row_ * (RSTR * 2) + col0 * 16;                  \
        size_t ga_ = (size_t)(bm + row_) * K + k0_ + col0 * 8;                \
        size_t gb_ = (size_t)(bn + row_) * K + k0_ + col0 * 8;                \
        cp16(so_ + 0 * TILE_B, Ah + ga_);                                     \
        cp16(so_ + 1 * TILE_B, Al + ga_);                                     \
        cp16(so_ + 2 * TILE_B, Bh + gb_);                                     \
        cp16(so_ + 3 * TILE_B, Bl + gb_);                                     \
    }                                                                         \
    cp_commit();                                                              \
} while (0)

    PREFETCH(0);
    if (iters > 1) PREFETCH(1);

    for (int it = 0; it < iters; it++) {
        if (it + 1 < iters) {
            asm volatile("cp.async.wait_group 1;" ::: "memory");
        } else {
            asm volatile("cp.async.wait_group 0;" ::: "memory");
        }
        __syncthreads();

        const uint32_t base = sb + (it & 1) * STG_B;
        const uint32_t a_h = base;
        const uint32_t a_l = base + TILE_B;
        const uint32_t b_h = base + 2 * TILE_B;
        const uint32_t b_l = base + 3 * TILE_B;

#pragma unroll
        for (int kk = 0; kk < 2; kk++) {
            const int kc = kk * 16 + (lane >> 4) * 8;
            uint32_t a[4][4], bhf[4][2], blf[4][2];
#pragma unroll
            for (int nq = 0; nq < 2; nq++) {
                int row = wn * 32 + nq * 16 + (lane & 15);
                uint32_t off = row * (RSTR * 2) + kc * 2;
                uint32_t r0, r1, r2, r3;
                ldm_x4(b_h + off, r0, r1, r2, r3);
                bhf[nq * 2][0] = r0; bhf[nq * 2][1] = r2;
                bhf[nq * 2 + 1][0] = r1; bhf[nq * 2 + 1][1] = r3;
                ldm_x4(b_l + off, r0, r1, r2, r3);
                blf[nq * 2][0] = r0; blf[nq * 2][1] = r2;
                blf[nq * 2 + 1][0] = r1; blf[nq * 2 + 1][1] = r3;
            }
#pragma unroll
            for (int mf = 0; mf < 4; mf++) {
                int row = wm * 64 + mf * 16 + (lane & 15);
                ldm_x4(a_h + row * (RSTR * 2) + kc * 2,
                       a[mf][0], a[mf][1], a[mf][2], a[mf][3]);
            }
#pragma unroll
            for (int mf = 0; mf < 4; mf++)
#pragma unroll
                for (int nf = 0; nf < 4; nf++) {
                    mma_bf16(acc[mf][nf][0], acc[mf][nf][1], acc[mf][nf][2], acc[mf][nf][3],
                             a[mf][0], a[mf][1], a[mf][2], a[mf][3],
                             bhf[nf][0], bhf[nf][1]);
                    mma_bf16(acc[mf][nf][0], acc[mf][nf][1], acc[mf][nf][2], acc[mf][nf][3],
                             a[mf][0], a[mf][1], a[mf][2], a[mf][3],
                             blf[nf][0], blf[nf][1]);
                }
#pragma unroll
            for (int mf = 0; mf < 4; mf++) {
                int row = wm * 64 + mf * 16 + (lane & 15);
                ldm_x4(a_l + row * (RSTR * 2) + kc * 2,
                       a[mf][0], a[mf][1], a[mf][2], a[mf][3]);
            }
#pragma unroll
            for (int mf = 0; mf < 4; mf++)
#pragma unroll
                for (int nf = 0; nf < 4; nf++)
                    mma_bf16(acc[mf][nf][0], acc[mf][nf][1], acc[mf][nf][2], acc[mf][nf][3],
                             a[mf][0], a[mf][1], a[mf][2], a[mf][3],
                             bhf[nf][0], bhf[nf][1]);
        }

        __syncthreads();
        if (it + 2 < iters) PREFETCH(it + 2);
    }

    const int qr = lane >> 2;
    const int qc = lane & 3;
#pragma unroll
    for (int mf = 0; mf < 4; mf++) {
#pragma unroll
        for (int half = 0; half < 2; half++) {
            int m = bm + wm * 64 + mf * 16 + qr + half * 8;
            float* dst;
            if (!head_layout) {
                dst = C + (size_t)m * N + bn;
            } else {
                int b = m >> 11;
                int s = m & (S_ - 1);
                int h = bn >> 7;
                dst = C + (((size_t)b * H + h) * S_ + s) * HD_;
            }
#pragma unroll
            for (int nf = 0; nf < 4; nf++) {
                int n = wn * 32 + nf * 8 + 2 * qc;
                float2 w = half ? make_float2(acc[mf][nf][2], acc[mf][nf][3])
                                : make_float2(acc[mf][nf][0], acc[mf][nf][1]);
                *(float2*)(dst + n) = w;
            }
        }
    }
#undef PREFETCH
}

// ---------------------------------------------------------------------------
// RoPE in place on g_q ([B,HQ,S,HD]) and g_k ([B,HKV,S,HD]).
// ---------------------------------------------------------------------------
__global__ void rope_kernel(float* __restrict__ q, float* __restrict__ k,
                            const float* __restrict__ fcos,
                            const float* __restrict__ fsin)
{
    long id = (long)blockIdx.x * blockDim.x + threadIdx.x;
    int i = (int)(id & 63);
    long t = id >> 6;
    int s = (int)(t & (S_ - 1));
    t >>= 11;
    int hh = (int)(t % (HQ_ + HKV_));
    int b  = (int)(t / (HQ_ + HKV_));
    if (b >= B_) return;

    float c  = fcos[s * (HD_ / 2) + i];
    float sn = fsin[s * (HD_ / 2) + i];

    float* base;
    size_t off;
    if (hh < HQ_) {
        base = q;
        off = (((size_t)b * HQ_ + hh) * S_ + s) * HD_ + 2 * i;
    } else {
        base = k;
        off = (((size_t)b * HKV_ + (hh - HQ_)) * S_ + s) * HD_ + 2 * i;
    }
    float2 v = *(float2*)(base + off);
    float x0 = v.x, x1 = v.y;
    v.x = x0 * c - x1 * sn;
    v.y = x0 * sn + x1 * c;
    *(float2*)(base + off) = v;
}

// ---------------------------------------------------------------------------
// Tensor-core flash attention (bf16x3, fp32 accuracy).
// Grid (S/64, B*HQ), block 128 (4 warps). Warp w owns q-rows w*16..w*16+15.
// Q,K in smem as [64][AQ_STR] bf16 (h/l); V transposed: Vt[128 hd][AV_STR] (h/l).
// S = Q K^T: 3 passes (QhKh, QlKh, QhKl). PV: 3 passes (PhVh, PlVh, PhVl).
// ---------------------------------------------------------------------------
#define AQ_STR 136
#define AV_STR 72
#define ATT_SMEM ((4 * 64 * AQ_STR + 2 * 128 * AV_STR) * 2)   // 106496 B

__global__ __launch_bounds__(128) void attn_mma(
    const float* __restrict__ Q, const float* __restrict__ Kg,
    const float* __restrict__ Vg, float* __restrict__ O)
{
    extern __shared__ __nv_bfloat16 sm2[];
    __nv_bfloat16* Qh  = sm2;
    __nv_bfloat16* Ql  = Qh + 64 * AQ_STR;
    __nv_bfloat16* Kh  = Ql + 64 * AQ_STR;
    __nv_bfloat16* Kl  = Kh + 64 * AQ_STR;
    __nv_bfloat16* Vth = Kl + 64 * AQ_STR;
    __nv_bfloat16* Vtl = Vth + 128 * AV_STR;

    const uint32_t uqh = smem_u32(Qh), uql = smem_u32(Ql);
    const uint32_t ukh = smem_u32(Kh), ukl = smem_u32(Kl);
    const uint32_t uvh = smem_u32(Vth), uvl = smem_u32(Vtl);

    const int bh = blockIdx.y;
    const int b = bh >> 5;
    const int h = bh & (HQ_ - 1);
    const int kvh = h >> 2;
    const int q0 = blockIdx.x * 64;
    const int tid = threadIdx.x;
    const int lane = tid & 31;
    const int warp = tid >> 5;

    const float* Qg = Q + (((size_t)b * HQ_ + h) * S_ + q0) * HD_;
    const float* Kb = Kg + ((size_t)b * HKV_ + kvh) * S_ * HD_;
    const float* Vb = Vg + ((size_t)b * HKV_ + kvh) * S_ * HD_;

    // stage Q once (64x128 fp32 -> bf16 h/l)
#pragma unroll 4
    for (int it = 0; it < 16; it++) {
        int lin = tid + it * 128;
        int r = lin >> 5;
        int c4 = (lin & 31) << 2;
        float4 v = *(const float4*)(Qg + (size_t)r * HD_ + c4);
        __nv_bfloat16 h0 = __float2bfloat16_rn(v.x), h1 = __float2bfloat16_rn(v.y);
        __nv_bfloat16 h2 = __float2bfloat16_rn(v.z), h3 = __float2bfloat16_rn(v.w);
        int o0 = r * AQ_STR + c4;
        Qh[o0 + 0] = h0; Qh[o0 + 1] = h1; Qh[o0 + 2] = h2; Qh[o0 + 3] = h3;
        Ql[o0 + 0] = __float2bfloat16_rn(v.x - __bfloat162float(h0));
        Ql[o0 + 1] = __float2bfloat16_rn(v.y - __bfloat162float(h1));
        Ql[o0 + 2] = __float2bfloat16_rn(v.z - __bfloat162float(h2));
        Ql[o0 + 3] = __float2bfloat16_rn(v.w - __bfloat162float(h3));
    }

    float o[16][4];
#pragma unroll
    for (int t = 0; t < 16; t++)
#pragma unroll
        for (int c = 0; c < 4; c++) o[t][c] = 0.f;
    float m0 = -1e30f, m1 = -1e30f, l0 = 0.f, l1 = 0.f;

    const float scale = 0.08838834764831845f;   // 1/sqrt(128)
    const uint32_t qrow_off = (warp * 16 + (lane & 15)) * (AQ_STR * 2);
    const uint32_t kcol_off = (lane >> 4) * 16;  // byte offset within k16

    for (int t0 = 0; t0 < S_; t0 += 64) {
        __syncthreads();
        // stage K (rows) and V (transposed)
#pragma unroll 4
        for (int it = 0; it < 16; it++) {
            int lin = tid + it * 128;
            int r = lin >> 5;
            int c4 = (lin & 31) << 2;
            float4 kv = *(const float4*)(Kb + (size_t)(t0 + r) * HD_ + c4);
            __nv_bfloat16 h0 = __float2bfloat16_rn(kv.x), h1 = __float2bfloat16_rn(kv.y);
            __nv_bfloat16 h2 = __float2bfloat16_rn(kv.z), h3 = __float2bfloat16_rn(kv.w);
            int o0 = r * AQ_STR + c4;
            Kh[o0 + 0] = h0; Kh[o0 + 1] = h1; Kh[o0 + 2] = h2; Kh[o0 + 3] = h3;
            Kl[o0 + 0] = __float2bfloat16_rn(kv.x - __bfloat162float(h0));
            Kl[o0 + 1] = __float2bfloat16_rn(kv.y - __bfloat162float(h1));
            Kl[o0 + 2] = __float2bfloat16_rn(kv.z - __bfloat162float(h2));
            Kl[o0 + 3] = __float2bfloat16_rn(kv.w - __bfloat162float(h3));

            float4 vv = *(const float4*)(Vb + (size_t)(t0 + r) * HD_ + c4);
            float vf[4] = {vv.x, vv.y, vv.z, vv.w};
#pragma unroll
            for (int j = 0; j < 4; j++) {
                __nv_bfloat16 vh = __float2bfloat16_rn(vf[j]);
                Vth[(c4 + j) * AV_STR + r] = vh;
                Vtl[(c4 + j) * AV_STR + r] =
                    __float2bfloat16_rn(vf[j] - __bfloat162float(vh));
            }
        }
        __syncthreads();

        // ---- S = Q K^T (bf16 x3, fp32 accum) ----
        float sc[8][4];
#pragma unroll
        for (int j = 0; j < 8; j++)
#pragma unroll
            for (int c = 0; c < 4; c++) sc[j][c] = 0.f;

#pragma unroll
        for (int ks = 0; ks < 8; ks++) {
            const uint32_t kb_off = ks * 32 + kcol_off;
            uint32_t qa[4], qb[4];
            ldm_x4(uqh + qrow_off + kb_off, qa[0], qa[1], qa[2], qa[3]);
            ldm_x4(uql + qrow_off + kb_off, qb[0], qb[1], qb[2], qb[3]);
#pragma unroll
            for (int np = 0; np < 4; np++) {
                uint32_t roff = (np * 16 + (lane & 15)) * (AQ_STR * 2) + kb_off;
                uint32_t r0, r1, r2, r3, s0, s1, s2, s3;
                ldm_x4(ukh + roff, r0, r1, r2, r3);
                ldm_x4(ukl + roff, s0, s1, s2, s3);
                mma_bf16(sc[2*np][0], sc[2*np][1], sc[2*np][2], sc[2*np][3],
                         qa[0], qa[1], qa[2], qa[3], r0, r2);
                mma_bf16(sc[2*np+1][0], sc[2*np+1][1], sc[2*np+1][2], sc[2*np+1][3],
                         qa[0], qa[1], qa[2], qa[3], r1, r3);
                mma_bf16(sc[2*np][0], sc[2*np][1], sc[2*np][2], sc[2*np][3],
                         qb[0], qb[1], qb[2], qb[3], r0, r2);
                mma_bf16(sc[2*np+1][0], sc[2*np+1][1], sc[2*np+1][2], sc[2*np+1][3],
                         qb[0], qb[1], qb[2], qb[3], r1, r3);
                mma_bf16(sc[2*np][0], sc[2*np][1], sc[2*np][2], sc[2*np][3],
                         qa[0], qa[1], qa[2], qa[3], s0, s2);
                mma_bf16(sc[2*np+1][0], sc[2*np+1][1], sc[2*np+1][2], sc[2*np+1][3],
                         qa[0], qa[1], qa[2], qa[3], s1, s3);
            }
        }

        // ---- online softmax in registers ----
        float mx0 = -1e30f, mx1 = -1e30f;
#pragma unroll
        for (int j = 0; j < 8; j++) {
#pragma unroll
            for (int c = 0; c < 4; c++) sc[j][c] *= scale;
            mx0 = fmaxf(mx0, fmaxf(sc[j][0], sc[j][1]));
            mx1 = fmaxf(mx1, fmaxf(sc[j][2], sc[j][3]));
        }
        mx0 = fmaxf(mx0, __shfl_xor_sync(0xffffffffu, mx0, 1));
        mx0 = fmaxf(mx0, __shfl_xor_sync(0xffffffffu, mx0, 2));
        mx1 = fmaxf(mx1, __shfl_xor_sync(0xffffffffu, mx1, 1));
        mx1 = fmaxf(mx1, __shfl_xor_sync(0xffffffffu, mx1, 2));
        float mn0 = fmaxf(m0, mx0), mn1 = fmaxf(m1, mx1);
        float al0 = __expf(m0 - mn0), al1 = __expf(m1 - mn1);
        m0 = mn0; m1 = mn1;
        float rs0 = 0.f, rs1 = 0.f;
#pragma unroll
        for (int j = 0; j < 8; j++) {
            sc[j][0] = __expf(sc[j][0] - m0);
            sc[j][1] = __expf(sc[j][1] - m0);
            sc[j][2] = __expf(sc[j][2] - m1);
            sc[j][3] = __expf(sc[j][3] - m1);
            rs0 += sc[j][0] + sc[j][1];
            rs1 += sc[j][2] + sc[j][3];
        }
        rs0 += __shfl_xor_sync(0xffffffffu, rs0, 1);
        rs0 += __shfl_xor_sync(0xffffffffu, rs0, 2);
        rs1 += __shfl_xor_sync(0xffffffffu, rs1, 1);
        rs1 += __shfl_xor_sync(0xffffffffu, rs1, 2);
        l0 = l0 * al0 + rs0;
        l1 = l1 * al1 + rs1;
#pragma unroll
        for (int t = 0; t < 16; t++) {
            o[t][0] *= al0; o[t][1] *= al0;
            o[t][2] *= al1; o[t][3] *= al1;
        }

        // ---- O += P V (bf16 x3) ----
#pragma unroll
        for (int kb = 0; kb < 4; kb++) {
            // P fragments (hi/lo) from C-frags of S
            float e00 = sc[2*kb][0],   e01 = sc[2*kb][1];
            float e10 = sc[2*kb][2],   e11 = sc[2*kb][3];
            float f00 = sc[2*kb+1][0], f01 = sc[2*kb+1][1];
            float f10 = sc[2*kb+1][2], f11 = sc[2*kb+1][3];
            uint32_t ph0 = packbf(e00, e01), ph1 = packbf(e10, e11);
            uint32_t ph2 = packbf(f00, f01), ph3 = packbf(f10, f11);
            uint32_t pl0 = packbf(e00 - __bfloat162float(__float2bfloat16_rn(e00)),
                                  e01 - __bfloat162float(__float2bfloat16_rn(e01)));
            uint32_t pl1 = packbf(e10 - __bfloat162float(__float2bfloat16_rn(e10)),
                                  e11 - __bfloat162float(__float2bfloat16_rn(e11)));
            uint32_t pl2 = packbf(f00 - __bfloat162float(__float2bfloat16_rn(f00)),
                                  f01 - __bfloat162float(__float2bfloat16_rn(f01)));
            uint32_t pl3 = packbf(f10 - __bfloat162float(__float2bfloat16_rn(f10)),
                                  f11 - __bfloat162float(__float2bfloat16_rn(f11)));
            const uint32_t kb_off = kb * 32 + kcol_off;
#pragma unroll
            for (int np = 0; np < 8; np++) {
                uint32_t roff = (np * 16 + (lane & 15)) * (AV_STR * 2) + kb_off;
                uint32_t r0, r1, r2, r3, s0, s1, s2, s3;
                ldm_x4(uvh + roff, r0, r1, r2, r3);
                ldm_x4(uvl + roff, s0, s1, s2, s3);
                mma_bf16(o[2*np][0], o[2*np][1], o[2*np][2], o[2*np][3],
                         ph0, ph1, ph2, ph3, r0, r2);
                mma_bf16(o[2*np+1][0], o[2*np+1][1], o[2*np+1][2], o[2*np+1][3],
                         ph0, ph1, ph2, ph3, r1, r3);
                mma_bf16(o[2*np][0], o[2*np][1], o[2*np][2], o[2*np][3],
                         pl0, pl1, pl2, pl3, r0, r2);
                mma_bf16(o[2*np+1][0], o[2*np+1][1], o[2*np+1][2], o[2*np+1][3],
                         pl0, pl1, pl2, pl3, r1, r3);
                mma_bf16(o[2*np][0], o[2*np][1], o[2*np][2], o[2*np][3],
                         ph0, ph1, ph2, ph3, s0, s2);
                mma_bf16(o[2*np+1][0], o[2*np+1][1], o[2*np+1][2], o[2*np+1][3],
                         ph0, ph1, ph2, ph3, s1, s3);
            }
        }
    }

    // epilogue: normalize and write [B,S,HQ,HD]
    float inv0 = 1.0f / l0, inv1 = 1.0f / l1;
    int s0 = q0 + warp * 16 + (lane >> 2);
    int s1 = s0 + 8;
    float* p0 = O + (((size_t)b * S_ + s0) * HQ_ + h) * HD_ + 2 * (lane & 3);
    float* p1 = O + (((size_t)b * S_ + s1) * HQ_ + h) * HD_ + 2 * (lane & 3);
#pragma unroll
    for (int t = 0; t < 16; t++) {
        *(float2*)(p0 + 8 * t) = make_float2(o[t][0] * inv0, o[t][1] * inv0);
        *(float2*)(p1 + 8 * t) = make_float2(o[t][2] * inv1, o[t][3] * inv1);
    }
}

// ---------------------------------------------------------------------------
extern "C" void kernel_launch(void* const* d_in, const int* in_sizes, int n_in,
                              void* d_out, int out_size)
{
    const float* x  = (const float*)d_in[0];
    const float* wq = (const float*)d_in[1];
    const float* wk = (const float*)d_in[2];
    const float* wv = (const float*)d_in[3];
    const float* wo = (const float*)d_in[4];
    const float* fc = (const float*)d_in[5];
    const float* fs = (const float*)d_in[6];
    float* out = (float*)d_out;

    float *gq, *gk, *gv, *ga;
    cudaGetSymbolAddress((void**)&gq, g_q);
    cudaGetSymbolAddress((void**)&gk, g_k);
    cudaGetSymbolAddress((void**)&gv, g_v);
    cudaGetSymbolAddress((void**)&ga, g_att);
    __nv_bfloat16 *xh, *xl, *wqh, *wql, *wkh, *wkl, *wvh, *wvl, *woh, *wol, *ah, *al;
    cudaGetSymbolAddress((void**)&xh, g_xh);   cudaGetSymbolAddress((void**)&xl, g_xl);
    cudaGetSymbolAddress((void**)&wqh, g_wqh); cudaGetSymbolAddress((void**)&wql, g_wql);
    cudaGetSymbolAddress((void**)&wkh, g_wkh); cudaGetSymbolAddress((void**)&wkl, g_wkl);
    cudaGetSymbolAddress((void**)&wvh, g_wvh); cudaGetSymbolAddress((void**)&wvl, g_wvl);
    cudaGetSymbolAddress((void**)&woh, g_woh); cudaGetSymbolAddress((void**)&wol, g_wol);
    cudaGetSymbolAddress((void**)&ah, g_ah);   cudaGetSymbolAddress((void**)&al, g_al);

    const int M = B_ * S_;  // 4096

    // splits
    int n4x = (B_ * S_ * D_) / 4;
    split_kernel<<<(n4x + 255) / 256, 256>>>(x, xh, xl, n4x);
    int n4q = (HQ_ * HD_ * D_) / 4;
    split_kernel<<<(n4q + 255) / 256, 256>>>(wq, wqh, wql, n4q);
    int n4k = (HKV_ * HD_ * D_) / 4;
    split_kernel<<<(n4k + 255) / 256, 256>>>(wk, wkh, wkl, n4k);
    split_kernel<<<(n4k + 255) / 256, 256>>>(wv, wvh, wvl, n4k);
    int n4o = (D_ * HQ_ * HD_) / 4;
    split_kernel<<<(n4o + 255) / 256, 256>>>(wo, woh, wol, n4o);

    cudaFuncSetAttribute(gemm_bf16x3, cudaFuncAttributeMaxDynamicSharedMemorySize, GSMEM);

    // QKV projections (write head-split fp32 layouts)
    gemm_bf16x3<<<dim3((HQ_ * HD_) / 128, M / 128), 256, GSMEM>>>(
        xh, xl, wqh, wql, gq, M, HQ_ * HD_, D_, 1, HQ_);
    gemm_bf16x3<<<dim3((HKV_ * HD_) / 128, M / 128), 256, GSMEM>>>(
        xh, xl, wkh, wkl, gk, M, HKV_ * HD_, D_, 1, HKV_);
    gemm_bf16x3<<<dim3((HKV_ * HD_) / 128, M / 128), 256, GSMEM>>>(
        xh, xl, wvh, wvl, gv, M, HKV_ * HD_, D_, 1, HKV_);

    // RoPE on Q and K
    long npairs = (long)B_ * (HQ_ + HKV_) * S_ * (HD_ / 2);
    rope_kernel<<<(unsigned)((npairs + 255) / 256), 256>>>(gq, gk, fc, fs);

    // tensor-core attention
    cudaFuncSetAttribute(attn_mma, cudaFuncAttributeMaxDynamicSharedMemorySize, ATT_SMEM);
    attn_mma<<<dim3(S_ / 64, B_ * HQ_), 128, ATT_SMEM>>>(gq, gk, gv, ga);

    // split attention output, then output projection -> d_out
    int n4a = (B_ * S_ * HQ_ * HD_) / 4;
    split_kernel<<<(n4a + 255) / 256, 256>>>(ga, ah, al, n4a);
    gemm_bf16x3<<<dim3(D_ / 128, M / 128), 256, GSMEM>>>(
        ah, al, woh, wol, out, M, D_, D_, 0, 0);
}

// round 6
// speedup vs baseline: 2.4592x; 1.4019x over previous
#include <cuda_runtime.h>
#include <cuda_bf16.h>
#include <cstdint>
#include <math.h>

#define B_   2
#define S_   2048
#define D_   4096
#define HQ_  32
#define HKV_ 8
#define HD_  128

typedef unsigned long long u64;

// ---------------- scratch (static device globals; no allocations) ----------
// bf16 hi/lo split inputs
__device__ __nv_bfloat16 g_xh[(size_t)B_ * S_ * D_];
__device__ __nv_bfloat16 g_xl[(size_t)B_ * S_ * D_];
__device__ __nv_bfloat16 g_wqh[(size_t)HQ_ * HD_ * D_];
__device__ __nv_bfloat16 g_wql[(size_t)HQ_ * HD_ * D_];
__device__ __nv_bfloat16 g_wkh[(size_t)HKV_ * HD_ * D_];
__device__ __nv_bfloat16 g_wkl[(size_t)HKV_ * HD_ * D_];
__device__ __nv_bfloat16 g_wvh[(size_t)HKV_ * HD_ * D_];
__device__ __nv_bfloat16 g_wvl[(size_t)HKV_ * HD_ * D_];
__device__ __nv_bfloat16 g_woh[(size_t)D_ * HQ_ * HD_];
__device__ __nv_bfloat16 g_wol[(size_t)D_ * HQ_ * HD_];
// rope'd Q/K, transposed V (all bf16 h/l)
__device__ __nv_bfloat16 g_qh[(size_t)B_ * HQ_ * S_ * HD_];   // [B,HQ,S,HD]
__device__ __nv_bfloat16 g_ql[(size_t)B_ * HQ_ * S_ * HD_];
__device__ __nv_bfloat16 g_kh[(size_t)B_ * HKV_ * S_ * HD_];  // [B,HKV,S,HD]
__device__ __nv_bfloat16 g_kl[(size_t)B_ * HKV_ * S_ * HD_];
__device__ __nv_bfloat16 g_vth[(size_t)B_ * HKV_ * HD_ * S_]; // [B,HKV,HD,S]
__device__ __nv_bfloat16 g_vtl[(size_t)B_ * HKV_ * HD_ * S_];
// attention output (bf16 h/l, [B,S,HQ,HD])
__device__ __nv_bfloat16 g_ah[(size_t)B_ * S_ * HQ_ * HD_];
__device__ __nv_bfloat16 g_al[(size_t)B_ * S_ * HQ_ * HD_];

// ---------------- PTX helpers (family-portable only) -----------------------
__device__ __forceinline__ uint32_t smem_u32(const void* p) {
    uint32_t a;
    asm("{ .reg .u64 t; cvta.to.shared.u64 t, %1; cvt.u32.u64 %0, t; }" : "=r"(a) : "l"(p));
    return a;
}
__device__ __forceinline__ void cp16(uint32_t s, const void* g) {
    asm volatile("cp.async.cg.shared.global [%0], [%1], 16;" :: "r"(s), "l"(g));
}
__device__ __forceinline__ void cp_commit() {
    asm volatile("cp.async.commit_group;" ::: "memory");
}
__device__ __forceinline__ void ldm_x4(uint32_t a, uint32_t& r0, uint32_t& r1,
                                       uint32_t& r2, uint32_t& r3) {
    asm volatile("ldmatrix.sync.aligned.m8n8.x4.shared.b16 {%0,%1,%2,%3}, [%4];"
                 : "=r"(r0), "=r"(r1), "=r"(r2), "=r"(r3) : "r"(a));
}
__device__ __forceinline__ void mma_bf16(float& d0, float& d1, float& d2, float& d3,
                                         uint32_t a0, uint32_t a1, uint32_t a2, uint32_t a3,
                                         uint32_t b0, uint32_t b1) {
    asm volatile("mma.sync.aligned.m16n8k16.row.col.f32.bf16.bf16.f32 "
                 "{%0,%1,%2,%3}, {%4,%5,%6,%7}, {%8,%9}, {%0,%1,%2,%3};"
                 : "+f"(d0), "+f"(d1), "+f"(d2), "+f"(d3)
                 : "r"(a0), "r"(a1), "r"(a2), "r"(a3), "r"(b0), "r"(b1));
}
__device__ __forceinline__ uint32_t packbf(float lo, float hi) {
    __nv_bfloat162 t = __floats2bfloat162_rn(lo, hi);
    return *(uint32_t*)&t;
}

// ---------------------------------------------------------------------------
// split fp32 -> bf16 hi + bf16 lo
// ---------------------------------------------------------------------------
__global__ void split_kernel(const float* __restrict__ in,
                             __nv_bfloat16* __restrict__ hi,
                             __nv_bfloat16* __restrict__ lo, int n4)
{
    int i = blockIdx.x * blockDim.x + threadIdx.x;
    if (i >= n4) return;
    float4 v = ((const float4*)in)[i];
    __nv_bfloat16 h0 = __float2bfloat16_rn(v.x);
    __nv_bfloat16 h1 = __float2bfloat16_rn(v.y);
    __nv_bfloat16 h2 = __float2bfloat16_rn(v.z);
    __nv_bfloat16 h3 = __float2bfloat16_rn(v.w);
    __nv_bfloat16 l0 = __float2bfloat16_rn(v.x - __bfloat162float(h0));
    __nv_bfloat16 l1 = __float2bfloat16_rn(v.y - __bfloat162float(h1));
    __nv_bfloat16 l2 = __float2bfloat16_rn(v.z - __bfloat162float(h2));
    __nv_bfloat16 l3 = __float2bfloat16_rn(v.w - __bfloat162float(h3));
    __nv_bfloat162* hp = (__nv_bfloat162*)(hi + 4 * (size_t)i);
    __nv_bfloat162* lp = (__nv_bfloat162*)(lo + 4 * (size_t)i);
    hp[0] = __halves2bfloat162(h0, h1);
    hp[1] = __halves2bfloat162(h2, h3);
    lp[0] = __halves2bfloat162(l0, l1);
    lp[1] = __halves2bfloat162(l2, l3);
}

// ---------------------------------------------------------------------------
// bf16x3 GEMM (NT) via mma.sync. Epilogue modes:
//  0: write fp32 C[M,N]
//  1: rope + bf16 h/l split, head layout ((b*H+h)*S+s)*HD+d  (Q and K)
//  2: bf16 h/l split, transposed V layout ((b*H+h)*HD+d)*S+s (V, no rope)
// ---------------------------------------------------------------------------
#define RSTR   40
#define TILE_B (128 * RSTR * 2)
#define STG_B  (4 * TILE_B)
#define GSMEM  (2 * STG_B)

__global__ __launch_bounds__(256, 1) void gemm_bf16x3(
    const __nv_bfloat16* __restrict__ Ah, const __nv_bfloat16* __restrict__ Al,
    const __nv_bfloat16* __restrict__ Bh, const __nv_bfloat16* __restrict__ Bl,
    float* __restrict__ Cf,
    __nv_bfloat16* __restrict__ Ch, __nv_bfloat16* __restrict__ Cl,
    int M, int N, int K, int mode, int H,
    const float* __restrict__ fc, const float* __restrict__ fs)
{
    extern __shared__ char smem[];
    const uint32_t sb = smem_u32(smem);
    const int tid = threadIdx.x;
    const int lane = tid & 31;
    const int wid = tid >> 5;
    const int wm = wid >> 2;
    const int wn = wid & 3;
    const int bm = blockIdx.y * 128;
    const int bn = blockIdx.x * 128;

    float acc[4][4][4];
#pragma unroll
    for (int i = 0; i < 4; i++)
#pragma unroll
        for (int j = 0; j < 4; j++)
#pragma unroll
            for (int c = 0; c < 4; c++) acc[i][j][c] = 0.f;

    const int iters = K >> 5;
    const int row0 = tid >> 2;
    const int col0 = tid & 3;

#define PREFETCH(it_) do {                                                    \
    const int st_ = (it_) & 1;                                                \
    const int k0_ = (it_) << 5;                                               \
    const uint32_t sob_ = sb + st_ * STG_B;                                   \
    _Pragma("unroll")                                                         \
    for (int j_ = 0; j_ < 2; j_++) {                                          \
        int row_ = row0 + j_ * 64;                                            \
        uint32_t so_ = sob_ + row_ * (RSTR * 2) + col0 * 16;                  \
        size_t ga_ = (size_t)(bm + row_) * K + k0_ + col0 * 8;                \
        size_t gb_ = (size_t)(bn + row_) * K + k0_ + col0 * 8;                \
        cp16(so_ + 0 * TILE_B, Ah + ga_);                                     \
        cp16(so_ + 1 * TILE_B, Al + ga_);                                     \
        cp16(so_ + 2 * TILE_B, Bh + gb_);                                     \
        cp16(so_ + 3 * TILE_B, Bl + gb_);                                     \
    }                                                                         \
    cp_commit();                                                              \
} while (0)

    PREFETCH(0);
    if (iters > 1) PREFETCH(1);

    for (int it = 0; it < iters; it++) {
        if (it + 1 < iters) {
            asm volatile("cp.async.wait_group 1;" ::: "memory");
        } else {
            asm volatile("cp.async.wait_group 0;" ::: "memory");
        }
        __syncthreads();

        const uint32_t base = sb + (it & 1) * STG_B;
        const uint32_t a_h = base;
        const uint32_t a_l = base + TILE_B;
        const uint32_t b_h = base + 2 * TILE_B;
        const uint32_t b_l = base + 3 * TILE_B;

#pragma unroll
        for (int kk = 0; kk < 2; kk++) {
            const int kc = kk * 16 + (lane >> 4) * 8;
            uint32_t a[4][4], bhf[4][2], blf[4][2];
#pragma unroll
            for (int nq = 0; nq < 2; nq++) {
                int row = wn * 32 + nq * 16 + (lane & 15);
                uint32_t off = row * (RSTR * 2) + kc * 2;
                uint32_t r0, r1, r2, r3;
                ldm_x4(b_h + off, r0, r1, r2, r3);
                bhf[nq * 2][0] = r0; bhf[nq * 2][1] = r2;
                bhf[nq * 2 + 1][0] = r1; bhf[nq * 2 + 1][1] = r3;
                ldm_x4(b_l + off, r0, r1, r2, r3);
                blf[nq * 2][0] = r0; blf[nq * 2][1] = r2;
                blf[nq * 2 + 1][0] = r1; blf[nq * 2 + 1][1] = r3;
            }
#pragma unroll
            for (int mf = 0; mf < 4; mf++) {
                int row = wm * 64 + mf * 16 + (lane & 15);
                ldm_x4(a_h + row * (RSTR * 2) + kc * 2,
                       a[mf][0], a[mf][1], a[mf][2], a[mf][3]);
            }
#pragma unroll
            for (int mf = 0; mf < 4; mf++)
#pragma unroll
                for (int nf = 0; nf < 4; nf++) {
                    mma_bf16(acc[mf][nf][0], acc[mf][nf][1], acc[mf][nf][2], acc[mf][nf][3],
                             a[mf][0], a[mf][1], a[mf][2], a[mf][3],
                             bhf[nf][0], bhf[nf][1]);
                    mma_bf16(acc[mf][nf][0], acc[mf][nf][1], acc[mf][nf][2], acc[mf][nf][3],
                             a[mf][0], a[mf][1], a[mf][2], a[mf][3],
                             blf[nf][0], blf[nf][1]);
                }
#pragma unroll
            for (int mf = 0; mf < 4; mf++) {
                int row = wm * 64 + mf * 16 + (lane & 15);
                ldm_x4(a_l + row * (RSTR * 2) + kc * 2,
                       a[mf][0], a[mf][1], a[mf][2], a[mf][3]);
            }
#pragma unroll
            for (int mf = 0; mf < 4; mf++)
#pragma unroll
                for (int nf = 0; nf < 4; nf++)
                    mma_bf16(acc[mf][nf][0], acc[mf][nf][1], acc[mf][nf][2], acc[mf][nf][3],
                             a[mf][0], a[mf][1], a[mf][2], a[mf][3],
                             bhf[nf][0], bhf[nf][1]);
        }

        __syncthreads();
        if (it + 2 < iters) PREFETCH(it + 2);
    }

    const int qr = lane >> 2;
    const int qc = lane & 3;
#pragma unroll
    for (int mf = 0; mf < 4; mf++) {
#pragma unroll
        for (int half = 0; half < 2; half++) {
            int m = bm + wm * 64 + mf * 16 + qr + half * 8;
            if (mode == 0) {
                float* dst = Cf + (size_t)m * N + bn;
#pragma unroll
                for (int nf = 0; nf < 4; nf++) {
                    int n = wn * 32 + nf * 8 + 2 * qc;
                    float2 w = half ? make_float2(acc[mf][nf][2], acc[mf][nf][3])
                                    : make_float2(acc[mf][nf][0], acc[mf][nf][1]);
                    *(float2*)(dst + n) = w;
                }
            } else {
                int b = m >> 11;
                int s = m & (S_ - 1);
#pragma unroll
                for (int nf = 0; nf < 4; nf++) {
                    int n = bn + wn * 32 + nf * 8 + 2 * qc;
                    int h = n >> 7;
                    int d = n & (HD_ - 1);
                    float2 w = half ? make_float2(acc[mf][nf][2], acc[mf][nf][3])
                                    : make_float2(acc[mf][nf][0], acc[mf][nf][1]);
                    float x0, x1;
                    if (mode == 1) {
                        int i = d >> 1;
                        float c = fc[s * (HD_ / 2) + i];
                        float sn = fs[s * (HD_ / 2) + i];
                        x0 = w.x * c - w.y * sn;
                        x1 = w.x * sn + w.y * c;
                    } else {
                        x0 = w.x; x1 = w.y;
                    }
                    __nv_bfloat16 h0 = __float2bfloat16_rn(x0);
                    __nv_bfloat16 h1 = __float2bfloat16_rn(x1);
                    __nv_bfloat16 l0 = __float2bfloat16_rn(x0 - __bfloat162float(h0));
                    __nv_bfloat16 l1 = __float2bfloat16_rn(x1 - __bfloat162float(h1));
                    if (mode == 1) {
                        size_t off = (((size_t)b * H + h) * S_ + s) * HD_ + d;
                        *(__nv_bfloat162*)(Ch + off) = __halves2bfloat162(h0, h1);
                        *(__nv_bfloat162*)(Cl + off) = __halves2bfloat162(l0, l1);
                    } else {
                        size_t off = (((size_t)b * H + h) * HD_ + d) * S_ + s;
                        Ch[off] = h0; Cl[off] = l0;
                        Ch[off + S_] = h1; Cl[off + S_] = l1;
                    }
                }
            }
        }
    }
#undef PREFETCH
}

// ---------------------------------------------------------------------------
// Tensor-core flash attention v2: all operands pre-split bf16 in global,
// cp.async double-buffered staging, zero conversions in the loop.
// Grid (S/128, B*HQ), block 256 (8 warps); warp w owns q-rows w*16..w*16+15.
// Q,K smem rows: 128 data bf16 + 8 pad (QROW_B=272 bytes).
// Vt smem rows (d): 64 data bf16 + 8 pad (VROW_B=144 bytes).
// ---------------------------------------------------------------------------
#define QT 128
#define KT 64
#define QROW_B 272
#define VROW_B 144
#define QTILE_B (QT * QROW_B)     // 34816
#define KTILE_B (KT * QROW_B)     // 17408
#define VTILE_B (128 * VROW_B)    // 18432
#define OFF_Q   0
#define OFF_K   (2 * QTILE_B)               // 69632
#define OFF_V   (OFF_K + 4 * KTILE_B)       // 139264
#define ATT_SMEM (OFF_V + 4 * VTILE_B)      // 212992

__global__ __launch_bounds__(256) void attn_mma2(
    const __nv_bfloat16* __restrict__ Qh_g, const __nv_bfloat16* __restrict__ Ql_g,
    const __nv_bfloat16* __restrict__ Kh_g, const __nv_bfloat16* __restrict__ Kl_g,
    const __nv_bfloat16* __restrict__ Vh_g, const __nv_bfloat16* __restrict__ Vl_g,
    __nv_bfloat16* __restrict__ Oh, __nv_bfloat16* __restrict__ Ol)
{
    extern __shared__ char smem[];
    const uint32_t sb = smem_u32(smem);
    const int bh = blockIdx.y;
    const int b = bh >> 5;
    const int h = bh & (HQ_ - 1);
    const int kvh = h >> 2;
    const int q0 = blockIdx.x * QT;
    const int tid = threadIdx.x;
    const int lane = tid & 31;
    const int warp = tid >> 5;

    const __nv_bfloat16* qh = Qh_g + (((size_t)b * HQ_ + h) * S_ + q0) * HD_;
    const __nv_bfloat16* ql = Ql_g + (((size_t)b * HQ_ + h) * S_ + q0) * HD_;
    const __nv_bfloat16* kh = Kh_g + ((size_t)b * HKV_ + kvh) * S_ * HD_;
    const __nv_bfloat16* kl = Kl_g + ((size_t)b * HKV_ + kvh) * S_ * HD_;
    const __nv_bfloat16* vh = Vh_g + ((size_t)b * HKV_ + kvh) * HD_ * S_;
    const __nv_bfloat16* vl = Vl_g + ((size_t)b * HKV_ + kvh) * HD_ * S_;

    // stage Q (group 0)
#pragma unroll
    for (int i = 0; i < 8; i++) {
        int lin = tid + i * 256;
        int r = lin >> 4, c = lin & 15;
        cp16(sb + OFF_Q + r * QROW_B + c * 16, qh + (size_t)r * HD_ + c * 8);
        cp16(sb + OFF_Q + QTILE_B + r * QROW_B + c * 16, ql + (size_t)r * HD_ + c * 8);
    }
    cp_commit();

#define STAGE_KV(t_, buf_) do {                                               \
    int t0_ = (t_) * KT;                                                      \
    uint32_t kb_ = sb + OFF_K + (buf_) * (2 * KTILE_B);                       \
    uint32_t vb_ = sb + OFF_V + (buf_) * (2 * VTILE_B);                       \
    _Pragma("unroll")                                                         \
    for (int i_ = 0; i_ < 4; i_++) {                                          \
        int lin_ = tid + i_ * 256;                                            \
        int r_ = lin_ >> 4, c_ = lin_ & 15;                                   \
        cp16(kb_ + r_ * QROW_B + c_ * 16, kh + (size_t)(t0_ + r_) * HD_ + c_ * 8); \
        cp16(kb_ + KTILE_B + r_ * QROW_B + c_ * 16, kl + (size_t)(t0_ + r_) * HD_ + c_ * 8); \
        int d_ = lin_ >> 3, c2_ = lin_ & 7;                                   \
        cp16(vb_ + d_ * VROW_B + c2_ * 16, vh + (size_t)d_ * S_ + t0_ + c2_ * 8); \
        cp16(vb_ + VTILE_B + d_ * VROW_B + c2_ * 16, vl + (size_t)d_ * S_ + t0_ + c2_ * 8); \
    }                                                                         \
    cp_commit();                                                              \
} while (0)

    STAGE_KV(0, 0);
    STAGE_KV(1, 1);

    float o[16][4];
#pragma unroll
    for (int t = 0; t < 16; t++)
#pragma unroll
        for (int c = 0; c < 4; c++) o[t][c] = 0.f;
    float m0 = -1e30f, m1 = -1e30f, l0v = 0.f, l1v = 0.f;

    const float scale = 0.08838834764831845f;   // 1/sqrt(128)
    const uint32_t uqh = sb + OFF_Q;
    const uint32_t uql = uqh + QTILE_B;
    const uint32_t qrow_off = (warp * 16 + (lane & 15)) * QROW_B;
    const uint32_t kcol_off = (lane >> 4) * 16;

    const int T = S_ / KT;   // 32
    for (int t = 0; t < T; t++) {
        if (t + 1 < T) {
            asm volatile("cp.async.wait_group 1;" ::: "memory");
        } else {
            asm volatile("cp.async.wait_group 0;" ::: "memory");
        }
        __syncthreads();

        const int buf = t & 1;
        const uint32_t ukh = sb + OFF_K + buf * (2 * KTILE_B);
        const uint32_t ukl = ukh + KTILE_B;
        const uint32_t uvh = sb + OFF_V + buf * (2 * VTILE_B);
        const uint32_t uvl = uvh + VTILE_B;

        // ---- S = Q K^T (bf16 x3, fp32 accum) ----
        float sc[8][4];
#pragma unroll
        for (int j = 0; j < 8; j++)
#pragma unroll
            for (int c = 0; c < 4; c++) sc[j][c] = 0.f;

#pragma unroll
        for (int ks = 0; ks < 8; ks++) {
            const uint32_t kb_off = ks * 32 + kcol_off;
            uint32_t qa[4], qb[4];
            ldm_x4(uqh + qrow_off + kb_off, qa[0], qa[1], qa[2], qa[3]);
            ldm_x4(uql + qrow_off + kb_off, qb[0], qb[1], qb[2], qb[3]);
#pragma unroll
            for (int np = 0; np < 4; np++) {
                uint32_t roff = (np * 16 + (lane & 15)) * QROW_B + kb_off;
                uint32_t r0, r1, r2, r3, s0, s1, s2, s3;
                ldm_x4(ukh + roff, r0, r1, r2, r3);
                ldm_x4(ukl + roff, s0, s1, s2, s3);
                mma_bf16(sc[2*np][0], sc[2*np][1], sc[2*np][2], sc[2*np][3],
                         qa[0], qa[1], qa[2], qa[3], r0, r2);
                mma_bf16(sc[2*np+1][0], sc[2*np+1][1], sc[2*np+1][2], sc[2*np+1][3],
                         qa[0], qa[1], qa[2], qa[3], r1, r3);
                mma_bf16(sc[2*np][0], sc[2*np][1], sc[2*np][2], sc[2*np][3],
                         qb[0], qb[1], qb[2], qb[3], r0, r2);
                mma_bf16(sc[2*np+1][0], sc[2*np+1][1], sc[2*np+1][2], sc[2*np+1][3],
                         qb[0], qb[1], qb[2], qb[3], r1, r3);
                mma_bf16(sc[2*np][0], sc[2*np][1], sc[2*np][2], sc[2*np][3],
                         qa[0], qa[1], qa[2], qa[3], s0, s2);
                mma_bf16(sc[2*np+1][0], sc[2*np+1][1], sc[2*np+1][2], sc[2*np+1][3],
                         qa[0], qa[1], qa[2], qa[3], s1, s3);
            }
        }

        // ---- online softmax in registers ----
        float mx0 = -1e30f, mx1 = -1e30f;
#pragma unroll
        for (int j = 0; j < 8; j++) {
#pragma unroll
            for (int c = 0; c < 4; c++) sc[j][c] *= scale;
            mx0 = fmaxf(mx0, fmaxf(sc[j][0], sc[j][1]));
            mx1 = fmaxf(mx1, fmaxf(sc[j][2], sc[j][3]));
        }
        mx0 = fmaxf(mx0, __shfl_xor_sync(0xffffffffu, mx0, 1));
        mx0 = fmaxf(mx0, __shfl_xor_sync(0xffffffffu, mx0, 2));
        mx1 = fmaxf(mx1, __shfl_xor_sync(0xffffffffu, mx1, 1));
        mx1 = fmaxf(mx1, __shfl_xor_sync(0xffffffffu, mx1, 2));
        float mn0 = fmaxf(m0, mx0), mn1 = fmaxf(m1, mx1);
        float al0 = __expf(m0 - mn0), al1 = __expf(m1 - mn1);
        m0 = mn0; m1 = mn1;
        float rs0 = 0.f, rs1 = 0.f;
#pragma unroll
        for (int j = 0; j < 8; j++) {
            sc[j][0] = __expf(sc[j][0] - m0);
            sc[j][1] = __expf(sc[j][1] - m0);
            sc[j][2] = __expf(sc[j][2] - m1);
            sc[j][3] = __expf(sc[j][3] - m1);
            rs0 += sc[j][0] + sc[j][1];
            rs1 += sc[j][2] + sc[j][3];
        }
        rs0 += __shfl_xor_sync(0xffffffffu, rs0, 1);
        rs0 += __shfl_xor_sync(0xffffffffu, rs0, 2);
        rs1 += __shfl_xor_sync(0xffffffffu, rs1, 1);
        rs1 += __shfl_xor_sync(0xffffffffu, rs1, 2);
        l0v = l0v * al0 + rs0;
        l1v = l1v * al1 + rs1;
#pragma unroll
        for (int tt = 0; tt < 16; tt++) {
            o[tt][0] *= al0; o[tt][1] *= al0;
            o[tt][2] *= al1; o[tt][3] *= al1;
        }

        // ---- O += P V (bf16 x3) ----
#pragma unroll
        for (int kb = 0; kb < 4; kb++) {
            float e00 = sc[2*kb][0],   e01 = sc[2*kb][1];
            float e10 = sc[2*kb][2],   e11 = sc[2*kb][3];
            float f00 = sc[2*kb+1][0], f01 = sc[2*kb+1][1];
            float f10 = sc[2*kb+1][2], f11 = sc[2*kb+1][3];
            uint32_t ph0 = packbf(e00, e01), ph1 = packbf(e10, e11);
            uint32_t ph2 = packbf(f00, f01), ph3 = packbf(f10, f11);
            uint32_t pl0 = packbf(e00 - __bfloat162float(__float2bfloat16_rn(e00)),
                                  e01 - __bfloat162float(__float2bfloat16_rn(e01)));
            uint32_t pl1 = packbf(e10 - __bfloat162float(__float2bfloat16_rn(e10)),
                                  e11 - __bfloat162float(__float2bfloat16_rn(e11)));
            uint32_t pl2 = packbf(f00 - __bfloat162float(__float2bfloat16_rn(f00)),
                                  f01 - __bfloat162float(__float2bfloat16_rn(f01)));
            uint32_t pl3 = packbf(f10 - __bfloat162float(__float2bfloat16_rn(f10)),
                                  f11 - __bfloat162float(__float2bfloat16_rn(f11)));
            const uint32_t kb_off = kb * 32 + kcol_off;
#pragma unroll
            for (int np = 0; np < 8; np++) {
                uint32_t roff = (np * 16 + (lane & 15)) * VROW_B + kb_off;
                uint32_t r0, r1, r2, r3, s0, s1, s2, s3;
                ldm_x4(uvh + roff, r0, r1, r2, r3);
                ldm_x4(uvl + roff, s0, s1, s2, s3);
                mma_bf16(o[2*np][0], o[2*np][1], o[2*np][2], o[2*np][3],
                         ph0, ph1, ph2, ph3, r0, r2);
                mma_bf16(o[2*np+1][0], o[2*np+1][1], o[2*np+1][2], o[2*np+1][3],
                         ph0, ph1, ph2, ph3, r1, r3);
                mma_bf16(o[2*np][0], o[2*np][1], o[2*np][2], o[2*np][3],
                         pl0, pl1, pl2, pl3, r0, r2);
                mma_bf16(o[2*np+1][0], o[2*np+1][1], o[2*np+1][2], o[2*np+1][3],
                         pl0, pl1, pl2, pl3, r1, r3);
                mma_bf16(o[2*np][0], o[2*np][1], o[2*np][2], o[2*np][3],
                         ph0, ph1, ph2, ph3, s0, s2);
                mma_bf16(o[2*np+1][0], o[2*np+1][1], o[2*np+1][2], o[2*np+1][3],
                         ph0, ph1, ph2, ph3, s1, s3);
            }
        }

        __syncthreads();
        if (t + 2 < T) STAGE_KV(t + 2, buf);
    }
#undef STAGE_KV

    // epilogue: normalize, split to bf16 h/l, write [B,S,HQ,HD]
    float inv0 = 1.0f / l0v, inv1 = 1.0f / l1v;
    int s0 = q0 + warp * 16 + (lane >> 2);
    int s1 = s0 + 8;
    size_t base0 = (((size_t)b * S_ + s0) * HQ_ + h) * HD_ + 2 * (lane & 3);
    size_t base1 = (((size_t)b * S_ + s1) * HQ_ + h) * HD_ + 2 * (lane & 3);
#pragma unroll
    for (int t = 0; t < 16; t++) {
        float x0 = o[t][0] * inv0, x1 = o[t][1] * inv0;
        float y0 = o[t][2] * inv1, y1 = o[t][3] * inv1;
        __nv_bfloat16 xh0 = __float2bfloat16_rn(x0), xh1 = __float2bfloat16_rn(x1);
        __nv_bfloat16 yh0 = __float2bfloat16_rn(y0), yh1 = __float2bfloat16_rn(y1);
        *(__nv_bfloat162*)(Oh + base0 + 8 * t) = __halves2bfloat162(xh0, xh1);
        *(__nv_bfloat162*)(Ol + base0 + 8 * t) = __halves2bfloat162(
            __float2bfloat16_rn(x0 - __bfloat162float(xh0)),
            __float2bfloat16_rn(x1 - __bfloat162float(xh1)));
        *(__nv_bfloat162*)(Oh + base1 + 8 * t) = __halves2bfloat162(yh0, yh1);
        *(__nv_bfloat162*)(Ol + base1 + 8 * t) = __halves2bfloat162(
            __float2bfloat16_rn(y0 - __bfloat162float(yh0)),
            __float2bfloat16_rn(y1 - __bfloat162float(yh1)));
    }
}

// ---------------------------------------------------------------------------
extern "C" void kernel_launch(void* const* d_in, const int* in_sizes, int n_in,
                              void* d_out, int out_size)
{
    const float* x  = (const float*)d_in[0];
    const float* wq = (const float*)d_in[1];
    const float* wk = (const float*)d_in[2];
    const float* wv = (const float*)d_in[3];
    const float* wo = (const float*)d_in[4];
    const float* fc = (const float*)d_in[5];
    const float* fs = (const float*)d_in[6];
    float* out = (float*)d_out;

    __nv_bfloat16 *xh, *xl, *wqh, *wql, *wkh, *wkl, *wvh, *wvl, *woh, *wol;
    __nv_bfloat16 *qh, *ql, *kh, *kl, *vth, *vtl, *ah, *al;
    cudaGetSymbolAddress((void**)&xh, g_xh);   cudaGetSymbolAddress((void**)&xl, g_xl);
    cudaGetSymbolAddress((void**)&wqh, g_wqh); cudaGetSymbolAddress((void**)&wql, g_wql);
    cudaGetSymbolAddress((void**)&wkh, g_wkh); cudaGetSymbolAddress((void**)&wkl, g_wkl);
    cudaGetSymbolAddress((void**)&wvh, g_wvh); cudaGetSymbolAddress((void**)&wvl, g_wvl);
    cudaGetSymbolAddress((void**)&woh, g_woh); cudaGetSymbolAddress((void**)&wol, g_wol);
    cudaGetSymbolAddress((void**)&qh, g_qh);   cudaGetSymbolAddress((void**)&ql, g_ql);
    cudaGetSymbolAddress((void**)&kh, g_kh);   cudaGetSymbolAddress((void**)&kl, g_kl);
    cudaGetSymbolAddress((void**)&vth, g_vth); cudaGetSymbolAddress((void**)&vtl, g_vtl);
    cudaGetSymbolAddress((void**)&ah, g_ah);   cudaGetSymbolAddress((void**)&al, g_al);

    const int M = B_ * S_;  // 4096

    // input splits
    int n4x = (B_ * S_ * D_) / 4;
    split_kernel<<<(n4x + 255) / 256, 256>>>(x, xh, xl, n4x);
    int n4q = (HQ_ * HD_ * D_) / 4;
    split_kernel<<<(n4q + 255) / 256, 256>>>(wq, wqh, wql, n4q);
    int n4k = (HKV_ * HD_ * D_) / 4;
    split_kernel<<<(n4k + 255) / 256, 256>>>(wk, wkh, wkl, n4k);
    split_kernel<<<(n4k + 255) / 256, 256>>>(wv, wvh, wvl, n4k);
    int n4o = (D_ * HQ_ * HD_) / 4;
    split_kernel<<<(n4o + 255) / 256, 256>>>(wo, woh, wol, n4o);

    cudaFuncSetAttribute(gemm_bf16x3, cudaFuncAttributeMaxDynamicSharedMemorySize, GSMEM);

    // QKV projections: rope fused for Q/K, transpose fused for V, bf16 h/l out
    gemm_bf16x3<<<dim3((HQ_ * HD_) / 128, M / 128), 256, GSMEM>>>(
        xh, xl, wqh, wql, nullptr, qh, ql, M, HQ_ * HD_, D_, 1, HQ_, fc, fs);
    gemm_bf16x3<<<dim3((HKV_ * HD_) / 128, M / 128), 256, GSMEM>>>(
        xh, xl, wkh, wkl, nullptr, kh, kl, M, HKV_ * HD_, D_, 1, HKV_, fc, fs);
    gemm_bf16x3<<<dim3((HKV_ * HD_) / 128, M / 128), 256, GSMEM>>>(
        xh, xl, wvh, wvl, nullptr, vth, vtl, M, HKV_ * HD_, D_, 2, HKV_, fc, fs);

    // tensor-core attention (writes ah/al bf16 h/l directly)
    cudaFuncSetAttribute(attn_mma2, cudaFuncAttributeMaxDynamicSharedMemorySize, ATT_SMEM);
    attn_mma2<<<dim3(S_ / QT, B_ * HQ_), 256, ATT_SMEM>>>(
        qh, ql, kh, kl, vth, vtl, ah, al);

    // output projection -> d_out
    gemm_bf16x3<<<dim3(D_ / 128, M / 128), 256, GSMEM>>>(
        ah, al, woh, wol, out, nullptr, nullptr, M, D_, D_, 0, 0, fc, fs);
}

// round 7
// speedup vs baseline: 2.7426x; 1.1152x over previous
#include <cuda_runtime.h>
#include <cuda_bf16.h>
#include <cstdint>
#include <math.h>

#define B_   2
#define S_   2048
#define D_   4096
#define HQ_  32
#define HKV_ 8
#define HD_  128

typedef unsigned long long u64;

// ---------------- scratch (static device globals; no allocations) ----------
__device__ __nv_bfloat16 g_xh[(size_t)B_ * S_ * D_];
__device__ __nv_bfloat16 g_xl[(size_t)B_ * S_ * D_];
// stacked QKV weights: rows [0,4096)=wq, [4096,5120)=wk, [5120,6144)=wv
#define NQKV (HQ_ * HD_ + 2 * HKV_ * HD_)   // 6144
__device__ __nv_bfloat16 g_wqkvh[(size_t)NQKV * D_];
__device__ __nv_bfloat16 g_wqkvl[(size_t)NQKV * D_];
__device__ __nv_bfloat16 g_woh[(size_t)D_ * HQ_ * HD_];
__device__ __nv_bfloat16 g_wol[(size_t)D_ * HQ_ * HD_];
// rope'd Q/K, transposed V (bf16 h/l)
__device__ __nv_bfloat16 g_qh[(size_t)B_ * HQ_ * S_ * HD_];   // [B,HQ,S,HD]
__device__ __nv_bfloat16 g_ql[(size_t)B_ * HQ_ * S_ * HD_];
__device__ __nv_bfloat16 g_kh[(size_t)B_ * HKV_ * S_ * HD_];  // [B,HKV,S,HD]
__device__ __nv_bfloat16 g_kl[(size_t)B_ * HKV_ * S_ * HD_];
__device__ __nv_bfloat16 g_vth[(size_t)B_ * HKV_ * HD_ * S_]; // [B,HKV,HD,S]
__device__ __nv_bfloat16 g_vtl[(size_t)B_ * HKV_ * HD_ * S_];
// attention output (bf16 h/l, [B,S,HQ,HD])
__device__ __nv_bfloat16 g_ah[(size_t)B_ * S_ * HQ_ * HD_];
__device__ __nv_bfloat16 g_al[(size_t)B_ * S_ * HQ_ * HD_];

// ---------------- PTX helpers (family-portable only) -----------------------
__device__ __forceinline__ uint32_t smem_u32(const void* p) {
    uint32_t a;
    asm("{ .reg .u64 t; cvta.to.shared.u64 t, %1; cvt.u32.u64 %0, t; }" : "=r"(a) : "l"(p));
    return a;
}
__device__ __forceinline__ void cp16(uint32_t s, const void* g) {
    asm volatile("cp.async.cg.shared.global [%0], [%1], 16;" :: "r"(s), "l"(g));
}
__device__ __forceinline__ void cp_commit() {
    asm volatile("cp.async.commit_group;" ::: "memory");
}
__device__ __forceinline__ void ldm_x4(uint32_t a, uint32_t& r0, uint32_t& r1,
                                       uint32_t& r2, uint32_t& r3) {
    asm volatile("ldmatrix.sync.aligned.m8n8.x4.shared.b16 {%0,%1,%2,%3}, [%4];"
                 : "=r"(r0), "=r"(r1), "=r"(r2), "=r"(r3) : "r"(a));
}
__device__ __forceinline__ void mma_bf16(float& d0, float& d1, float& d2, float& d3,
                                         uint32_t a0, uint32_t a1, uint32_t a2, uint32_t a3,
                                         uint32_t b0, uint32_t b1) {
    asm volatile("mma.sync.aligned.m16n8k16.row.col.f32.bf16.bf16.f32 "
                 "{%0,%1,%2,%3}, {%4,%5,%6,%7}, {%8,%9}, {%0,%1,%2,%3};"
                 : "+f"(d0), "+f"(d1), "+f"(d2), "+f"(d3)
                 : "r"(a0), "r"(a1), "r"(a2), "r"(a3), "r"(b0), "r"(b1));
}
__device__ __forceinline__ uint32_t packbf(float lo, float hi) {
    __nv_bfloat162 t = __floats2bfloat162_rn(lo, hi);
    return *(uint32_t*)&t;
}

// ---------------------------------------------------------------------------
// split fp32 -> bf16 hi + bf16 lo
// ---------------------------------------------------------------------------
__global__ void split_kernel(const float* __restrict__ in,
                             __nv_bfloat16* __restrict__ hi,
                             __nv_bfloat16* __restrict__ lo, int n4)
{
    int i = blockIdx.x * blockDim.x + threadIdx.x;
    if (i >= n4) return;
    float4 v = ((const float4*)in)[i];
    __nv_bfloat16 h0 = __float2bfloat16_rn(v.x);
    __nv_bfloat16 h1 = __float2bfloat16_rn(v.y);
    __nv_bfloat16 h2 = __float2bfloat16_rn(v.z);
    __nv_bfloat16 h3 = __float2bfloat16_rn(v.w);
    __nv_bfloat16 l0 = __float2bfloat16_rn(v.x - __bfloat162float(h0));
    __nv_bfloat16 l1 = __float2bfloat16_rn(v.y - __bfloat162float(h1));
    __nv_bfloat16 l2 = __float2bfloat16_rn(v.z - __bfloat162float(h2));
    __nv_bfloat16 l3 = __float2bfloat16_rn(v.w - __bfloat162float(h3));
    __nv_bfloat162* hp = (__nv_bfloat162*)(hi + 4 * (size_t)i);
    __nv_bfloat162* lp = (__nv_bfloat162*)(lo + 4 * (size_t)i);
    hp[0] = __halves2bfloat162(h0, h1);
    hp[1] = __halves2bfloat162(h2, h3);
    lp[0] = __halves2bfloat162(l0, l1);
    lp[1] = __halves2bfloat162(l2, l3);
}

// ---------------------------------------------------------------------------
// bf16x3 GEMM (NT) via mma.sync. Epilogue modes:
//  0: write fp32 Cf[M,N]
//  3: fused QKV: n<4096 -> rope->Q head layout; n<5120 -> rope->K; else V^T
// ---------------------------------------------------------------------------
#define RSTR   40
#define TILE_B (128 * RSTR * 2)
#define STG_B  (4 * TILE_B)
#define GSMEM  (2 * STG_B)

__global__ __launch_bounds__(256, 2) void gemm_bf16x3(
    const __nv_bfloat16* __restrict__ Ah, const __nv_bfloat16* __restrict__ Al,
    const __nv_bfloat16* __restrict__ Bh, const __nv_bfloat16* __restrict__ Bl,
    float* __restrict__ Cf,
    __nv_bfloat16* __restrict__ Qh, __nv_bfloat16* __restrict__ Ql,
    __nv_bfloat16* __restrict__ Kh, __nv_bfloat16* __restrict__ Kl,
    __nv_bfloat16* __restrict__ Vh, __nv_bfloat16* __restrict__ Vl,
    int M, int N, int K, int mode,
    const float* __restrict__ fc, const float* __restrict__ fs)
{
    extern __shared__ char smem[];
    const uint32_t sb = smem_u32(smem);
    const int tid = threadIdx.x;
    const int lane = tid & 31;
    const int wid = tid >> 5;
    const int wm = wid >> 2;
    const int wn = wid & 3;
    const int bm = blockIdx.y * 128;
    const int bn = blockIdx.x * 128;

    float acc[4][4][4];
#pragma unroll
    for (int i = 0; i < 4; i++)
#pragma unroll
        for (int j = 0; j < 4; j++)
#pragma unroll
            for (int c = 0; c < 4; c++) acc[i][j][c] = 0.f;

    const int iters = K >> 5;
    const int row0 = tid >> 2;
    const int col0 = tid & 3;

#define PREFETCH(it_) do {                                                    \
    const int st_ = (it_) & 1;                                                \
    const int k0_ = (it_) << 5;                                               \
    const uint32_t sob_ = sb + st_ * STG_B;                                   \
    _Pragma("unroll")                                                         \
    for (int j_ = 0; j_ < 2; j_++) {                                          \
        int row_ = row0 + j_ * 64;                                            \
        uint32_t so_ = sob_ + row_ * (RSTR * 2) + col0 * 16;                  \
        size_t ga_ = (size_t)(bm + row_) * K + k0_ + col0 * 8;                \
        size_t gb_ = (size_t)(bn + row_) * K + k0_ + col0 * 8;                \
        cp16(so_ + 0 * TILE_B, Ah + ga_);                                     \
        cp16(so_ + 1 * TILE_B, Al + ga_);                                     \
        cp16(so_ + 2 * TILE_B, Bh + gb_);                                     \
        cp16(so_ + 3 * TILE_B, Bl + gb_);                                     \
    }                                                                         \
    cp_commit();                                                              \
} while (0)

    PREFETCH(0);
    if (iters > 1) PREFETCH(1);

    for (int it = 0; it < iters; it++) {
        if (it + 1 < iters) {
            asm volatile("cp.async.wait_group 1;" ::: "memory");
        } else {
            asm volatile("cp.async.wait_group 0;" ::: "memory");
        }
        __syncthreads();

        const uint32_t base = sb + (it & 1) * STG_B;
        const uint32_t a_h = base;
        const uint32_t a_l = base + TILE_B;
        const uint32_t b_h = base + 2 * TILE_B;
        const uint32_t b_l = base + 3 * TILE_B;

#pragma unroll
        for (int kk = 0; kk < 2; kk++) {
            const int kc = kk * 16 + (lane >> 4) * 8;
            uint32_t a[4][4], bhf[4][2], blf[4][2];
#pragma unroll
            for (int nq = 0; nq < 2; nq++) {
                int row = wn * 32 + nq * 16 + (lane & 15);
                uint32_t off = row * (RSTR * 2) + kc * 2;
                uint32_t r0, r1, r2, r3;
                ldm_x4(b_h + off, r0, r1, r2, r3);
                bhf[nq * 2][0] = r0; bhf[nq * 2][1] = r2;
                bhf[nq * 2 + 1][0] = r1; bhf[nq * 2 + 1][1] = r3;
                ldm_x4(b_l + off, r0, r1, r2, r3);
                blf[nq * 2][0] = r0; blf[nq * 2][1] = r2;
                blf[nq * 2 + 1][0] = r1; blf[nq * 2 + 1][1] = r3;
            }
#pragma unroll
            for (int mf = 0; mf < 4; mf++) {
                int row = wm * 64 + mf * 16 + (lane & 15);
                ldm_x4(a_h + row * (RSTR * 2) + kc * 2,
                       a[mf][0], a[mf][1], a[mf][2], a[mf][3]);
            }
#pragma unroll
            for (int mf = 0; mf < 4; mf++)
#pragma unroll
                for (int nf = 0; nf < 4; nf++) {
                    mma_bf16(acc[mf][nf][0], acc[mf][nf][1], acc[mf][nf][2], acc[mf][nf][3],
                             a[mf][0], a[mf][1], a[mf][2], a[mf][3],
                             bhf[nf][0], bhf[nf][1]);
                    mma_bf16(acc[mf][nf][0], acc[mf][nf][1], acc[mf][nf][2], acc[mf][nf][3],
                             a[mf][0], a[mf][1], a[mf][2], a[mf][3],
                             blf[nf][0], blf[nf][1]);
                }
#pragma unroll
            for (int mf = 0; mf < 4; mf++) {
                int row = wm * 64 + mf * 16 + (lane & 15);
                ldm_x4(a_l + row * (RSTR * 2) + kc * 2,
                       a[mf][0], a[mf][1], a[mf][2], a[mf][3]);
            }
#pragma unroll
            for (int mf = 0; mf < 4; mf++)
#pragma unroll
                for (int nf = 0; nf < 4; nf++)
                    mma_bf16(acc[mf][nf][0], acc[mf][nf][1], acc[mf][nf][2], acc[mf][nf][3],
                             a[mf][0], a[mf][1], a[mf][2], a[mf][3],
                             bhf[nf][0], bhf[nf][1]);
        }

        __syncthreads();
        if (it + 2 < iters) PREFETCH(it + 2);
    }

    const int qr = lane >> 2;
    const int qc = lane & 3;
#pragma unroll
    for (int mf = 0; mf < 4; mf++) {
#pragma unroll
        for (int half = 0; half < 2; half++) {
            int m = bm + wm * 64 + mf * 16 + qr + half * 8;
            if (mode == 0) {
                float* dst = Cf + (size_t)m * N + bn;
#pragma unroll
                for (int nf = 0; nf < 4; nf++) {
                    int n = wn * 32 + nf * 8 + 2 * qc;
                    float2 w = half ? make_float2(acc[mf][nf][2], acc[mf][nf][3])
                                    : make_float2(acc[mf][nf][0], acc[mf][nf][1]);
                    *(float2*)(dst + n) = w;
                }
            } else {
                int b = m >> 11;
                int s = m & (S_ - 1);
#pragma unroll
                for (int nf = 0; nf < 4; nf++) {
                    int n = bn + wn * 32 + nf * 8 + 2 * qc;
                    float2 w = half ? make_float2(acc[mf][nf][2], acc[mf][nf][3])
                                    : make_float2(acc[mf][nf][0], acc[mf][nf][1]);
                    if (n < HQ_ * HD_) {                    // Q: rope + head layout
                        int h = n >> 7;
                        int d = n & (HD_ - 1);
                        int i = d >> 1;
                        float c = fc[s * (HD_ / 2) + i];
                        float sn = fs[s * (HD_ / 2) + i];
                        float x0 = w.x * c - w.y * sn;
                        float x1 = w.x * sn + w.y * c;
                        __nv_bfloat16 h0 = __float2bfloat16_rn(x0);
                        __nv_bfloat16 h1 = __float2bfloat16_rn(x1);
                        size_t off = (((size_t)b * HQ_ + h) * S_ + s) * HD_ + d;
                        *(__nv_bfloat162*)(Qh + off) = __halves2bfloat162(h0, h1);
                        *(__nv_bfloat162*)(Ql + off) = __halves2bfloat162(
                            __float2bfloat16_rn(x0 - __bfloat162float(h0)),
                            __float2bfloat16_rn(x1 - __bfloat162float(h1)));
                    } else if (n < HQ_ * HD_ + HKV_ * HD_) { // K: rope + head layout
                        int nk = n - HQ_ * HD_;
                        int h = nk >> 7;
                        int d = nk & (HD_ - 1);
                        int i = d >> 1;
                        float c = fc[s * (HD_ / 2) + i];
                        float sn = fs[s * (HD_ / 2) + i];
                        float x0 = w.x * c - w.y * sn;
                        float x1 = w.x * sn + w.y * c;
                        __nv_bfloat16 h0 = __float2bfloat16_rn(x0);
                        __nv_bfloat16 h1 = __float2bfloat16_rn(x1);
                        size_t off = (((size_t)b * HKV_ + h) * S_ + s) * HD_ + d;
                        *(__nv_bfloat162*)(Kh + off) = __halves2bfloat162(h0, h1);
                        *(__nv_bfloat162*)(Kl + off) = __halves2bfloat162(
                            __float2bfloat16_rn(x0 - __bfloat162float(h0)),
                            __float2bfloat16_rn(x1 - __bfloat162float(h1)));
                    } else {                                 // V: transposed, no rope
                        int nv = n - (HQ_ * HD_ + HKV_ * HD_);
                        int h = nv >> 7;
                        int d = nv & (HD_ - 1);
                        __nv_bfloat16 h0 = __float2bfloat16_rn(w.x);
                        __nv_bfloat16 h1 = __float2bfloat16_rn(w.y);
                        size_t off = (((size_t)b * HKV_ + h) * HD_ + d) * S_ + s;
                        Vh[off] = h0;
                        Vl[off] = __float2bfloat16_rn(w.x - __bfloat162float(h0));
                        Vh[off + S_] = h1;
                        Vl[off + S_] = __float2bfloat16_rn(w.y - __bfloat162float(h1));
                    }
                }
            }
        }
    }
#undef PREFETCH
}

// ---------------------------------------------------------------------------
// Tensor-core flash attention v2 (unchanged from round 6).
// ---------------------------------------------------------------------------
#define QT 128
#define KT 64
#define QROW_B 272
#define VROW_B 144
#define QTILE_B (QT * QROW_B)
#define KTILE_B (KT * QROW_B)
#define VTILE_B (128 * VROW_B)
#define OFF_Q   0
#define OFF_K   (2 * QTILE_B)
#define OFF_V   (OFF_K + 4 * KTILE_B)
#define ATT_SMEM (OFF_V + 4 * VTILE_B)

__global__ __launch_bounds__(256) void attn_mma2(
    const __nv_bfloat16* __restrict__ Qh_g, const __nv_bfloat16* __restrict__ Ql_g,
    const __nv_bfloat16* __restrict__ Kh_g, const __nv_bfloat16* __restrict__ Kl_g,
    const __nv_bfloat16* __restrict__ Vh_g, const __nv_bfloat16* __restrict__ Vl_g,
    __nv_bfloat16* __restrict__ Oh, __nv_bfloat16* __restrict__ Ol)
{
    extern __shared__ char smem[];
    const uint32_t sb = smem_u32(smem);
    const int bh = blockIdx.y;
    const int b = bh >> 5;
    const int h = bh & (HQ_ - 1);
    const int kvh = h >> 2;
    const int q0 = blockIdx.x * QT;
    const int tid = threadIdx.x;
    const int lane = tid & 31;
    const int warp = tid >> 5;

    const __nv_bfloat16* qh = Qh_g + (((size_t)b * HQ_ + h) * S_ + q0) * HD_;
    const __nv_bfloat16* ql = Ql_g + (((size_t)b * HQ_ + h) * S_ + q0) * HD_;
    const __nv_bfloat16* kh = Kh_g + ((size_t)b * HKV_ + kvh) * S_ * HD_;
    const __nv_bfloat16* kl = Kl_g + ((size_t)b * HKV_ + kvh) * S_ * HD_;
    const __nv_bfloat16* vh = Vh_g + ((size_t)b * HKV_ + kvh) * HD_ * S_;
    const __nv_bfloat16* vl = Vl_g + ((size_t)b * HKV_ + kvh) * HD_ * S_;

#pragma unroll
    for (int i = 0; i < 8; i++) {
        int lin = tid + i * 256;
        int r = lin >> 4, c = lin & 15;
        cp16(sb + OFF_Q + r * QROW_B + c * 16, qh + (size_t)r * HD_ + c * 8);
        cp16(sb + OFF_Q + QTILE_B + r * QROW_B + c * 16, ql + (size_t)r * HD_ + c * 8);
    }
    cp_commit();

#define STAGE_KV(t_, buf_) do {                                               \
    int t0_ = (t_) * KT;                                                      \
    uint32_t kb_ = sb + OFF_K + (buf_) * (2 * KTILE_B);                       \
    uint32_t vb_ = sb + OFF_V + (buf_) * (2 * VTILE_B);                       \
    _Pragma("unroll")                                                         \
    for (int i_ = 0; i_ < 4; i_++) {                                          \
        int lin_ = tid + i_ * 256;                                            \
        int r_ = lin_ >> 4, c_ = lin_ & 15;                                   \
        cp16(kb_ + r_ * QROW_B + c_ * 16, kh + (size_t)(t0_ + r_) * HD_ + c_ * 8); \
        cp16(kb_ + KTILE_B + r_ * QROW_B + c_ * 16, kl + (size_t)(t0_ + r_) * HD_ + c_ * 8); \
        int d_ = lin_ >> 3, c2_ = lin_ & 7;                                   \
        cp16(vb_ + d_ * VROW_B + c2_ * 16, vh + (size_t)d_ * S_ + t0_ + c2_ * 8); \
        cp16(vb_ + VTILE_B + d_ * VROW_B + c2_ * 16, vl + (size_t)d_ * S_ + t0_ + c2_ * 8); \
    }                                                                         \
    cp_commit();                                                              \
} while (0)

    STAGE_KV(0, 0);
    STAGE_KV(1, 1);

    float o[16][4];
#pragma unroll
    for (int t = 0; t < 16; t++)
#pragma unroll
        for (int c = 0; c < 4; c++) o[t][c] = 0.f;
    float m0 = -1e30f, m1 = -1e30f, l0v = 0.f, l1v = 0.f;

    const float scale = 0.08838834764831845f;
    const uint32_t uqh = sb + OFF_Q;
    const uint32_t uql = uqh + QTILE_B;
    const uint32_t qrow_off = (warp * 16 + (lane & 15)) * QROW_B;
    const uint32_t kcol_off = (lane >> 4) * 16;

    const int T = S_ / KT;
    for (int t = 0; t < T; t++) {
        if (t + 1 < T) {
            asm volatile("cp.async.wait_group 1;" ::: "memory");
        } else {
            asm volatile("cp.async.wait_group 0;" ::: "memory");
        }
        __syncthreads();

        const int buf = t & 1;
        const uint32_t ukh = sb + OFF_K + buf * (2 * KTILE_B);
        const uint32_t ukl = ukh + KTILE_B;
        const uint32_t uvh = sb + OFF_V + buf * (2 * VTILE_B);
        const uint32_t uvl = uvh + VTILE_B;

        float sc[8][4];
#pragma unroll
        for (int j = 0; j < 8; j++)
#pragma unroll
            for (int c = 0; c < 4; c++) sc[j][c] = 0.f;

#pragma unroll
        for (int ks = 0; ks < 8; ks++) {
            const uint32_t kb_off = ks * 32 + kcol_off;
            uint32_t qa[4], qb[4];
            ldm_x4(uqh + qrow_off + kb_off, qa[0], qa[1], qa[2], qa[3]);
            ldm_x4(uql + qrow_off + kb_off, qb[0], qb[1], qb[2], qb[3]);
#pragma unroll
            for (int np = 0; np < 4; np++) {
                uint32_t roff = (np * 16 + (lane & 15)) * QROW_B + kb_off;
                uint32_t r0, r1, r2, r3, s0, s1, s2, s3;
                ldm_x4(ukh + roff, r0, r1, r2, r3);
                ldm_x4(ukl + roff, s0, s1, s2, s3);
                mma_bf16(sc[2*np][0], sc[2*np][1], sc[2*np][2], sc[2*np][3],
                         qa[0], qa[1], qa[2], qa[3], r0, r2);
                mma_bf16(sc[2*np+1][0], sc[2*np+1][1], sc[2*np+1][2], sc[2*np+1][3],
                         qa[0], qa[1], qa[2], qa[3], r1, r3);
                mma_bf16(sc[2*np][0], sc[2*np][1], sc[2*np][2], sc[2*np][3],
                         qb[0], qb[1], qb[2], qb[3], r0, r2);
                mma_bf16(sc[2*np+1][0], sc[2*np+1][1], sc[2*np+1][2], sc[2*np+1][3],
                         qb[0], qb[1], qb[2], qb[3], r1, r3);
                mma_bf16(sc[2*np][0], sc[2*np][1], sc[2*np][2], sc[2*np][3],
                         qa[0], qa[1], qa[2], qa[3], s0, s2);
                mma_bf16(sc[2*np+1][0], sc[2*np+1][1], sc[2*np+1][2], sc[2*np+1][3],
                         qa[0], qa[1], qa[2], qa[3], s1, s3);
            }
        }

        float mx0 = -1e30f, mx1 = -1e30f;
#pragma unroll
        for (int j = 0; j < 8; j++) {
#pragma unroll
            for (int c = 0; c < 4; c++) sc[j][c] *= scale;
            mx0 = fmaxf(mx0, fmaxf(sc[j][0], sc[j][1]));
            mx1 = fmaxf(mx1, fmaxf(sc[j][2], sc[j][3]));
        }
        mx0 = fmaxf(mx0, __shfl_xor_sync(0xffffffffu, mx0, 1));
        mx0 = fmaxf(mx0, __shfl_xor_sync(0xffffffffu, mx0, 2));
        mx1 = fmaxf(mx1, __shfl_xor_sync(0xffffffffu, mx1, 1));
        mx1 = fmaxf(mx1, __shfl_xor_sync(0xffffffffu, mx1, 2));
        float mn0 = fmaxf(m0, mx0), mn1 = fmaxf(m1, mx1);
        float al0 = __expf(m0 - mn0), al1 = __expf(m1 - mn1);
        m0 = mn0; m1 = mn1;
        float rs0 = 0.f, rs1 = 0.f;
#pragma unroll
        for (int j = 0; j < 8; j++) {
            sc[j][0] = __expf(sc[j][0] - m0);
            sc[j][1] = __expf(sc[j][1] - m0);
            sc[j][2] = __expf(sc[j][2] - m1);
            sc[j][3] = __expf(sc[j][3] - m1);
            rs0 += sc[j][0] + sc[j][1];
            rs1 += sc[j][2] + sc[j][3];
        }
        rs0 += __shfl_xor_sync(0xffffffffu, rs0, 1);
        rs0 += __shfl_xor_sync(0xffffffffu, rs0, 2);
        rs1 += __shfl_xor_sync(0xffffffffu, rs1, 1);
        rs1 += __shfl_xor_sync(0xffffffffu, rs1, 2);
        l0v = l0v * al0 + rs0;
        l1v = l1v * al1 + rs1;
#pragma unroll
        for (int tt = 0; tt < 16; tt++) {
            o[tt][0] *= al0; o[tt][1] *= al0;
            o[tt][2] *= al1; o[tt][3] *= al1;
        }

#pragma unroll
        for (int kb = 0; kb < 4; kb++) {
            float e00 = sc[2*kb][0],   e01 = sc[2*kb][1];
            float e10 = sc[2*kb][2],   e11 = sc[2*kb][3];
            float f00 = sc[2*kb+1][0], f01 = sc[2*kb+1][1];
            float f10 = sc[2*kb+1][2], f11 = sc[2*kb+1][3];
            uint32_t ph0 = packbf(e00, e01), ph1 = packbf(e10, e11);
            uint32_t ph2 = packbf(f00, f01), ph3 = packbf(f10, f11);
            uint32_t pl0 = packbf(e00 - __bfloat162float(__float2bfloat16_rn(e00)),
                                  e01 - __bfloat162float(__float2bfloat16_rn(e01)));
            uint32_t pl1 = packbf(e10 - __bfloat162float(__float2bfloat16_rn(e10)),
                                  e11 - __bfloat162float(__float2bfloat16_rn(e11)));
            uint32_t pl2 = packbf(f00 - __bfloat162float(__float2bfloat16_rn(f00)),
                                  f01 - __bfloat162float(__float2bfloat16_rn(f01)));
            uint32_t pl3 = packbf(f10 - __bfloat162float(__float2bfloat16_rn(f10)),
                                  f11 - __bfloat162float(__float2bfloat16_rn(f11)));
            const uint32_t kb_off = kb * 32 + kcol_off;
#pragma unroll
            for (int np = 0; np < 8; np++) {
                uint32_t roff = (np * 16 + (lane & 15)) * VROW_B + kb_off;
                uint32_t r0, r1, r2, r3, s0, s1, s2, s3;
                ldm_x4(uvh + roff, r0, r1, r2, r3);
                ldm_x4(uvl + roff, s0, s1, s2, s3);
                mma_bf16(o[2*np][0], o[2*np][1], o[2*np][2], o[2*np][3],
                         ph0, ph1, ph2, ph3, r0, r2);
                mma_bf16(o[2*np+1][0], o[2*np+1][1], o[2*np+1][2], o[2*np+1][3],
                         ph0, ph1, ph2, ph3, r1, r3);
                mma_bf16(o[2*np][0], o[2*np][1], o[2*np][2], o[2*np][3],
                         pl0, pl1, pl2, pl3, r0, r2);
                mma_bf16(o[2*np+1][0], o[2*np+1][1], o[2*np+1][2], o[2*np+1][3],
                         pl0, pl1, pl2, pl3, r1, r3);
                mma_bf16(o[2*np][0], o[2*np][1], o[2*np][2], o[2*np][3],
                         ph0, ph1, ph2, ph3, s0, s2);
                mma_bf16(o[2*np+1][0], o[2*np+1][1], o[2*np+1][2], o[2*np+1][3],
                         ph0, ph1, ph2, ph3, s1, s3);
            }
        }

        __syncthreads();
        if (t + 2 < T) STAGE_KV(t + 2, buf);
    }
#undef STAGE_KV

    float inv0 = 1.0f / l0v, inv1 = 1.0f / l1v;
    int s0 = q0 + warp * 16 + (lane >> 2);
    int s1 = s0 + 8;
    size_t base0 = (((size_t)b * S_ + s0) * HQ_ + h) * HD_ + 2 * (lane & 3);
    size_t base1 = (((size_t)b * S_ + s1) * HQ_ + h) * HD_ + 2 * (lane & 3);
#pragma unroll
    for (int t = 0; t < 16; t++) {
        float x0 = o[t][0] * inv0, x1 = o[t][1] * inv0;
        float y0 = o[t][2] * inv1, y1 = o[t][3] * inv1;
        __nv_bfloat16 xh0 = __float2bfloat16_rn(x0), xh1 = __float2bfloat16_rn(x1);
        __nv_bfloat16 yh0 = __float2bfloat16_rn(y0), yh1 = __float2bfloat16_rn(y1);
        *(__nv_bfloat162*)(Oh + base0 + 8 * t) = __halves2bfloat162(xh0, xh1);
        *(__nv_bfloat162*)(Ol + base0 + 8 * t) = __halves2bfloat162(
            __float2bfloat16_rn(x0 - __bfloat162float(xh0)),
            __float2bfloat16_rn(x1 - __bfloat162float(xh1)));
        *(__nv_bfloat162*)(Oh + base1 + 8 * t) = __halves2bfloat162(yh0, yh1);
        *(__nv_bfloat162*)(Ol + base1 + 8 * t) = __halves2bfloat162(
            __float2bfloat16_rn(y0 - __bfloat162float(yh0)),
            __float2bfloat16_rn(y1 - __bfloat162float(yh1)));
    }
}

// ---------------------------------------------------------------------------
extern "C" void kernel_launch(void* const* d_in, const int* in_sizes, int n_in,
                              void* d_out, int out_size)
{
    const float* x  = (const float*)d_in[0];
    const float* wq = (const float*)d_in[1];
    const float* wk = (const float*)d_in[2];
    const float* wv = (const float*)d_in[3];
    const float* wo = (const float*)d_in[4];
    const float* fc = (const float*)d_in[5];
    const float* fs = (const float*)d_in[6];
    float* out = (float*)d_out;

    __nv_bfloat16 *xh, *xl, *wqkvh, *wqkvl, *woh, *wol;
    __nv_bfloat16 *qh, *ql, *kh, *kl, *vth, *vtl, *ah, *al;
    cudaGetSymbolAddress((void**)&xh, g_xh);       cudaGetSymbolAddress((void**)&xl, g_xl);
    cudaGetSymbolAddress((void**)&wqkvh, g_wqkvh); cudaGetSymbolAddress((void**)&wqkvl, g_wqkvl);
    cudaGetSymbolAddress((void**)&woh, g_woh);     cudaGetSymbolAddress((void**)&wol, g_wol);
    cudaGetSymbolAddress((void**)&qh, g_qh);       cudaGetSymbolAddress((void**)&ql, g_ql);
    cudaGetSymbolAddress((void**)&kh, g_kh);       cudaGetSymbolAddress((void**)&kl, g_kl);
    cudaGetSymbolAddress((void**)&vth, g_vth);     cudaGetSymbolAddress((void**)&vtl, g_vtl);
    cudaGetSymbolAddress((void**)&ah, g_ah);       cudaGetSymbolAddress((void**)&al, g_al);

    const int M = B_ * S_;  // 4096

    // splits (wq/wk/wv into stacked buffer)
    int n4x = (B_ * S_ * D_) / 4;
    split_kernel<<<(n4x + 255) / 256, 256>>>(x, xh, xl, n4x);
    int n4q = (HQ_ * HD_ * D_) / 4;
    split_kernel<<<(n4q + 255) / 256, 256>>>(wq, wqkvh, wqkvl, n4q);
    int n4k = (HKV_ * HD_ * D_) / 4;
    size_t offk = (size_t)HQ_ * HD_ * D_;
    size_t offv = offk + (size_t)HKV_ * HD_ * D_;
    split_kernel<<<(n4k + 255) / 256, 256>>>(wk, wqkvh + offk, wqkvl + offk, n4k);
    split_kernel<<<(n4k + 255) / 256, 256>>>(wv, wqkvh + offv, wqkvl + offv, n4k);
    int n4o = (D_ * HQ_ * HD_) / 4;
    split_kernel<<<(n4o + 255) / 256, 256>>>(wo, woh, wol, n4o);

    cudaFuncSetAttribute(gemm_bf16x3, cudaFuncAttributeMaxDynamicSharedMemorySize, GSMEM);

    // fused QKV projection: rope + split + layout in epilogue
    gemm_bf16x3<<<dim3(NQKV / 128, M / 128), 256, GSMEM>>>(
        xh, xl, wqkvh, wqkvl, nullptr,
        qh, ql, kh, kl, vth, vtl, M, NQKV, D_, 3, fc, fs);

    // tensor-core attention (writes ah/al bf16 h/l directly)
    cudaFuncSetAttribute(attn_mma2, cudaFuncAttributeMaxDynamicSharedMemorySize, ATT_SMEM);
    attn_mma2<<<dim3(S_ / QT, B_ * HQ_), 256, ATT_SMEM>>>(
        qh, ql, kh, kl, vth, vtl, ah, al);

    // output projection -> d_out
    gemm_bf16x3<<<dim3(D_ / 128, M / 128), 256, GSMEM>>>(
        ah, al, woh, wol, out,
        nullptr, nullptr, nullptr, nullptr, nullptr, nullptr, M, D_, D_, 0, fc, fs);
}

// round 8
// speedup vs baseline: 3.9669x; 1.4464x over previous
#include <cuda_runtime.h>
#include <cuda_fp16.h>
#include <cstdint>
#include <math.h>

#define B_   2
#define S_   2048
#define D_   4096
#define HQ_  32
#define HKV_ 8
#define HD_  128

// ---------------- scratch (static device globals; no allocations) ----------
__device__ __half g_xh[(size_t)B_ * S_ * D_];                  // x hi only (A operand)
#define NQKV (HQ_ * HD_ + 2 * HKV_ * HD_)   // 6144
__device__ __half g_wqkvh[(size_t)NQKV * D_];
__device__ __half g_wqkvl[(size_t)NQKV * D_];
__device__ __half g_woh[(size_t)D_ * HQ_ * HD_];
__device__ __half g_wol[(size_t)D_ * HQ_ * HD_];
// rope'd Q (hi only), K (h/l), transposed V (h/l)
__device__ __half g_qh[(size_t)B_ * HQ_ * S_ * HD_];   // [B,HQ,S,HD]
__device__ __half g_kh[(size_t)B_ * HKV_ * S_ * HD_];  // [B,HKV,S,HD]
__device__ __half g_kl[(size_t)B_ * HKV_ * S_ * HD_];
__device__ __half g_vth[(size_t)B_ * HKV_ * HD_ * S_]; // [B,HKV,HD,S]
__device__ __half g_vtl[(size_t)B_ * HKV_ * HD_ * S_];
// attention output (hi only, [B,S,HQ,HD]) — A operand of out-proj
__device__ __half g_ah[(size_t)B_ * S_ * HQ_ * HD_];

// ---------------- PTX helpers (family-portable only) -----------------------
__device__ __forceinline__ uint32_t smem_u32(const void* p) {
    uint32_t a;
    asm("{ .reg .u64 t; cvta.to.shared.u64 t, %1; cvt.u32.u64 %0, t; }" : "=r"(a) : "l"(p));
    return a;
}
__device__ __forceinline__ void cp16(uint32_t s, const void* g) {
    asm volatile("cp.async.cg.shared.global [%0], [%1], 16;" :: "r"(s), "l"(g));
}
__device__ __forceinline__ void cp_commit() {
    asm volatile("cp.async.commit_group;" ::: "memory");
}
__device__ __forceinline__ void ldm_x4(uint32_t a, uint32_t& r0, uint32_t& r1,
                                       uint32_t& r2, uint32_t& r3) {
    asm volatile("ldmatrix.sync.aligned.m8n8.x4.shared.b16 {%0,%1,%2,%3}, [%4];"
                 : "=r"(r0), "=r"(r1), "=r"(r2), "=r"(r3) : "r"(a));
}
__device__ __forceinline__ void mma_f16(float& d0, float& d1, float& d2, float& d3,
                                        uint32_t a0, uint32_t a1, uint32_t a2, uint32_t a3,
                                        uint32_t b0, uint32_t b1) {
    asm volatile("mma.sync.aligned.m16n8k16.row.col.f32.f16.f16.f32 "
                 "{%0,%1,%2,%3}, {%4,%5,%6,%7}, {%8,%9}, {%0,%1,%2,%3};"
                 : "+f"(d0), "+f"(d1), "+f"(d2), "+f"(d3)
                 : "r"(a0), "r"(a1), "r"(a2), "r"(a3), "r"(b0), "r"(b1));
}
__device__ __forceinline__ uint32_t packh(float lo, float hi) {
    __half2 t = __floats2half2_rn(lo, hi);
    return *(uint32_t*)&t;
}

// ---------------------------------------------------------------------------
// converts: fp32 -> fp16 hi only / fp32 -> fp16 hi + lo
// ---------------------------------------------------------------------------
__global__ void conv_kernel(const float* __restrict__ in,
                            __half* __restrict__ hi, int n4)
{
    int i = blockIdx.x * blockDim.x + threadIdx.x;
    if (i >= n4) return;
    float4 v = ((const float4*)in)[i];
    __half2* hp = (__half2*)(hi + 4 * (size_t)i);
    hp[0] = __floats2half2_rn(v.x, v.y);
    hp[1] = __floats2half2_rn(v.z, v.w);
}

__global__ void split_kernel(const float* __restrict__ in,
                             __half* __restrict__ hi,
                             __half* __restrict__ lo, int n4)
{
    int i = blockIdx.x * blockDim.x + threadIdx.x;
    if (i >= n4) return;
    float4 v = ((const float4*)in)[i];
    __half h0 = __float2half_rn(v.x);
    __half h1 = __float2half_rn(v.y);
    __half h2 = __float2half_rn(v.z);
    __half h3 = __float2half_rn(v.w);
    __half2* hp = (__half2*)(hi + 4 * (size_t)i);
    __half2* lp = (__half2*)(lo + 4 * (size_t)i);
    hp[0] = __halves2half2(h0, h1);
    hp[1] = __halves2half2(h2, h3);
    lp[0] = __floats2half2_rn(v.x - __half2float(h0), v.y - __half2float(h1));
    lp[1] = __floats2half2_rn(v.z - __half2float(h2), v.w - __half2float(h3));
}

// ---------------------------------------------------------------------------
// fp16x2 GEMM (NT): C = A*B^T with A fp16-hi only, B split hi/lo.
// 2 passes: Ah*Bh + Ah*Bl, fp32 accum. CTA 128x128, K-chunk 32, 8 warps.
// modes: 0 = fp32 C; 3 = fused QKV epilogue (rope Q/K, V transposed).
// ---------------------------------------------------------------------------
#define RSTR   40
#define TILE_B (128 * RSTR * 2)     // 10240 B
#define STG_B  (3 * TILE_B)         // Ah, Bh, Bl
#define GSMEM  (2 * STG_B)          // 61440 B

__global__ __launch_bounds__(256, 2) void gemm_fp16x2(
    const __half* __restrict__ Ah,
    const __half* __restrict__ Bh, const __half* __restrict__ Bl,
    float* __restrict__ Cf,
    __half* __restrict__ Qh,
    __half* __restrict__ Kh, __half* __restrict__ Kl,
    __half* __restrict__ Vh, __half* __restrict__ Vl,
    int M, int N, int K, int mode,
    const float* __restrict__ fc, const float* __restrict__ fs)
{
    extern __shared__ char smem[];
    const uint32_t sb = smem_u32(smem);
    const int tid = threadIdx.x;
    const int lane = tid & 31;
    const int wid = tid >> 5;
    const int wm = wid >> 2;
    const int wn = wid & 3;
    const int bm = blockIdx.y * 128;
    const int bn = blockIdx.x * 128;

    float acc[4][4][4];
#pragma unroll
    for (int i = 0; i < 4; i++)
#pragma unroll
        for (int j = 0; j < 4; j++)
#pragma unroll
            for (int c = 0; c < 4; c++) acc[i][j][c] = 0.f;

    const int iters = K >> 5;
    const int row0 = tid >> 2;
    const int col0 = tid & 3;

#define PREFETCH(it_) do {                                                    \
    const int st_ = (it_) & 1;                                                \
    const int k0_ = (it_) << 5;                                               \
    const uint32_t sob_ = sb + st_ * STG_B;                                   \
    _Pragma("unroll")                                                         \
    for (int j_ = 0; j_ < 2; j_++) {                                          \
        int row_ = row0 + j_ * 64;                                            \
        uint32_t so_ = sob_ + row_ * (RSTR * 2) + col0 * 16;                  \
        size_t ga_ = (size_t)(bm + row_) * K + k0_ + col0 * 8;                \
        size_t gb_ = (size_t)(bn + row_) * K + k0_ + col0 * 8;                \
        cp16(so_ + 0 * TILE_B, Ah + ga_);                                     \
        cp16(so_ + 1 * TILE_B, Bh + gb_);                                     \
        cp16(so_ + 2 * TILE_B, Bl + gb_);                                     \
    }                                                                         \
    cp_commit();                                                              \
} while (0)

    PREFETCH(0);
    if (iters > 1) PREFETCH(1);

    for (int it = 0; it < iters; it++) {
        if (it + 1 < iters) {
            asm volatile("cp.async.wait_group 1;" ::: "memory");
        } else {
            asm volatile("cp.async.wait_group 0;" ::: "memory");
        }
        __syncthreads();

        const uint32_t base = sb + (it & 1) * STG_B;
        const uint32_t a_h = base;
        const uint32_t b_h = base + TILE_B;
        const uint32_t b_l = base + 2 * TILE_B;

#pragma unroll
        for (int kk = 0; kk < 2; kk++) {
            const int kc = kk * 16 + (lane >> 4) * 8;
            uint32_t a[4][4], bhf[4][2], blf[4][2];
#pragma unroll
            for (int nq = 0; nq < 2; nq++) {
                int row = wn * 32 + nq * 16 + (lane & 15);
                uint32_t off = row * (RSTR * 2) + kc * 2;
                uint32_t r0, r1, r2, r3;
                ldm_x4(b_h + off, r0, r1, r2, r3);
                bhf[nq * 2][0] = r0; bhf[nq * 2][1] = r2;
                bhf[nq * 2 + 1][0] = r1; bhf[nq * 2 + 1][1] = r3;
                ldm_x4(b_l + off, r0, r1, r2, r3);
                blf[nq * 2][0] = r0; blf[nq * 2][1] = r2;
                blf[nq * 2 + 1][0] = r1; blf[nq * 2 + 1][1] = r3;
            }
#pragma unroll
            for (int mf = 0; mf < 4; mf++) {
                int row = wm * 64 + mf * 16 + (lane & 15);
                ldm_x4(a_h + row * (RSTR * 2) + kc * 2,
                       a[mf][0], a[mf][1], a[mf][2], a[mf][3]);
            }
#pragma unroll
            for (int mf = 0; mf < 4; mf++)
#pragma unroll
                for (int nf = 0; nf < 4; nf++) {
                    mma_f16(acc[mf][nf][0], acc[mf][nf][1], acc[mf][nf][2], acc[mf][nf][3],
                            a[mf][0], a[mf][1], a[mf][2], a[mf][3],
                            bhf[nf][0], bhf[nf][1]);
                    mma_f16(acc[mf][nf][0], acc[mf][nf][1], acc[mf][nf][2], acc[mf][nf][3],
                            a[mf][0], a[mf][1], a[mf][2], a[mf][3],
                            blf[nf][0], blf[nf][1]);
                }
        }

        __syncthreads();
        if (it + 2 < iters) PREFETCH(it + 2);
    }

    const int qr = lane >> 2;
    const int qc = lane & 3;
#pragma unroll
    for (int mf = 0; mf < 4; mf++) {
#pragma unroll
        for (int half_ = 0; half_ < 2; half_++) {
            int m = bm + wm * 64 + mf * 16 + qr + half_ * 8;
            if (mode == 0) {
                float* dst = Cf + (size_t)m * N + bn;
#pragma unroll
                for (int nf = 0; nf < 4; nf++) {
                    int n = wn * 32 + nf * 8 + 2 * qc;
                    float2 w = half_ ? make_float2(acc[mf][nf][2], acc[mf][nf][3])
                                     : make_float2(acc[mf][nf][0], acc[mf][nf][1]);
                    *(float2*)(dst + n) = w;
                }
            } else {
                int b = m >> 11;
                int s = m & (S_ - 1);
#pragma unroll
                for (int nf = 0; nf < 4; nf++) {
                    int n = bn + wn * 32 + nf * 8 + 2 * qc;
                    float2 w = half_ ? make_float2(acc[mf][nf][2], acc[mf][nf][3])
                                     : make_float2(acc[mf][nf][0], acc[mf][nf][1]);
                    if (n < HQ_ * HD_) {                    // Q: rope, hi only
                        int h = n >> 7;
                        int d = n & (HD_ - 1);
                        int i = d >> 1;
                        float c = fc[s * (HD_ / 2) + i];
                        float sn = fs[s * (HD_ / 2) + i];
                        float x0 = w.x * c - w.y * sn;
                        float x1 = w.x * sn + w.y * c;
                        size_t off = (((size_t)b * HQ_ + h) * S_ + s) * HD_ + d;
                        *(__half2*)(Qh + off) = __floats2half2_rn(x0, x1);
                    } else if (n < HQ_ * HD_ + HKV_ * HD_) { // K: rope, h/l split
                        int nk = n - HQ_ * HD_;
                        int h = nk >> 7;
                        int d = nk & (HD_ - 1);
                        int i = d >> 1;
                        float c = fc[s * (HD_ / 2) + i];
                        float sn = fs[s * (HD_ / 2) + i];
                        float x0 = w.x * c - w.y * sn;
                        float x1 = w.x * sn + w.y * c;
                        __half h0 = __float2half_rn(x0);
                        __half h1 = __float2half_rn(x1);
                        size_t off = (((size_t)b * HKV_ + h) * S_ + s) * HD_ + d;
                        *(__half2*)(Kh + off) = __halves2half2(h0, h1);
                        *(__half2*)(Kl + off) = __floats2half2_rn(
                            x0 - __half2float(h0), x1 - __half2float(h1));
                    } else {                                 // V: transposed, h/l split
                        int nv = n - (HQ_ * HD_ + HKV_ * HD_);
                        int h = nv >> 7;
                        int d = nv & (HD_ - 1);
                        __half h0 = __float2half_rn(w.x);
                        __half h1 = __float2half_rn(w.y);
                        size_t off = (((size_t)b * HKV_ + h) * HD_ + d) * S_ + s;
                        Vh[off] = h0;
                        Vl[off] = __float2half_rn(w.x - __half2float(h0));
                        Vh[off + S_] = h1;
                        Vl[off + S_] = __float2half_rn(w.y - __half2float(h1));
                    }
                }
            }
        }
    }
#undef PREFETCH
}

// ---------------------------------------------------------------------------
// Tensor-core flash attention (fp16x2): Q hi-only (A), K h/l (B), V h/l (B).
// Grid (S/128, B*HQ), block 256 (8 warps), 2 CTAs/SM.
// KT=32 key tile, double-buffered. smem = 110592 B.
// ---------------------------------------------------------------------------
#define QT 128
#define KT 32
#define QROW_B 272                 // 128 halves + 8 pad
#define VROW_B 80                  // 32 halves + 8 pad
#define QTILE_B (QT * QROW_B)      // 34816
#define KTILE_B (KT * QROW_B)      // 8704
#define VTILE_B (128 * VROW_B)     // 10240
#define OFF_K   QTILE_B                       // 34816
#define OFF_V   (OFF_K + 4 * KTILE_B)         // 69632
#define ATT_SMEM (OFF_V + 4 * VTILE_B)        // 110592

__global__ __launch_bounds__(256, 2) void attn_mma3(
    const __half* __restrict__ Qh_g,
    const __half* __restrict__ Kh_g, const __half* __restrict__ Kl_g,
    const __half* __restrict__ Vh_g, const __half* __restrict__ Vl_g,
    __half* __restrict__ Oh)
{
    extern __shared__ char smem[];
    const uint32_t sb = smem_u32(smem);
    const int bh = blockIdx.y;
    const int b = bh >> 5;
    const int h = bh & (HQ_ - 1);
    const int kvh = h >> 2;
    const int q0 = blockIdx.x * QT;
    const int tid = threadIdx.x;
    const int lane = tid & 31;
    const int warp = tid >> 5;

    const __half* qh = Qh_g + (((size_t)b * HQ_ + h) * S_ + q0) * HD_;
    const __half* kh = Kh_g + ((size_t)b * HKV_ + kvh) * S_ * HD_;
    const __half* kl = Kl_g + ((size_t)b * HKV_ + kvh) * S_ * HD_;
    const __half* vh = Vh_g + ((size_t)b * HKV_ + kvh) * HD_ * S_;
    const __half* vl = Vl_g + ((size_t)b * HKV_ + kvh) * HD_ * S_;

    // stage Q (hi only): 128 rows x 16 chunks
#pragma unroll
    for (int i = 0; i < 8; i++) {
        int lin = tid + i * 256;
        int r = lin >> 4, c = lin & 15;
        cp16(sb + r * QROW_B + c * 16, qh + (size_t)r * HD_ + c * 8);
    }
    cp_commit();

#define STAGE_KV(t_, buf_) do {                                               \
    int t0_ = (t_) * KT;                                                      \
    uint32_t kb_ = sb + OFF_K + (buf_) * (2 * KTILE_B);                       \
    uint32_t vb_ = sb + OFF_V + (buf_) * (2 * VTILE_B);                       \
    _Pragma("unroll")                                                         \
    for (int i_ = 0; i_ < 2; i_++) {                                          \
        int lin_ = tid + i_ * 256;                                            \
        int r_ = lin_ >> 4, c_ = lin_ & 15;                                   \
        cp16(kb_ + r_ * QROW_B + c_ * 16, kh + (size_t)(t0_ + r_) * HD_ + c_ * 8); \
        cp16(kb_ + KTILE_B + r_ * QROW_B + c_ * 16, kl + (size_t)(t0_ + r_) * HD_ + c_ * 8); \
        int d_ = lin_ >> 2, c2_ = lin_ & 3;                                   \
        cp16(vb_ + d_ * VROW_B + c2_ * 16, vh + (size_t)d_ * S_ + t0_ + c2_ * 8); \
        cp16(vb_ + VTILE_B + d_ * VROW_B + c2_ * 16, vl + (size_t)d_ * S_ + t0_ + c2_ * 8); \
    }                                                                         \
    cp_commit();                                                              \
} while (0)

    STAGE_KV(0, 0);
    STAGE_KV(1, 1);

    float o[16][4];
#pragma unroll
    for (int t = 0; t < 16; t++)
#pragma unroll
        for (int c = 0; c < 4; c++) o[t][c] = 0.f;
    float m0 = -1e30f, m1 = -1e30f, l0v = 0.f, l1v = 0.f;

    const float scale = 0.08838834764831845f;   // 1/sqrt(128)
    const uint32_t qrow_off = (warp * 16 + (lane & 15)) * QROW_B;
    const uint32_t kcol_off = (lane >> 4) * 16;

    const int T = S_ / KT;   // 64
    for (int t = 0; t < T; t++) {
        if (t + 1 < T) {
            asm volatile("cp.async.wait_group 1;" ::: "memory");
        } else {
            asm volatile("cp.async.wait_group 0;" ::: "memory");
        }
        __syncthreads();

        const int buf = t & 1;
        const uint32_t ukh = sb + OFF_K + buf * (2 * KTILE_B);
        const uint32_t ukl = ukh + KTILE_B;
        const uint32_t uvh = sb + OFF_V + buf * (2 * VTILE_B);
        const uint32_t uvl = uvh + VTILE_B;

        // ---- S = Q K^T (fp16 x2: Qh*Kh + Qh*Kl) ----
        float sc[4][4];
#pragma unroll
        for (int j = 0; j < 4; j++)
#pragma unroll
            for (int c = 0; c < 4; c++) sc[j][c] = 0.f;

#pragma unroll
        for (int ks = 0; ks < 8; ks++) {
            const uint32_t kb_off = ks * 32 + kcol_off;
            uint32_t qa[4];
            ldm_x4(sb + qrow_off + kb_off, qa[0], qa[1], qa[2], qa[3]);
#pragma unroll
            for (int np = 0; np < 2; np++) {
                uint32_t roff = (np * 16 + (lane & 15)) * QROW_B + kb_off;
                uint32_t r0, r1, r2, r3, s0, s1, s2, s3;
                ldm_x4(ukh + roff, r0, r1, r2, r3);
                ldm_x4(ukl + roff, s0, s1, s2, s3);
                mma_f16(sc[2*np][0], sc[2*np][1], sc[2*np][2], sc[2*np][3],
                        qa[0], qa[1], qa[2], qa[3], r0, r2);
                mma_f16(sc[2*np+1][0], sc[2*np+1][1], sc[2*np+1][2], sc[2*np+1][3],
                        qa[0], qa[1], qa[2], qa[3], r1, r3);
                mma_f16(sc[2*np][0], sc[2*np][1], sc[2*np][2], sc[2*np][3],
                        qa[0], qa[1], qa[2], qa[3], s0, s2);
                mma_f16(sc[2*np+1][0], sc[2*np+1][1], sc[2*np+1][2], sc[2*np+1][3],
                        qa[0], qa[1], qa[2], qa[3], s1, s3);
            }
        }

        // ---- online softmax ----
        float mx0 = -1e30f, mx1 = -1e30f;
#pragma unroll
        for (int j = 0; j < 4; j++) {
#pragma unroll
            for (int c = 0; c < 4; c++) sc[j][c] *= scale;
            mx0 = fmaxf(mx0, fmaxf(sc[j][0], sc[j][1]));
            mx1 = fmaxf(mx1, fmaxf(sc[j][2], sc[j][3]));
        }
        mx0 = fmaxf(mx0, __shfl_xor_sync(0xffffffffu, mx0, 1));
        mx0 = fmaxf(mx0, __shfl_xor_sync(0xffffffffu, mx0, 2));
        mx1 = fmaxf(mx1, __shfl_xor_sync(0xffffffffu, mx1, 1));
        mx1 = fmaxf(mx1, __shfl_xor_sync(0xffffffffu, mx1, 2));
        float mn0 = fmaxf(m0, mx0), mn1 = fmaxf(m1, mx1);
        float al0 = __expf(m0 - mn0), al1 = __expf(m1 - mn1);
        m0 = mn0; m1 = mn1;
        float rs0 = 0.f, rs1 = 0.f;
#pragma unroll
        for (int j = 0; j < 4; j++) {
            sc[j][0] = __expf(sc[j][0] - m0);
            sc[j][1] = __expf(sc[j][1] - m0);
            sc[j][2] = __expf(sc[j][2] - m1);
            sc[j][3] = __expf(sc[j][3] - m1);
            rs0 += sc[j][0] + sc[j][1];
            rs1 += sc[j][2] + sc[j][3];
        }
        rs0 += __shfl_xor_sync(0xffffffffu, rs0, 1);
        rs0 += __shfl_xor_sync(0xffffffffu, rs0, 2);
        rs1 += __shfl_xor_sync(0xffffffffu, rs1, 1);
        rs1 += __shfl_xor_sync(0xffffffffu, rs1, 2);
        l0v = l0v * al0 + rs0;
        l1v = l1v * al1 + rs1;
#pragma unroll
        for (int tt = 0; tt < 16; tt++) {
            o[tt][0] *= al0; o[tt][1] *= al0;
            o[tt][2] *= al1; o[tt][3] *= al1;
        }

        // ---- O += P V (fp16 x2: Ph*Vh + Ph*Vl) ----
#pragma unroll
        for (int kb = 0; kb < 2; kb++) {
            uint32_t ph0 = packh(sc[2*kb][0],   sc[2*kb][1]);
            uint32_t ph1 = packh(sc[2*kb][2],   sc[2*kb][3]);
            uint32_t ph2 = packh(sc[2*kb+1][0], sc[2*kb+1][1]);
            uint32_t ph3 = packh(sc[2*kb+1][2], sc[2*kb+1][3]);
            const uint32_t kb_off = kb * 32 + kcol_off;
#pragma unroll
            for (int np = 0; np < 8; np++) {
                uint32_t roff = (np * 16 + (lane & 15)) * VROW_B + kb_off;
                uint32_t r0, r1, r2, r3, s0, s1, s2, s3;
                ldm_x4(uvh + roff, r0, r1, r2, r3);
                ldm_x4(uvl + roff, s0, s1, s2, s3);
                mma_f16(o[2*np][0], o[2*np][1], o[2*np][2], o[2*np][3],
                        ph0, ph1, ph2, ph3, r0, r2);
                mma_f16(o[2*np+1][0], o[2*np+1][1], o[2*np+1][2], o[2*np+1][3],
                        ph0, ph1, ph2, ph3, r1, r3);
                mma_f16(o[2*np][0], o[2*np][1], o[2*np][2], o[2*np][3],
                        ph0, ph1, ph2, ph3, s0, s2);
                mma_f16(o[2*np+1][0], o[2*np+1][1], o[2*np+1][2], o[2*np+1][3],
                        ph0, ph1, ph2, ph3, s1, s3);
            }
        }

        __syncthreads();
        if (t + 2 < T) STAGE_KV(t + 2, buf);
    }
#undef STAGE_KV

    // epilogue: normalize, write hi-only fp16 [B,S,HQ,HD]
    float inv0 = 1.0f / l0v, inv1 = 1.0f / l1v;
    int s0 = q0 + warp * 16 + (lane >> 2);
    int s1 = s0 + 8;
    size_t base0 = (((size_t)b * S_ + s0) * HQ_ + h) * HD_ + 2 * (lane & 3);
    size_t base1 = (((size_t)b * S_ + s1) * HQ_ + h) * HD_ + 2 * (lane & 3);
#pragma unroll
    for (int t = 0; t < 16; t++) {
        *(__half2*)(Oh + base0 + 8 * t) =
            __floats2half2_rn(o[t][0] * inv0, o[t][1] * inv0);
        *(__half2*)(Oh + base1 + 8 * t) =
            __floats2half2_rn(o[t][2] * inv1, o[t][3] * inv1);
    }
}

// ---------------------------------------------------------------------------
extern "C" void kernel_launch(void* const* d_in, const int* in_sizes, int n_in,
                              void* d_out, int out_size)
{
    const float* x  = (const float*)d_in[0];
    const float* wq = (const float*)d_in[1];
    const float* wk = (const float*)d_in[2];
    const float* wv = (const float*)d_in[3];
    const float* wo = (const float*)d_in[4];
    const float* fc = (const float*)d_in[5];
    const float* fs = (const float*)d_in[6];
    float* out = (float*)d_out;

    __half *xh, *wqkvh, *wqkvl, *woh, *wol;
    __half *qh, *kh, *kl, *vth, *vtl, *ah;
    cudaGetSymbolAddress((void**)&xh, g_xh);
    cudaGetSymbolAddress((void**)&wqkvh, g_wqkvh);
    cudaGetSymbolAddress((void**)&wqkvl, g_wqkvl);
    cudaGetSymbolAddress((void**)&woh, g_woh);
    cudaGetSymbolAddress((void**)&wol, g_wol);
    cudaGetSymbolAddress((void**)&qh, g_qh);
    cudaGetSymbolAddress((void**)&kh, g_kh);
    cudaGetSymbolAddress((void**)&kl, g_kl);
    cudaGetSymbolAddress((void**)&vth, g_vth);
    cudaGetSymbolAddress((void**)&vtl, g_vtl);
    cudaGetSymbolAddress((void**)&ah, g_ah);

    const int M = B_ * S_;  // 4096

    // converts/splits
    int n4x = (B_ * S_ * D_) / 4;
    conv_kernel<<<(n4x + 255) / 256, 256>>>(x, xh, n4x);
    int n4q = (HQ_ * HD_ * D_) / 4;
    split_kernel<<<(n4q + 255) / 256, 256>>>(wq, wqkvh, wqkvl, n4q);
    int n4k = (HKV_ * HD_ * D_) / 4;
    size_t offk = (size_t)HQ_ * HD_ * D_;
    size_t offv = offk + (size_t)HKV_ * HD_ * D_;
    split_kernel<<<(n4k + 255) / 256, 256>>>(wk, wqkvh + offk, wqkvl + offk, n4k);
    split_kernel<<<(n4k + 255) / 256, 256>>>(wv, wqkvh + offv, wqkvl + offv, n4k);
    int n4o = (D_ * HQ_ * HD_) / 4;
    split_kernel<<<(n4o + 255) / 256, 256>>>(wo, woh, wol, n4o);

    cudaFuncSetAttribute(gemm_fp16x2, cudaFuncAttributeMaxDynamicSharedMemorySize, GSMEM);

    // fused QKV projection (rope + layout + precision split in epilogue)
    gemm_fp16x2<<<dim3(NQKV / 128, M / 128), 256, GSMEM>>>(
        xh, wqkvh, wqkvl, nullptr,
        qh, kh, kl, vth, vtl, M, NQKV, D_, 3, fc, fs);

    // tensor-core attention
    cudaFuncSetAttribute(attn_mma3, cudaFuncAttributeMaxDynamicSharedMemorySize, ATT_SMEM);
    attn_mma3<<<dim3(S_ / QT, B_ * HQ_), 256, ATT_SMEM>>>(
        qh, kh, kl, vth, vtl, ah);

    // output projection -> d_out (fp32)
    gemm_fp16x2<<<dim3(D_ / 128, M / 128), 256, GSMEM>>>(
        ah, woh, wol, out,
        nullptr, nullptr, nullptr, nullptr, nullptr, M, D_, D_, 0, fc, fs);
}

// round 9
// speedup vs baseline: 5.6897x; 1.4343x over previous
#include <cuda_runtime.h>
#include <cuda_fp16.h>
#include <cstdint>
#include <math.h>

#define B_   2
#define S_   2048
#define D_   4096
#define HQ_  32
#define HKV_ 8
#define HD_  128

// ---------------- scratch (static device globals; no allocations) ----------
__device__ __half g_xh[(size_t)B_ * S_ * D_];                  // x hi only
#define NQKV (HQ_ * HD_ + 2 * HKV_ * HD_)   // 6144
__device__ __half g_wqkvh[(size_t)NQKV * D_];                  // weights hi only
__device__ __half g_woh[(size_t)D_ * HQ_ * HD_];
// rope'd Q (hi only), K (h/l), transposed V (h/l)
__device__ __half g_qh[(size_t)B_ * HQ_ * S_ * HD_];   // [B,HQ,S,HD]
__device__ __half g_kh[(size_t)B_ * HKV_ * S_ * HD_];  // [B,HKV,S,HD]
__device__ __half g_kl[(size_t)B_ * HKV_ * S_ * HD_];
__device__ __half g_vth[(size_t)B_ * HKV_ * HD_ * S_]; // [B,HKV,HD,S]
__device__ __half g_vtl[(size_t)B_ * HKV_ * HD_ * S_];
// attention output (hi only, [B,S,HQ,HD])
__device__ __half g_ah[(size_t)B_ * S_ * HQ_ * HD_];

// ---------------- PTX helpers (family-portable only) -----------------------
__device__ __forceinline__ uint32_t smem_u32(const void* p) {
    uint32_t a;
    asm("{ .reg .u64 t; cvta.to.shared.u64 t, %1; cvt.u32.u64 %0, t; }" : "=r"(a) : "l"(p));
    return a;
}
__device__ __forceinline__ void cp16(uint32_t s, const void* g) {
    asm volatile("cp.async.cg.shared.global [%0], [%1], 16;" :: "r"(s), "l"(g));
}
__device__ __forceinline__ void cp_commit() {
    asm volatile("cp.async.commit_group;" ::: "memory");
}
__device__ __forceinline__ void ldm_x4(uint32_t a, uint32_t& r0, uint32_t& r1,
                                       uint32_t& r2, uint32_t& r3) {
    asm volatile("ldmatrix.sync.aligned.m8n8.x4.shared.b16 {%0,%1,%2,%3}, [%4];"
                 : "=r"(r0), "=r"(r1), "=r"(r2), "=r"(r3) : "r"(a));
}
__device__ __forceinline__ void mma_f16(float& d0, float& d1, float& d2, float& d3,
                                        uint32_t a0, uint32_t a1, uint32_t a2, uint32_t a3,
                                        uint32_t b0, uint32_t b1) {
    asm volatile("mma.sync.aligned.m16n8k16.row.col.f32.f16.f16.f32 "
                 "{%0,%1,%2,%3}, {%4,%5,%6,%7}, {%8,%9}, {%0,%1,%2,%3};"
                 : "+f"(d0), "+f"(d1), "+f"(d2), "+f"(d3)
                 : "r"(a0), "r"(a1), "r"(a2), "r"(a3), "r"(b0), "r"(b1));
}
__device__ __forceinline__ uint32_t packh(float lo, float hi) {
    __half2 t = __floats2half2_rn(lo, hi);
    return *(uint32_t*)&t;
}

// ---------------------------------------------------------------------------
// fp32 -> fp16 (hi only)
// ---------------------------------------------------------------------------
__global__ void conv_kernel(const float* __restrict__ in,
                            __half* __restrict__ hi, int n4)
{
    int i = blockIdx.x * blockDim.x + threadIdx.x;
    if (i >= n4) return;
    float4 v = ((const float4*)in)[i];
    __half2* hp = (__half2*)(hi + 4 * (size_t)i);
    hp[0] = __floats2half2_rn(v.x, v.y);
    hp[1] = __floats2half2_rn(v.z, v.w);
}

// ---------------------------------------------------------------------------
// fp16 single-pass GEMM (NT): C = A*B^T, fp32 accum via mma.sync.
// CTA 128x128, K-chunk 32, 8 warps, 2 CTAs/SM, double-buffered cp.async.
// modes: 0 = fp32 C; 3 = fused QKV epilogue (rope Q/K, V transposed, h/l K,V).
// ---------------------------------------------------------------------------
#define RSTR   40
#define TILE_B (128 * RSTR * 2)     // 10240 B
#define STG_B  (2 * TILE_B)         // Ah, Bh
#define GSMEM  (2 * STG_B)          // 40960 B

__global__ __launch_bounds__(256, 2) void gemm_fp16(
    const __half* __restrict__ Ah, const __half* __restrict__ Bh,
    float* __restrict__ Cf,
    __half* __restrict__ Qh,
    __half* __restrict__ Kh, __half* __restrict__ Kl,
    __half* __restrict__ Vh, __half* __restrict__ Vl,
    int M, int N, int K, int mode,
    const float* __restrict__ fc, const float* __restrict__ fs)
{
    extern __shared__ char smem[];
    const uint32_t sb = smem_u32(smem);
    const int tid = threadIdx.x;
    const int lane = tid & 31;
    const int wid = tid >> 5;
    const int wm = wid >> 2;
    const int wn = wid & 3;
    const int bm = blockIdx.y * 128;
    const int bn = blockIdx.x * 128;

    float acc[4][4][4];
#pragma unroll
    for (int i = 0; i < 4; i++)
#pragma unroll
        for (int j = 0; j < 4; j++)
#pragma unroll
            for (int c = 0; c < 4; c++) acc[i][j][c] = 0.f;

    const int iters = K >> 5;
    const int row0 = tid >> 2;
    const int col0 = tid & 3;

#define PREFETCH(it_) do {                                                    \
    const int st_ = (it_) & 1;                                                \
    const int k0_ = (it_) << 5;                                               \
    const uint32_t sob_ = sb + st_ * STG_B;                                   \
    _Pragma("unroll")                                                         \
    for (int j_ = 0; j_ < 2; j_++) {                                          \
        int row_ = row0 + j_ * 64;                                            \
        uint32_t so_ = sob_ + row_ * (RSTR * 2) + col0 * 16;                  \
        size_t ga_ = (size_t)(bm + row_) * K + k0_ + col0 * 8;                \
        size_t gb_ = (size_t)(bn + row_) * K + k0_ + col0 * 8;                \
        cp16(so_ + 0 * TILE_B, Ah + ga_);                                     \
        cp16(so_ + 1 * TILE_B, Bh + gb_);                                     \
    }                                                                         \
    cp_commit();                                                              \
} while (0)

    PREFETCH(0);
    if (iters > 1) PREFETCH(1);

    for (int it = 0; it < iters; it++) {
        if (it + 1 < iters) {
            asm volatile("cp.async.wait_group 1;" ::: "memory");
        } else {
            asm volatile("cp.async.wait_group 0;" ::: "memory");
        }
        __syncthreads();

        const uint32_t base = sb + (it & 1) * STG_B;
        const uint32_t a_h = base;
        const uint32_t b_h = base + TILE_B;

#pragma unroll
        for (int kk = 0; kk < 2; kk++) {
            const int kc = kk * 16 + (lane >> 4) * 8;
            uint32_t a[4][4], bhf[4][2];
#pragma unroll
            for (int nq = 0; nq < 2; nq++) {
                int row = wn * 32 + nq * 16 + (lane & 15);
                uint32_t off = row * (RSTR * 2) + kc * 2;
                uint32_t r0, r1, r2, r3;
                ldm_x4(b_h + off, r0, r1, r2, r3);
                bhf[nq * 2][0] = r0; bhf[nq * 2][1] = r2;
                bhf[nq * 2 + 1][0] = r1; bhf[nq * 2 + 1][1] = r3;
            }
#pragma unroll
            for (int mf = 0; mf < 4; mf++) {
                int row = wm * 64 + mf * 16 + (lane & 15);
                ldm_x4(a_h + row * (RSTR * 2) + kc * 2,
                       a[mf][0], a[mf][1], a[mf][2], a[mf][3]);
            }
#pragma unroll
            for (int mf = 0; mf < 4; mf++)
#pragma unroll
                for (int nf = 0; nf < 4; nf++)
                    mma_f16(acc[mf][nf][0], acc[mf][nf][1], acc[mf][nf][2], acc[mf][nf][3],
                            a[mf][0], a[mf][1], a[mf][2], a[mf][3],
                            bhf[nf][0], bhf[nf][1]);
        }

        __syncthreads();
        if (it + 2 < iters) PREFETCH(it + 2);
    }

    const int qr = lane >> 2;
    const int qc = lane & 3;
#pragma unroll
    for (int mf = 0; mf < 4; mf++) {
#pragma unroll
        for (int half_ = 0; half_ < 2; half_++) {
            int m = bm + wm * 64 + mf * 16 + qr + half_ * 8;
            if (mode == 0) {
                float* dst = Cf + (size_t)m * N + bn;
#pragma unroll
                for (int nf = 0; nf < 4; nf++) {
                    int n = wn * 32 + nf * 8 + 2 * qc;
                    float2 w = half_ ? make_float2(acc[mf][nf][2], acc[mf][nf][3])
                                     : make_float2(acc[mf][nf][0], acc[mf][nf][1]);
                    *(float2*)(dst + n) = w;
                }
            } else {
                int b = m >> 11;
                int s = m & (S_ - 1);
#pragma unroll
                for (int nf = 0; nf < 4; nf++) {
                    int n = bn + wn * 32 + nf * 8 + 2 * qc;
                    float2 w = half_ ? make_float2(acc[mf][nf][2], acc[mf][nf][3])
                                     : make_float2(acc[mf][nf][0], acc[mf][nf][1]);
                    if (n < HQ_ * HD_) {                    // Q: rope, hi only
                        int h = n >> 7;
                        int d = n & (HD_ - 1);
                        int i = d >> 1;
                        float c = fc[s * (HD_ / 2) + i];
                        float sn = fs[s * (HD_ / 2) + i];
                        float x0 = w.x * c - w.y * sn;
                        float x1 = w.x * sn + w.y * c;
                        size_t off = (((size_t)b * HQ_ + h) * S_ + s) * HD_ + d;
                        *(__half2*)(Qh + off) = __floats2half2_rn(x0, x1);
                    } else if (n < HQ_ * HD_ + HKV_ * HD_) { // K: rope, h/l split
                        int nk = n - HQ_ * HD_;
                        int h = nk >> 7;
                        int d = nk & (HD_ - 1);
                        int i = d >> 1;
                        float c = fc[s * (HD_ / 2) + i];
                        float sn = fs[s * (HD_ / 2) + i];
                        float x0 = w.x * c - w.y * sn;
                        float x1 = w.x * sn + w.y * c;
                        __half h0 = __float2half_rn(x0);
                        __half h1 = __float2half_rn(x1);
                        size_t off = (((size_t)b * HKV_ + h) * S_ + s) * HD_ + d;
                        *(__half2*)(Kh + off) = __halves2half2(h0, h1);
                        *(__half2*)(Kl + off) = __floats2half2_rn(
                            x0 - __half2float(h0), x1 - __half2float(h1));
                    } else {                                 // V: transposed, h/l split
                        int nv = n - (HQ_ * HD_ + HKV_ * HD_);
                        int h = nv >> 7;
                        int d = nv & (HD_ - 1);
                        __half h0 = __float2half_rn(w.x);
                        __half h1 = __float2half_rn(w.y);
                        size_t off = (((size_t)b * HKV_ + h) * HD_ + d) * S_ + s;
                        Vh[off] = h0;
                        Vl[off] = __float2half_rn(w.x - __half2float(h0));
                        Vh[off + S_] = h1;
                        Vl[off + S_] = __float2half_rn(w.y - __half2float(h1));
                    }
                }
            }
        }
    }
#undef PREFETCH
}

// ---------------------------------------------------------------------------
// Tensor-core flash attention (fp16x2): Q hi-only (A), K h/l (B), V h/l (B).
// Grid (S/128, B*HQ), block 256 (8 warps), 2 CTAs/SM. KT=32, double-buffered.
// ---------------------------------------------------------------------------
#define QT 128
#define KT 32
#define QROW_B 272
#define VROW_B 80
#define QTILE_B (QT * QROW_B)
#define KTILE_B (KT * QROW_B)
#define VTILE_B (128 * VROW_B)
#define OFF_K   QTILE_B
#define OFF_V   (OFF_K + 4 * KTILE_B)
#define ATT_SMEM (OFF_V + 4 * VTILE_B)

__global__ __launch_bounds__(256, 2) void attn_mma3(
    const __half* __restrict__ Qh_g,
    const __half* __restrict__ Kh_g, const __half* __restrict__ Kl_g,
    const __half* __restrict__ Vh_g, const __half* __restrict__ Vl_g,
    __half* __restrict__ Oh)
{
    extern __shared__ char smem[];
    const uint32_t sb = smem_u32(smem);
    const int bh = blockIdx.y;
    const int b = bh >> 5;
    const int h = bh & (HQ_ - 1);
    const int kvh = h >> 2;
    const int q0 = blockIdx.x * QT;
    const int tid = threadIdx.x;
    const int lane = tid & 31;
    const int warp = tid >> 5;

    const __half* qh = Qh_g + (((size_t)b * HQ_ + h) * S_ + q0) * HD_;
    const __half* kh = Kh_g + ((size_t)b * HKV_ + kvh) * S_ * HD_;
    const __half* kl = Kl_g + ((size_t)b * HKV_ + kvh) * S_ * HD_;
    const __half* vh = Vh_g + ((size_t)b * HKV_ + kvh) * HD_ * S_;
    const __half* vl = Vl_g + ((size_t)b * HKV_ + kvh) * HD_ * S_;

#pragma unroll
    for (int i = 0; i < 8; i++) {
        int lin = tid + i * 256;
        int r = lin >> 4, c = lin & 15;
        cp16(sb + r * QROW_B + c * 16, qh + (size_t)r * HD_ + c * 8);
    }
    cp_commit();

#define STAGE_KV(t_, buf_) do {                                               \
    int t0_ = (t_) * KT;                                                      \
    uint32_t kb_ = sb + OFF_K + (buf_) * (2 * KTILE_B);                       \
    uint32_t vb_ = sb + OFF_V + (buf_) * (2 * VTILE_B);                       \
    _Pragma("unroll")                                                         \
    for (int i_ = 0; i_ < 2; i_++) {                                          \
        int lin_ = tid + i_ * 256;                                            \
        int r_ = lin_ >> 4, c_ = lin_ & 15;                                   \
        cp16(kb_ + r_ * QROW_B + c_ * 16, kh + (size_t)(t0_ + r_) * HD_ + c_ * 8); \
        cp16(kb_ + KTILE_B + r_ * QROW_B + c_ * 16, kl + (size_t)(t0_ + r_) * HD_ + c_ * 8); \
        int d_ = lin_ >> 2, c2_ = lin_ & 3;                                   \
        cp16(vb_ + d_ * VROW_B + c2_ * 16, vh + (size_t)d_ * S_ + t0_ + c2_ * 8); \
        cp16(vb_ + VTILE_B + d_ * VROW_B + c2_ * 16, vl + (size_t)d_ * S_ + t0_ + c2_ * 8); \
    }                                                                         \
    cp_commit();                                                              \
} while (0)

    STAGE_KV(0, 0);
    STAGE_KV(1, 1);

    float o[16][4];
#pragma unroll
    for (int t = 0; t < 16; t++)
#pragma unroll
        for (int c = 0; c < 4; c++) o[t][c] = 0.f;
    float m0 = -1e30f, m1 = -1e30f, l0v = 0.f, l1v = 0.f;

    const float scale = 0.08838834764831845f;
    const uint32_t qrow_off = (warp * 16 + (lane & 15)) * QROW_B;
    const uint32_t kcol_off = (lane >> 4) * 16;

    const int T = S_ / KT;   // 64
    for (int t = 0; t < T; t++) {
        if (t + 1 < T) {
            asm volatile("cp.async.wait_group 1;" ::: "memory");
        } else {
            asm volatile("cp.async.wait_group 0;" ::: "memory");
        }
        __syncthreads();

        const int buf = t & 1;
        const uint32_t ukh = sb + OFF_K + buf * (2 * KTILE_B);
        const uint32_t ukl = ukh + KTILE_B;
        const uint32_t uvh = sb + OFF_V + buf * (2 * VTILE_B);
        const uint32_t uvl = uvh + VTILE_B;

        float sc[4][4];
#pragma unroll
        for (int j = 0; j < 4; j++)
#pragma unroll
            for (int c = 0; c < 4; c++) sc[j][c] = 0.f;

#pragma unroll
        for (int ks = 0; ks < 8; ks++) {
            const uint32_t kb_off = ks * 32 + kcol_off;
            uint32_t qa[4];
            ldm_x4(sb + qrow_off + kb_off, qa[0], qa[1], qa[2], qa[3]);
#pragma unroll
            for (int np = 0; np < 2; np++) {
                uint32_t roff = (np * 16 + (lane & 15)) * QROW_B + kb_off;
                uint32_t r0, r1, r2, r3, s0, s1, s2, s3;
                ldm_x4(ukh + roff, r0, r1, r2, r3);
                ldm_x4(ukl + roff, s0, s1, s2, s3);
                mma_f16(sc[2*np][0], sc[2*np][1], sc[2*np][2], sc[2*np][3],
                        qa[0], qa[1], qa[2], qa[3], r0, r2);
                mma_f16(sc[2*np+1][0], sc[2*np+1][1], sc[2*np+1][2], sc[2*np+1][3],
                        qa[0], qa[1], qa[2], qa[3], r1, r3);
                mma_f16(sc[2*np][0], sc[2*np][1], sc[2*np][2], sc[2*np][3],
                        qa[0], qa[1], qa[2], qa[3], s0, s2);
                mma_f16(sc[2*np+1][0], sc[2*np+1][1], sc[2*np+1][2], sc[2*np+1][3],
                        qa[0], qa[1], qa[2], qa[3], s1, s3);
            }
        }

        float mx0 = -1e30f, mx1 = -1e30f;
#pragma unroll
        for (int j = 0; j < 4; j++) {
#pragma unroll
            for (int c = 0; c < 4; c++) sc[j][c] *= scale;
            mx0 = fmaxf(mx0, fmaxf(sc[j][0], sc[j][1]));
            mx1 = fmaxf(mx1, fmaxf(sc[j][2], sc[j][3]));
        }
        mx0 = fmaxf(mx0, __shfl_xor_sync(0xffffffffu, mx0, 1));
        mx0 = fmaxf(mx0, __shfl_xor_sync(0xffffffffu, mx0, 2));
        mx1 = fmaxf(mx1, __shfl_xor_sync(0xffffffffu, mx1, 1));
        mx1 = fmaxf(mx1, __shfl_xor_sync(0xffffffffu, mx1, 2));
        float mn0 = fmaxf(m0, mx0), mn1 = fmaxf(m1, mx1);
        float al0 = __expf(m0 - mn0), al1 = __expf(m1 - mn1);
        m0 = mn0; m1 = mn1;
        float rs0 = 0.f, rs1 = 0.f;
#pragma unroll
        for (int j = 0; j < 4; j++) {
            sc[j][0] = __expf(sc[j][0] - m0);
            sc[j][1] = __expf(sc[j][1] - m0);
            sc[j][2] = __expf(sc[j][2] - m1);
            sc[j][3] = __expf(sc[j][3] - m1);
            rs0 += sc[j][0] + sc[j][1];
            rs1 += sc[j][2] + sc[j][3];
        }
        rs0 += __shfl_xor_sync(0xffffffffu, rs0, 1);
        rs0 += __shfl_xor_sync(0xffffffffu, rs0, 2);
        rs1 += __shfl_xor_sync(0xffffffffu, rs1, 1);
        rs1 += __shfl_xor_sync(0xffffffffu, rs1, 2);
        l0v = l0v * al0 + rs0;
        l1v = l1v * al1 + rs1;
#pragma unroll
        for (int tt = 0; tt < 16; tt++) {
            o[tt][0] *= al0; o[tt][1] *= al0;
            o[tt][2] *= al1; o[tt][3] *= al1;
        }

#pragma unroll
        for (int kb = 0; kb < 2; kb++) {
            uint32_t ph0 = packh(sc[2*kb][0],   sc[2*kb][1]);
            uint32_t ph1 = packh(sc[2*kb][2],   sc[2*kb][3]);
            uint32_t ph2 = packh(sc[2*kb+1][0], sc[2*kb+1][1]);
            uint32_t ph3 = packh(sc[2*kb+1][2], sc[2*kb+1][3]);
            const uint32_t kb_off = kb * 32 + kcol_off;
#pragma unroll
            for (int np = 0; np < 8; np++) {
                uint32_t roff = (np * 16 + (lane & 15)) * VROW_B + kb_off;
                uint32_t r0, r1, r2, r3, s0, s1, s2, s3;
                ldm_x4(uvh + roff, r0, r1, r2, r3);
                ldm_x4(uvl + roff, s0, s1, s2, s3);
                mma_f16(o[2*np][0], o[2*np][1], o[2*np][2], o[2*np][3],
                        ph0, ph1, ph2, ph3, r0, r2);
                mma_f16(o[2*np+1][0], o[2*np+1][1], o[2*np+1][2], o[2*np+1][3],
                        ph0, ph1, ph2, ph3, r1, r3);
                mma_f16(o[2*np][0], o[2*np][1], o[2*np][2], o[2*np][3],
                        ph0, ph1, ph2, ph3, s0, s2);
                mma_f16(o[2*np+1][0], o[2*np+1][1], o[2*np+1][2], o[2*np+1][3],
                        ph0, ph1, ph2, ph3, s1, s3);
            }
        }

        __syncthreads();
        if (t + 2 < T) STAGE_KV(t + 2, buf);
    }
#undef STAGE_KV

    float inv0 = 1.0f / l0v, inv1 = 1.0f / l1v;
    int s0 = q0 + warp * 16 + (lane >> 2);
    int s1 = s0 + 8;
    size_t base0 = (((size_t)b * S_ + s0) * HQ_ + h) * HD_ + 2 * (lane & 3);
    size_t base1 = (((size_t)b * S_ + s1) * HQ_ + h) * HD_ + 2 * (lane & 3);
#pragma unroll
    for (int t = 0; t < 16; t++) {
        *(__half2*)(Oh + base0 + 8 * t) =
            __floats2half2_rn(o[t][0] * inv0, o[t][1] * inv0);
        *(__half2*)(Oh + base1 + 8 * t) =
            __floats2half2_rn(o[t][2] * inv1, o[t][3] * inv1);
    }
}

// ---------------------------------------------------------------------------
extern "C" void kernel_launch(void* const* d_in, const int* in_sizes, int n_in,
                              void* d_out, int out_size)
{
    const float* x  = (const float*)d_in[0];
    const float* wq = (const float*)d_in[1];
    const float* wk = (const float*)d_in[2];
    const float* wv = (const float*)d_in[3];
    const float* wo = (const float*)d_in[4];
    const float* fc = (const float*)d_in[5];
    const float* fs = (const float*)d_in[6];
    float* out = (float*)d_out;

    __half *xh, *wqkvh, *woh;
    __half *qh, *kh, *kl, *vth, *vtl, *ah;
    cudaGetSymbolAddress((void**)&xh, g_xh);
    cudaGetSymbolAddress((void**)&wqkvh, g_wqkvh);
    cudaGetSymbolAddress((void**)&woh, g_woh);
    cudaGetSymbolAddress((void**)&qh, g_qh);
    cudaGetSymbolAddress((void**)&kh, g_kh);
    cudaGetSymbolAddress((void**)&kl, g_kl);
    cudaGetSymbolAddress((void**)&vth, g_vth);
    cudaGetSymbolAddress((void**)&vtl, g_vtl);
    cudaGetSymbolAddress((void**)&ah, g_ah);

    const int M = B_ * S_;  // 4096

    // converts (all hi-only)
    int n4x = (B_ * S_ * D_) / 4;
    conv_kernel<<<(n4x + 255) / 256, 256>>>(x, xh, n4x);
    int n4q = (HQ_ * HD_ * D_) / 4;
    conv_kernel<<<(n4q + 255) / 256, 256>>>(wq, wqkvh, n4q);
    int n4k = (HKV_ * HD_ * D_) / 4;
    size_t offk = (size_t)HQ_ * HD_ * D_;
    size_t offv = offk + (size_t)HKV_ * HD_ * D_;
    conv_kernel<<<(n4k + 255) / 256, 256>>>(wk, wqkvh + offk, n4k);
    conv_kernel<<<(n4k + 255) / 256, 256>>>(wv, wqkvh + offv, n4k);
    int n4o = (D_ * HQ_ * HD_) / 4;
    conv_kernel<<<(n4o + 255) / 256, 256>>>(wo, woh, n4o);

    cudaFuncSetAttribute(gemm_fp16, cudaFuncAttributeMaxDynamicSharedMemorySize, GSMEM);

    // fused QKV projection (rope + layout + K/V h/l split in epilogue)
    gemm_fp16<<<dim3(NQKV / 128, M / 128), 256, GSMEM>>>(
        xh, wqkvh, nullptr,
        qh, kh, kl, vth, vtl, M, NQKV, D_, 3, fc, fs);

    // tensor-core attention
    cudaFuncSetAttribute(attn_mma3, cudaFuncAttributeMaxDynamicSharedMemorySize, ATT_SMEM);
    attn_mma3<<<dim3(S_ / QT, B_ * HQ_), 256, ATT_SMEM>>>(
        qh, kh, kl, vth, vtl, ah);

    // output projection -> d_out (fp32)
    gemm_fp16<<<dim3(D_ / 128, M / 128), 256, GSMEM>>>(
        ah, woh, out,
        nullptr, nullptr, nullptr, nullptr, nullptr, M, D_, D_, 0, fc, fs);
}

// round 10
// speedup vs baseline: 6.7886x; 1.1931x over previous
#include <cuda_runtime.h>
#include <cuda_fp16.h>
#include <cstdint>
#include <math.h>

#define B_   2
#define S_   2048
#define D_   4096
#define HQ_  32
#define HKV_ 8
#define HD_  128

// ---------------- scratch (static device globals; no allocations) ----------
__device__ __half g_xh[(size_t)B_ * S_ * D_];                  // x hi only
#define NQKV (HQ_ * HD_ + 2 * HKV_ * HD_)   // 6144
__device__ __half g_wqkvh[(size_t)NQKV * D_];                  // weights hi only
__device__ __half g_woh[(size_t)D_ * HQ_ * HD_];
// rope'd Q, K, transposed V (all fp16)
__device__ __half g_qh[(size_t)B_ * HQ_ * S_ * HD_];   // [B,HQ,S,HD]
__device__ __half g_kh[(size_t)B_ * HKV_ * S_ * HD_];  // [B,HKV,S,HD]
__device__ __half g_vth[(size_t)B_ * HKV_ * HD_ * S_]; // [B,HKV,HD,S]
// attention output (fp16, [B,S,HQ,HD])
__device__ __half g_ah[(size_t)B_ * S_ * HQ_ * HD_];

// ---------------- PTX helpers (family-portable only) -----------------------
__device__ __forceinline__ uint32_t smem_u32(const void* p) {
    uint32_t a;
    asm("{ .reg .u64 t; cvta.to.shared.u64 t, %1; cvt.u32.u64 %0, t; }" : "=r"(a) : "l"(p));
    return a;
}
__device__ __forceinline__ void cp16(uint32_t s, const void* g) {
    asm volatile("cp.async.cg.shared.global [%0], [%1], 16;" :: "r"(s), "l"(g));
}
__device__ __forceinline__ void cp_commit() {
    asm volatile("cp.async.commit_group;" ::: "memory");
}
__device__ __forceinline__ void ldm_x4(uint32_t a, uint32_t& r0, uint32_t& r1,
                                       uint32_t& r2, uint32_t& r3) {
    asm volatile("ldmatrix.sync.aligned.m8n8.x4.shared.b16 {%0,%1,%2,%3}, [%4];"
                 : "=r"(r0), "=r"(r1), "=r"(r2), "=r"(r3) : "r"(a));
}
__device__ __forceinline__ void mma_f16(float& d0, float& d1, float& d2, float& d3,
                                        uint32_t a0, uint32_t a1, uint32_t a2, uint32_t a3,
                                        uint32_t b0, uint32_t b1) {
    asm volatile("mma.sync.aligned.m16n8k16.row.col.f32.f16.f16.f32 "
                 "{%0,%1,%2,%3}, {%4,%5,%6,%7}, {%8,%9}, {%0,%1,%2,%3};"
                 : "+f"(d0), "+f"(d1), "+f"(d2), "+f"(d3)
                 : "r"(a0), "r"(a1), "r"(a2), "r"(a3), "r"(b0), "r"(b1));
}
__device__ __forceinline__ uint32_t packh(float lo, float hi) {
    __half2 t = __floats2half2_rn(lo, hi);
    return *(uint32_t*)&t;
}

// ---------------------------------------------------------------------------
// fp32 -> fp16
// ---------------------------------------------------------------------------
__global__ void conv_kernel(const float* __restrict__ in,
                            __half* __restrict__ hi, int n4)
{
    int i = blockIdx.x * blockDim.x + threadIdx.x;
    if (i >= n4) return;
    float4 v = ((const float4*)in)[i];
    __half2* hp = (__half2*)(hi + 4 * (size_t)i);
    hp[0] = __floats2half2_rn(v.x, v.y);
    hp[1] = __floats2half2_rn(v.z, v.w);
}

// ---------------------------------------------------------------------------
// fp16 single-pass GEMM (NT): C = A*B^T, fp32 accum via mma.sync.
// CTA 128x128, K-chunk 32, 8 warps, 2 CTAs/SM, double-buffered cp.async.
// modes: 0 = fp32 C; 3 = fused QKV epilogue (rope Q/K, V transposed).
// ---------------------------------------------------------------------------
#define RSTR   40
#define TILE_B (128 * RSTR * 2)     // 10240 B
#define STG_B  (2 * TILE_B)         // Ah, Bh
#define GSMEM  (2 * STG_B)          // 40960 B

__global__ __launch_bounds__(256, 2) void gemm_fp16(
    const __half* __restrict__ Ah, const __half* __restrict__ Bh,
    float* __restrict__ Cf,
    __half* __restrict__ Qh, __half* __restrict__ Kh, __half* __restrict__ Vh,
    int M, int N, int K, int mode,
    const float* __restrict__ fc, const float* __restrict__ fs)
{
    extern __shared__ char smem[];
    const uint32_t sb = smem_u32(smem);
    const int tid = threadIdx.x;
    const int lane = tid & 31;
    const int wid = tid >> 5;
    const int wm = wid >> 2;
    const int wn = wid & 3;
    const int bm = blockIdx.y * 128;
    const int bn = blockIdx.x * 128;

    float acc[4][4][4];
#pragma unroll
    for (int i = 0; i < 4; i++)
#pragma unroll
        for (int j = 0; j < 4; j++)
#pragma unroll
            for (int c = 0; c < 4; c++) acc[i][j][c] = 0.f;

    const int iters = K >> 5;
    const int row0 = tid >> 2;
    const int col0 = tid & 3;

#define PREFETCH(it_) do {                                                    \
    const int st_ = (it_) & 1;                                                \
    const int k0_ = (it_) << 5;                                               \
    const uint32_t sob_ = sb + st_ * STG_B;                                   \
    _Pragma("unroll")                                                         \
    for (int j_ = 0; j_ < 2; j_++) {                                          \
        int row_ = row0 + j_ * 64;                                            \
        uint32_t so_ = sob_ + row_ * (RSTR * 2) + col0 * 16;                  \
        size_t ga_ = (size_t)(bm + row_) * K + k0_ + col0 * 8;                \
        size_t gb_ = (size_t)(bn + row_) * K + k0_ + col0 * 8;                \
        cp16(so_ + 0 * TILE_B, Ah + ga_);                                     \
        cp16(so_ + 1 * TILE_B, Bh + gb_);                                     \
    }                                                                         \
    cp_commit();                                                              \
} while (0)

    PREFETCH(0);
    if (iters > 1) PREFETCH(1);

    for (int it = 0; it < iters; it++) {
        if (it + 1 < iters) {
            asm volatile("cp.async.wait_group 1;" ::: "memory");
        } else {
            asm volatile("cp.async.wait_group 0;" ::: "memory");
        }
        __syncthreads();

        const uint32_t base = sb + (it & 1) * STG_B;
        const uint32_t a_h = base;
        const uint32_t b_h = base + TILE_B;

#pragma unroll
        for (int kk = 0; kk < 2; kk++) {
            const int kc = kk * 16 + (lane >> 4) * 8;
            uint32_t a[4][4], bhf[4][2];
#pragma unroll
            for (int nq = 0; nq < 2; nq++) {
                int row = wn * 32 + nq * 16 + (lane & 15);
                uint32_t off = row * (RSTR * 2) + kc * 2;
                uint32_t r0, r1, r2, r3;
                ldm_x4(b_h + off, r0, r1, r2, r3);
                bhf[nq * 2][0] = r0; bhf[nq * 2][1] = r2;
                bhf[nq * 2 + 1][0] = r1; bhf[nq * 2 + 1][1] = r3;
            }
#pragma unroll
            for (int mf = 0; mf < 4; mf++) {
                int row = wm * 64 + mf * 16 + (lane & 15);
                ldm_x4(a_h + row * (RSTR * 2) + kc * 2,
                       a[mf][0], a[mf][1], a[mf][2], a[mf][3]);
            }
#pragma unroll
            for (int mf = 0; mf < 4; mf++)
#pragma unroll
                for (int nf = 0; nf < 4; nf++)
                    mma_f16(acc[mf][nf][0], acc[mf][nf][1], acc[mf][nf][2], acc[mf][nf][3],
                            a[mf][0], a[mf][1], a[mf][2], a[mf][3],
                            bhf[nf][0], bhf[nf][1]);
        }

        __syncthreads();
        if (it + 2 < iters) PREFETCH(it + 2);
    }

    const int qr = lane >> 2;
    const int qc = lane & 3;
#pragma unroll
    for (int mf = 0; mf < 4; mf++) {
#pragma unroll
        for (int half_ = 0; half_ < 2; half_++) {
            int m = bm + wm * 64 + mf * 16 + qr + half_ * 8;
            if (mode == 0) {
                float* dst = Cf + (size_t)m * N + bn;
#pragma unroll
                for (int nf = 0; nf < 4; nf++) {
                    int n = wn * 32 + nf * 8 + 2 * qc;
                    float2 w = half_ ? make_float2(acc[mf][nf][2], acc[mf][nf][3])
                                     : make_float2(acc[mf][nf][0], acc[mf][nf][1]);
                    *(float2*)(dst + n) = w;
                }
            } else {
                int b = m >> 11;
                int s = m & (S_ - 1);
#pragma unroll
                for (int nf = 0; nf < 4; nf++) {
                    int n = bn + wn * 32 + nf * 8 + 2 * qc;
                    float2 w = half_ ? make_float2(acc[mf][nf][2], acc[mf][nf][3])
                                     : make_float2(acc[mf][nf][0], acc[mf][nf][1]);
                    if (n < HQ_ * HD_) {                    // Q: rope
                        int h = n >> 7;
                        int d = n & (HD_ - 1);
                        int i = d >> 1;
                        float c = fc[s * (HD_ / 2) + i];
                        float sn = fs[s * (HD_ / 2) + i];
                        float x0 = w.x * c - w.y * sn;
                        float x1 = w.x * sn + w.y * c;
                        size_t off = (((size_t)b * HQ_ + h) * S_ + s) * HD_ + d;
                        *(__half2*)(Qh + off) = __floats2half2_rn(x0, x1);
                    } else if (n < HQ_ * HD_ + HKV_ * HD_) { // K: rope
                        int nk = n - HQ_ * HD_;
                        int h = nk >> 7;
                        int d = nk & (HD_ - 1);
                        int i = d >> 1;
                        float c = fc[s * (HD_ / 2) + i];
                        float sn = fs[s * (HD_ / 2) + i];
                        float x0 = w.x * c - w.y * sn;
                        float x1 = w.x * sn + w.y * c;
                        size_t off = (((size_t)b * HKV_ + h) * S_ + s) * HD_ + d;
                        *(__half2*)(Kh + off) = __floats2half2_rn(x0, x1);
                    } else {                                 // V: transposed
                        int nv = n - (HQ_ * HD_ + HKV_ * HD_);
                        int h = nv >> 7;
                        int d = nv & (HD_ - 1);
                        size_t off = (((size_t)b * HKV_ + h) * HD_ + d) * S_ + s;
                        Vh[off] = __float2half_rn(w.x);
                        Vh[off + S_] = __float2half_rn(w.y);
                    }
                }
            }
        }
    }
#undef PREFETCH
}

// ---------------------------------------------------------------------------
// Tensor-core flash attention (plain fp16 operands, fp32 accum).
// Grid (S/128, B*HQ), block 256 (8 warps), 2 CTAs/SM. KT=32, double-buffered.
// smem = 72704 B.
// ---------------------------------------------------------------------------
#define QT 128
#define KT 32
#define QROW_B 272                 // 128 halves + 8 pad
#define VROW_B 80                  // 32 halves + 8 pad
#define QTILE_B (QT * QROW_B)      // 34816
#define KTILE_B (KT * QROW_B)      // 8704
#define VTILE_B (128 * VROW_B)     // 10240
#define OFF_K   QTILE_B                       // 34816
#define OFF_V   (OFF_K + 2 * KTILE_B)         // 52224
#define ATT_SMEM (OFF_V + 2 * VTILE_B)        // 72704

__global__ __launch_bounds__(256, 2) void attn_mma4(
    const __half* __restrict__ Qh_g,
    const __half* __restrict__ Kh_g,
    const __half* __restrict__ Vh_g,
    __half* __restrict__ Oh)
{
    extern __shared__ char smem[];
    const uint32_t sb = smem_u32(smem);
    const int bh = blockIdx.y;
    const int b = bh >> 5;
    const int h = bh & (HQ_ - 1);
    const int kvh = h >> 2;
    const int q0 = blockIdx.x * QT;
    const int tid = threadIdx.x;
    const int lane = tid & 31;
    const int warp = tid >> 5;

    const __half* qh = Qh_g + (((size_t)b * HQ_ + h) * S_ + q0) * HD_;
    const __half* kh = Kh_g + ((size_t)b * HKV_ + kvh) * S_ * HD_;
    const __half* vh = Vh_g + ((size_t)b * HKV_ + kvh) * HD_ * S_;

    // stage Q
#pragma unroll
    for (int i = 0; i < 8; i++) {
        int lin = tid + i * 256;
        int r = lin >> 4, c = lin & 15;
        cp16(sb + r * QROW_B + c * 16, qh + (size_t)r * HD_ + c * 8);
    }
    cp_commit();

#define STAGE_KV(t_, buf_) do {                                               \
    int t0_ = (t_) * KT;                                                      \
    uint32_t kb_ = sb + OFF_K + (buf_) * KTILE_B;                             \
    uint32_t vb_ = sb + OFF_V + (buf_) * VTILE_B;                             \
    _Pragma("unroll")                                                         \
    for (int i_ = 0; i_ < 2; i_++) {                                          \
        int lin_ = tid + i_ * 256;                                            \
        int r_ = lin_ >> 4, c_ = lin_ & 15;                                   \
        cp16(kb_ + r_ * QROW_B + c_ * 16, kh + (size_t)(t0_ + r_) * HD_ + c_ * 8); \
        int d_ = lin_ >> 2, c2_ = lin_ & 3;                                   \
        cp16(vb_ + d_ * VROW_B + c2_ * 16, vh + (size_t)d_ * S_ + t0_ + c2_ * 8); \
    }                                                                         \
    cp_commit();                                                              \
} while (0)

    STAGE_KV(0, 0);
    STAGE_KV(1, 1);

    float o[16][4];
#pragma unroll
    for (int t = 0; t < 16; t++)
#pragma unroll
        for (int c = 0; c < 4; c++) o[t][c] = 0.f;
    float m0 = -1e30f, m1 = -1e30f, l0v = 0.f, l1v = 0.f;

    const float scale = 0.08838834764831845f;   // 1/sqrt(128)
    const uint32_t qrow_off = (warp * 16 + (lane & 15)) * QROW_B;
    const uint32_t kcol_off = (lane >> 4) * 16;

    const int T = S_ / KT;   // 64
    for (int t = 0; t < T; t++) {
        if (t + 1 < T) {
            asm volatile("cp.async.wait_group 1;" ::: "memory");
        } else {
            asm volatile("cp.async.wait_group 0;" ::: "memory");
        }
        __syncthreads();

        const int buf = t & 1;
        const uint32_t ukh = sb + OFF_K + buf * KTILE_B;
        const uint32_t uvh = sb + OFF_V + buf * VTILE_B;

        // ---- S = Q K^T ----
        float sc[4][4];
#pragma unroll
        for (int j = 0; j < 4; j++)
#pragma unroll
            for (int c = 0; c < 4; c++) sc[j][c] = 0.f;

#pragma unroll
        for (int ks = 0; ks < 8; ks++) {
            const uint32_t kb_off = ks * 32 + kcol_off;
            uint32_t qa[4];
            ldm_x4(sb + qrow_off + kb_off, qa[0], qa[1], qa[2], qa[3]);
#pragma unroll
            for (int np = 0; np < 2; np++) {
                uint32_t roff = (np * 16 + (lane & 15)) * QROW_B + kb_off;
                uint32_t r0, r1, r2, r3;
                ldm_x4(ukh + roff, r0, r1, r2, r3);
                mma_f16(sc[2*np][0], sc[2*np][1], sc[2*np][2], sc[2*np][3],
                        qa[0], qa[1], qa[2], qa[3], r0, r2);
                mma_f16(sc[2*np+1][0], sc[2*np+1][1], sc[2*np+1][2], sc[2*np+1][3],
                        qa[0], qa[1], qa[2], qa[3], r1, r3);
            }
        }

        // ---- online softmax ----
        float mx0 = -1e30f, mx1 = -1e30f;
#pragma unroll
        for (int j = 0; j < 4; j++) {
#pragma unroll
            for (int c = 0; c < 4; c++) sc[j][c] *= scale;
            mx0 = fmaxf(mx0, fmaxf(sc[j][0], sc[j][1]));
            mx1 = fmaxf(mx1, fmaxf(sc[j][2], sc[j][3]));
        }
        mx0 = fmaxf(mx0, __shfl_xor_sync(0xffffffffu, mx0, 1));
        mx0 = fmaxf(mx0, __shfl_xor_sync(0xffffffffu, mx0, 2));
        mx1 = fmaxf(mx1, __shfl_xor_sync(0xffffffffu, mx1, 1));
        mx1 = fmaxf(mx1, __shfl_xor_sync(0xffffffffu, mx1, 2));
        float mn0 = fmaxf(m0, mx0), mn1 = fmaxf(m1, mx1);
        float al0 = __expf(m0 - mn0), al1 = __expf(m1 - mn1);
        m0 = mn0; m1 = mn1;
        float rs0 = 0.f, rs1 = 0.f;
#pragma unroll
        for (int j = 0; j < 4; j++) {
            sc[j][0] = __expf(sc[j][0] - m0);
            sc[j][1] = __expf(sc[j][1] - m0);
            sc[j][2] = __expf(sc[j][2] - m1);
            sc[j][3] = __expf(sc[j][3] - m1);
            rs0 += sc[j][0] + sc[j][1];
            rs1 += sc[j][2] + sc[j][3];
        }
        rs0 += __shfl_xor_sync(0xffffffffu, rs0, 1);
        rs0 += __shfl_xor_sync(0xffffffffu, rs0, 2);
        rs1 += __shfl_xor_sync(0xffffffffu, rs1, 1);
        rs1 += __shfl_xor_sync(0xffffffffu, rs1, 2);
        l0v = l0v * al0 + rs0;
        l1v = l1v * al1 + rs1;
#pragma unroll
        for (int tt = 0; tt < 16; tt++) {
            o[tt][0] *= al0; o[tt][1] *= al0;
            o[tt][2] *= al1; o[tt][3] *= al1;
        }

        // ---- O += P V ----
#pragma unroll
        for (int kb = 0; kb < 2; kb++) {
            uint32_t ph0 = packh(sc[2*kb][0],   sc[2*kb][1]);
            uint32_t ph1 = packh(sc[2*kb][2],   sc[2*kb][3]);
            uint32_t ph2 = packh(sc[2*kb+1][0], sc[2*kb+1][1]);
            uint32_t ph3 = packh(sc[2*kb+1][2], sc[2*kb+1][3]);
            const uint32_t kb_off = kb * 32 + kcol_off;
#pragma unroll
            for (int np = 0; np < 8; np++) {
                uint32_t roff = (np * 16 + (lane & 15)) * VROW_B + kb_off;
                uint32_t r0, r1, r2, r3;
                ldm_x4(uvh + roff, r0, r1, r2, r3);
                mma_f16(o[2*np][0], o[2*np][1], o[2*np][2], o[2*np][3],
                        ph0, ph1, ph2, ph3, r0, r2);
                mma_f16(o[2*np+1][0], o[2*np+1][1], o[2*np+1][2], o[2*np+1][3],
                        ph0, ph1, ph2, ph3, r1, r3);
            }
        }

        __syncthreads();
        if (t + 2 < T) STAGE_KV(t + 2, buf);
    }
#undef STAGE_KV

    // epilogue: normalize, write fp16 [B,S,HQ,HD]
    float inv0 = 1.0f / l0v, inv1 = 1.0f / l1v;
    int s0 = q0 + warp * 16 + (lane >> 2);
    int s1 = s0 + 8;
    size_t base0 = (((size_t)b * S_ + s0) * HQ_ + h) * HD_ + 2 * (lane & 3);
    size_t base1 = (((size_t)b * S_ + s1) * HQ_ + h) * HD_ + 2 * (lane & 3);
#pragma unroll
    for (int t = 0; t < 16; t++) {
        *(__half2*)(Oh + base0 + 8 * t) =
            __floats2half2_rn(o[t][0] * inv0, o[t][1] * inv0);
        *(__half2*)(Oh + base1 + 8 * t) =
            __floats2half2_rn(o[t][2] * inv1, o[t][3] * inv1);
    }
}

// ---------------------------------------------------------------------------
extern "C" void kernel_launch(void* const* d_in, const int* in_sizes, int n_in,
                              void* d_out, int out_size)
{
    const float* x  = (const float*)d_in[0];
    const float* wq = (const float*)d_in[1];
    const float* wk = (const float*)d_in[2];
    const float* wv = (const float*)d_in[3];
    const float* wo = (const float*)d_in[4];
    const float* fc = (const float*)d_in[5];
    const float* fs = (const float*)d_in[6];
    float* out = (float*)d_out;

    __half *xh, *wqkvh, *woh, *qh, *kh, *vth, *ah;
    cudaGetSymbolAddress((void**)&xh, g_xh);
    cudaGetSymbolAddress((void**)&wqkvh, g_wqkvh);
    cudaGetSymbolAddress((void**)&woh, g_woh);
    cudaGetSymbolAddress((void**)&qh, g_qh);
    cudaGetSymbolAddress((void**)&kh, g_kh);
    cudaGetSymbolAddress((void**)&vth, g_vth);
    cudaGetSymbolAddress((void**)&ah, g_ah);

    const int M = B_ * S_;  // 4096

    // converts
    int n4x = (B_ * S_ * D_) / 4;
    conv_kernel<<<(n4x + 255) / 256, 256>>>(x, xh, n4x);
    int n4q = (HQ_ * HD_ * D_) / 4;
    conv_kernel<<<(n4q + 255) / 256, 256>>>(wq, wqkvh, n4q);
    int n4k = (HKV_ * HD_ * D_) / 4;
    size_t offk = (size_t)HQ_ * HD_ * D_;
    size_t offv = offk + (size_t)HKV_ * HD_ * D_;
    conv_kernel<<<(n4k + 255) / 256, 256>>>(wk, wqkvh + offk, n4k);
    conv_kernel<<<(n4k + 255) / 256, 256>>>(wv, wqkvh + offv, n4k);
    int n4o = (D_ * HQ_ * HD_) / 4;
    conv_kernel<<<(n4o + 255) / 256, 256>>>(wo, woh, n4o);

    cudaFuncSetAttribute(gemm_fp16, cudaFuncAttributeMaxDynamicSharedMemorySize, GSMEM);

    // fused QKV projection (rope + layout in epilogue)
    gemm_fp16<<<dim3(NQKV / 128, M / 128), 256, GSMEM>>>(
        xh, wqkvh, nullptr, qh, kh, vth, M, NQKV, D_, 3, fc, fs);

    // tensor-core attention
    cudaFuncSetAttribute(attn_mma4, cudaFuncAttributeMaxDynamicSharedMemorySize, ATT_SMEM);
    attn_mma4<<<dim3(S_ / QT, B_ * HQ_), 256, ATT_SMEM>>>(qh, kh, vth, ah);

    // output projection -> d_out (fp32)
    gemm_fp16<<<dim3(D_ / 128, M / 128), 256, GSMEM>>>(
        ah, woh, out, nullptr, nullptr, nullptr, M, D_, D_, 0, fc, fs);
}

// round 11
// speedup vs baseline: 6.9225x; 1.0197x over previous
#include <cuda_runtime.h>
#include <cuda_fp16.h>
#include <cstdint>
#include <math.h>

#define B_   2
#define S_   2048
#define D_   4096
#define HQ_  32
#define HKV_ 8
#define HD_  128

// ---------------- scratch (static device globals; no allocations) ----------
__device__ __half g_xh[(size_t)B_ * S_ * D_];                  // x fp16
#define NQKV (HQ_ * HD_ + 2 * HKV_ * HD_)   // 6144
__device__ __half g_wqkvh[(size_t)NQKV * D_];                  // stacked qkv weights
__device__ __half g_woh[(size_t)D_ * HQ_ * HD_];
// rope'd Q, K, transposed V (all fp16)
__device__ __half g_qh[(size_t)B_ * HQ_ * S_ * HD_];   // [B,HQ,S,HD]
__device__ __half g_kh[(size_t)B_ * HKV_ * S_ * HD_];  // [B,HKV,S,HD]
__device__ __half g_vth[(size_t)B_ * HKV_ * HD_ * S_]; // [B,HKV,HD,S]
// attention output (fp16, [B,S,HQ,HD])
__device__ __half g_ah[(size_t)B_ * S_ * HQ_ * HD_];

// ---------------- PTX helpers (family-portable only) -----------------------
__device__ __forceinline__ uint32_t smem_u32(const void* p) {
    uint32_t a;
    asm("{ .reg .u64 t; cvta.to.shared.u64 t, %1; cvt.u32.u64 %0, t; }" : "=r"(a) : "l"(p));
    return a;
}
__device__ __forceinline__ void cp16(uint32_t s, const void* g) {
    asm volatile("cp.async.cg.shared.global [%0], [%1], 16;" :: "r"(s), "l"(g));
}
__device__ __forceinline__ void cp_commit() {
    asm volatile("cp.async.commit_group;" ::: "memory");
}
__device__ __forceinline__ void ldm_x4(uint32_t a, uint32_t& r0, uint32_t& r1,
                                       uint32_t& r2, uint32_t& r3) {
    asm volatile("ldmatrix.sync.aligned.m8n8.x4.shared.b16 {%0,%1,%2,%3}, [%4];"
                 : "=r"(r0), "=r"(r1), "=r"(r2), "=r"(r3) : "r"(a));
}
__device__ __forceinline__ void mma_f16(float& d0, float& d1, float& d2, float& d3,
                                        uint32_t a0, uint32_t a1, uint32_t a2, uint32_t a3,
                                        uint32_t b0, uint32_t b1) {
    asm volatile("mma.sync.aligned.m16n8k16.row.col.f32.f16.f16.f32 "
                 "{%0,%1,%2,%3}, {%4,%5,%6,%7}, {%8,%9}, {%0,%1,%2,%3};"
                 : "+f"(d0), "+f"(d1), "+f"(d2), "+f"(d3)
                 : "r"(a0), "r"(a1), "r"(a2), "r"(a3), "r"(b0), "r"(b1));
}
__device__ __forceinline__ uint32_t packh(float lo, float hi) {
    __half2 t = __floats2half2_rn(lo, hi);
    return *(uint32_t*)&t;
}

// ---------------------------------------------------------------------------
// fp32 -> fp16
// ---------------------------------------------------------------------------
__global__ void conv_kernel(const float* __restrict__ in,
                            __half* __restrict__ hi, int n4)
{
    int i = blockIdx.x * blockDim.x + threadIdx.x;
    if (i >= n4) return;
    float4 v = ((const float4*)in)[i];
    __half2* hp = (__half2*)(hi + 4 * (size_t)i);
    hp[0] = __floats2half2_rn(v.x, v.y);
    hp[1] = __floats2half2_rn(v.z, v.w);
}

// ---------------------------------------------------------------------------
// fp16 GEMM (NT): C = A*B^T, fp32 accum via mma.sync.
// CTA 128x128, K-chunk 32, 8 warps, 2 CTAs/SM, 4-stage cp.async pipeline
// with ONE __syncthreads per iteration.
// modes: 0 = fp32 C; 3 = fused QKV epilogue (rope Q/K, V transposed).
// ---------------------------------------------------------------------------
#define RSTR   40
#define TILE_B (128 * RSTR * 2)     // 10240 B
#define STG_B  (2 * TILE_B)         // Ah, Bh  (20480 B)
#define NSTG   4
#define GSMEM  (NSTG * STG_B)       // 81920 B

__global__ __launch_bounds__(256, 2) void gemm_fp16(
    const __half* __restrict__ Ah, const __half* __restrict__ Bh,
    float* __restrict__ Cf,
    __half* __restrict__ Qh, __half* __restrict__ Kh, __half* __restrict__ Vh,
    int M, int N, int K, int mode,
    const float* __restrict__ fc, const float* __restrict__ fs)
{
    extern __shared__ char smem[];
    const uint32_t sb = smem_u32(smem);
    const int tid = threadIdx.x;
    const int lane = tid & 31;
    const int wid = tid >> 5;
    const int wm = wid >> 2;
    const int wn = wid & 3;
    const int bm = blockIdx.y * 128;
    const int bn = blockIdx.x * 128;

    float acc[4][4][4];
#pragma unroll
    for (int i = 0; i < 4; i++)
#pragma unroll
        for (int j = 0; j < 4; j++)
#pragma unroll
            for (int c = 0; c < 4; c++) acc[i][j][c] = 0.f;

    const int iters = K >> 5;
    const int row0 = tid >> 2;
    const int col0 = tid & 3;

    // Prefetch with dummy-commit tail: always commits exactly one group so
    // the pending-group count stays constant and wait_group(2) is exact.
#define PREFETCH(it_) do {                                                    \
    if ((it_) < iters) {                                                      \
        const uint32_t sob_ = sb + ((it_) & (NSTG - 1)) * STG_B;              \
        const int k0_ = (it_) << 5;                                           \
        _Pragma("unroll")                                                     \
        for (int j_ = 0; j_ < 2; j_++) {                                      \
            int row_ = row0 + j_ * 64;                                        \
            uint32_t so_ = sob_ + row_ * (RSTR * 2) + col0 * 16;              \
            size_t ga_ = (size_t)(bm + row_) * K + k0_ + col0 * 8;            \
            size_t gb_ = (size_t)(bn + row_) * K + k0_ + col0 * 8;            \
            cp16(so_ + 0 * TILE_B, Ah + ga_);                                 \
            cp16(so_ + 1 * TILE_B, Bh + gb_);                                 \
        }                                                                     \
    }                                                                         \
    cp_commit();                                                              \
} while (0)

    PREFETCH(0);
    PREFETCH(1);
    PREFETCH(2);

    for (int it = 0; it < iters; it++) {
        asm volatile("cp.async.wait_group 2;" ::: "memory");
        __syncthreads();
        PREFETCH(it + 3);   // writes buffer (it-1)%4 — safe after the barrier

        const uint32_t base = sb + (it & (NSTG - 1)) * STG_B;
        const uint32_t a_h = base;
        const uint32_t b_h = base + TILE_B;

#pragma unroll
        for (int kk = 0; kk < 2; kk++) {
            const int kc = kk * 16 + (lane >> 4) * 8;
            uint32_t a[4][4], bhf[4][2];
#pragma unroll
            for (int nq = 0; nq < 2; nq++) {
                int row = wn * 32 + nq * 16 + (lane & 15);
                uint32_t off = row * (RSTR * 2) + kc * 2;
                uint32_t r0, r1, r2, r3;
                ldm_x4(b_h + off, r0, r1, r2, r3);
                bhf[nq * 2][0] = r0; bhf[nq * 2][1] = r2;
                bhf[nq * 2 + 1][0] = r1; bhf[nq * 2 + 1][1] = r3;
            }
#pragma unroll
            for (int mf = 0; mf < 4; mf++) {
                int row = wm * 64 + mf * 16 + (lane & 15);
                ldm_x4(a_h + row * (RSTR * 2) + kc * 2,
                       a[mf][0], a[mf][1], a[mf][2], a[mf][3]);
            }
#pragma unroll
            for (int mf = 0; mf < 4; mf++)
#pragma unroll
                for (int nf = 0; nf < 4; nf++)
                    mma_f16(acc[mf][nf][0], acc[mf][nf][1], acc[mf][nf][2], acc[mf][nf][3],
                            a[mf][0], a[mf][1], a[mf][2], a[mf][3],
                            bhf[nf][0], bhf[nf][1]);
        }
    }
#undef PREFETCH

    const int qr = lane >> 2;
    const int qc = lane & 3;
#pragma unroll
    for (int mf = 0; mf < 4; mf++) {
#pragma unroll
        for (int half_ = 0; half_ < 2; half_++) {
            int m = bm + wm * 64 + mf * 16 + qr + half_ * 8;
            if (mode == 0) {
                float* dst = Cf + (size_t)m * N + bn;
#pragma unroll
                for (int nf = 0; nf < 4; nf++) {
                    int n = wn * 32 + nf * 8 + 2 * qc;
                    float2 w = half_ ? make_float2(acc[mf][nf][2], acc[mf][nf][3])
                                     : make_float2(acc[mf][nf][0], acc[mf][nf][1]);
                    *(float2*)(dst + n) = w;
                }
            } else {
                int b = m >> 11;
                int s = m & (S_ - 1);
#pragma unroll
                for (int nf = 0; nf < 4; nf++) {
                    int n = bn + wn * 32 + nf * 8 + 2 * qc;
                    float2 w = half_ ? make_float2(acc[mf][nf][2], acc[mf][nf][3])
                                     : make_float2(acc[mf][nf][0], acc[mf][nf][1]);
                    if (n < HQ_ * HD_) {                    // Q: rope
                        int h = n >> 7;
                        int d = n & (HD_ - 1);
                        int i = d >> 1;
                        float c = fc[s * (HD_ / 2) + i];
                        float sn = fs[s * (HD_ / 2) + i];
                        float x0 = w.x * c - w.y * sn;
                        float x1 = w.x * sn + w.y * c;
                        size_t off = (((size_t)b * HQ_ + h) * S_ + s) * HD_ + d;
                        *(__half2*)(Qh + off) = __floats2half2_rn(x0, x1);
                    } else if (n < HQ_ * HD_ + HKV_ * HD_) { // K: rope
                        int nk = n - HQ_ * HD_;
                        int h = nk >> 7;
                        int d = nk & (HD_ - 1);
                        int i = d >> 1;
                        float c = fc[s * (HD_ / 2) + i];
                        float sn = fs[s * (HD_ / 2) + i];
                        float x0 = w.x * c - w.y * sn;
                        float x1 = w.x * sn + w.y * c;
                        size_t off = (((size_t)b * HKV_ + h) * S_ + s) * HD_ + d;
                        *(__half2*)(Kh + off) = __floats2half2_rn(x0, x1);
                    } else {                                 // V: transposed
                        int nv = n - (HQ_ * HD_ + HKV_ * HD_);
                        int h = nv >> 7;
                        int d = nv & (HD_ - 1);
                        size_t off = (((size_t)b * HKV_ + h) * HD_ + d) * S_ + s;
                        Vh[off] = __float2half_rn(w.x);
                        Vh[off + S_] = __float2half_rn(w.y);
                    }
                }
            }
        }
    }
}

// ---------------------------------------------------------------------------
// Tensor-core flash attention (fp16 operands, fp32 accum).
// Grid (S/128, B*HQ), block 256 (8 warps), 2 CTAs/SM.
// KT=32, 4-stage KV pipeline, ONE __syncthreads per iteration.
// smem = 34816 + 4*18944 = 110592 B.
// ---------------------------------------------------------------------------
#define QT 128
#define KT 32
#define QROW_B 272                 // 128 halves + 8 pad
#define VROW_B 80                  // 32 halves + 8 pad
#define QTILE_B (QT * QROW_B)      // 34816
#define KTILE_B (KT * QROW_B)      // 8704
#define VTILE_B (128 * VROW_B)     // 10240
#define KVSTG_B (KTILE_B + VTILE_B)           // 18944
#define OFF_KV  QTILE_B                       // 34816
#define ATT_SMEM (OFF_KV + 4 * KVSTG_B)       // 110592

__global__ __launch_bounds__(256, 2) void attn_mma4(
    const __half* __restrict__ Qh_g,
    const __half* __restrict__ Kh_g,
    const __half* __restrict__ Vh_g,
    __half* __restrict__ Oh)
{
    extern __shared__ char smem[];
    const uint32_t sb = smem_u32(smem);
    const int bh = blockIdx.y;
    const int b = bh >> 5;
    const int h = bh & (HQ_ - 1);
    const int kvh = h >> 2;
    const int q0 = blockIdx.x * QT;
    const int tid = threadIdx.x;
    const int lane = tid & 31;
    const int warp = tid >> 5;

    const __half* qh = Qh_g + (((size_t)b * HQ_ + h) * S_ + q0) * HD_;
    const __half* kh = Kh_g + ((size_t)b * HKV_ + kvh) * S_ * HD_;
    const __half* vh = Vh_g + ((size_t)b * HKV_ + kvh) * HD_ * S_;

    const int T = S_ / KT;   // 64

    // stage Q (its own commit group — retires before KV group 0)
#pragma unroll
    for (int i = 0; i < 8; i++) {
        int lin = tid + i * 256;
        int r = lin >> 4, c = lin & 15;
        cp16(sb + r * QROW_B + c * 16, qh + (size_t)r * HD_ + c * 8);
    }
    cp_commit();

#define STAGE_KV(t_) do {                                                     \
    if ((t_) < T) {                                                           \
        int t0_ = (t_) * KT;                                                  \
        uint32_t kb_ = sb + OFF_KV + ((t_) & 3) * KVSTG_B;                    \
        uint32_t vb_ = kb_ + KTILE_B;                                         \
        _Pragma("unroll")                                                     \
        for (int i_ = 0; i_ < 2; i_++) {                                      \
            int lin_ = tid + i_ * 256;                                        \
            int r_ = lin_ >> 4, c_ = lin_ & 15;                               \
            cp16(kb_ + r_ * QROW_B + c_ * 16, kh + (size_t)(t0_ + r_) * HD_ + c_ * 8); \
            int d_ = lin_ >> 2, c2_ = lin_ & 3;                               \
            cp16(vb_ + d_ * VROW_B + c2_ * 16, vh + (size_t)d_ * S_ + t0_ + c2_ * 8); \
        }                                                                     \
    }                                                                         \
    cp_commit();                                                              \
} while (0)

    STAGE_KV(0);
    STAGE_KV(1);
    STAGE_KV(2);

    float o[16][4];
#pragma unroll
    for (int t = 0; t < 16; t++)
#pragma unroll
        for (int c = 0; c < 4; c++) o[t][c] = 0.f;
    float m0 = -1e30f, m1 = -1e30f, l0v = 0.f, l1v = 0.f;

    const float scale = 0.08838834764831845f;   // 1/sqrt(128)
    const uint32_t qrow_off = (warp * 16 + (lane & 15)) * QROW_B;
    const uint32_t kcol_off = (lane >> 4) * 16;

    for (int t = 0; t < T; t++) {
        asm volatile("cp.async.wait_group 2;" ::: "memory");
        __syncthreads();
        STAGE_KV(t + 3);   // writes buffer (t-1)&3 — safe after the barrier

        const uint32_t ukh = sb + OFF_KV + (t & 3) * KVSTG_B;
        const uint32_t uvh = ukh + KTILE_B;

        // ---- S = Q K^T ----
        float sc[4][4];
#pragma unroll
        for (int j = 0; j < 4; j++)
#pragma unroll
            for (int c = 0; c < 4; c++) sc[j][c] = 0.f;

#pragma unroll
        for (int ks = 0; ks < 8; ks++) {
            const uint32_t kb_off = ks * 32 + kcol_off;
            uint32_t qa[4];
            ldm_x4(sb + qrow_off + kb_off, qa[0], qa[1], qa[2], qa[3]);
#pragma unroll
            for (int np = 0; np < 2; np++) {
                uint32_t roff = (np * 16 + (lane & 15)) * QROW_B + kb_off;
                uint32_t r0, r1, r2, r3;
                ldm_x4(ukh + roff, r0, r1, r2, r3);
                mma_f16(sc[2*np][0], sc[2*np][1], sc[2*np][2], sc[2*np][3],
                        qa[0], qa[1], qa[2], qa[3], r0, r2);
                mma_f16(sc[2*np+1][0], sc[2*np+1][1], sc[2*np+1][2], sc[2*np+1][3],
                        qa[0], qa[1], qa[2], qa[3], r1, r3);
            }
        }

        // ---- online softmax ----
        float mx0 = -1e30f, mx1 = -1e30f;
#pragma unroll
        for (int j = 0; j < 4; j++) {
#pragma unroll
            for (int c = 0; c < 4; c++) sc[j][c] *= scale;
            mx0 = fmaxf(mx0, fmaxf(sc[j][0], sc[j][1]));
            mx1 = fmaxf(mx1, fmaxf(sc[j][2], sc[j][3]));
        }
        mx0 = fmaxf(mx0, __shfl_xor_sync(0xffffffffu, mx0, 1));
        mx0 = fmaxf(mx0, __shfl_xor_sync(0xffffffffu, mx0, 2));
        mx1 = fmaxf(mx1, __shfl_xor_sync(0xffffffffu, mx1, 1));
        mx1 = fmaxf(mx1, __shfl_xor_sync(0xffffffffu, mx1, 2));
        float mn0 = fmaxf(m0, mx0), mn1 = fmaxf(m1, mx1);
        float al0 = __expf(m0 - mn0), al1 = __expf(m1 - mn1);
        m0 = mn0; m1 = mn1;
        float rs0 = 0.f, rs1 = 0.f;
#pragma unroll
        for (int j = 0; j < 4; j++) {
            sc[j][0] = __expf(sc[j][0] - m0);
            sc[j][1] = __expf(sc[j][1] - m0);
            sc[j][2] = __expf(sc[j][2] - m1);
            sc[j][3] = __expf(sc[j][3] - m1);
            rs0 += sc[j][0] + sc[j][1];
            rs1 += sc[j][2] + sc[j][3];
        }
        rs0 += __shfl_xor_sync(0xffffffffu, rs0, 1);
        rs0 += __shfl_xor_sync(0xffffffffu, rs0, 2);
        rs1 += __shfl_xor_sync(0xffffffffu, rs1, 1);
        rs1 += __shfl_xor_sync(0xffffffffu, rs1, 2);
        l0v = l0v * al0 + rs0;
        l1v = l1v * al1 + rs1;
#pragma unroll
        for (int tt = 0; tt < 16; tt++) {
            o[tt][0] *= al0; o[tt][1] *= al0;
            o[tt][2] *= al1; o[tt][3] *= al1;
        }

        // ---- O += P V ----
#pragma unroll
        for (int kb = 0; kb < 2; kb++) {
            uint32_t ph0 = packh(sc[2*kb][0],   sc[2*kb][1]);
            uint32_t ph1 = packh(sc[2*kb][2],   sc[2*kb][3]);
            uint32_t ph2 = packh(sc[2*kb+1][0], sc[2*kb+1][1]);
            uint32_t ph3 = packh(sc[2*kb+1][2], sc[2*kb+1][3]);
            const uint32_t kb_off = kb * 32 + kcol_off;
#pragma unroll
            for (int np = 0; np < 8; np++) {
                uint32_t roff = (np * 16 + (lane & 15)) * VROW_B + kb_off;
                uint32_t r0, r1, r2, r3;
                ldm_x4(uvh + roff, r0, r1, r2, r3);
                mma_f16(o[2*np][0], o[2*np][1], o[2*np][2], o[2*np][3],
                        ph0, ph1, ph2, ph3, r0, r2);
                mma_f16(o[2*np+1][0], o[2*np+1][1], o[2*np+1][2], o[2*np+1][3],
                        ph0, ph1, ph2, ph3, r1, r3);
            }
        }
    }
#undef STAGE_KV

    // epilogue: normalize, write fp16 [B,S,HQ,HD]
    float inv0 = 1.0f / l0v, inv1 = 1.0f / l1v;
    int s0 = q0 + warp * 16 + (lane >> 2);
    int s1 = s0 + 8;
    size_t base0 = (((size_t)b * S_ + s0) * HQ_ + h) * HD_ + 2 * (lane & 3);
    size_t base1 = (((size_t)b * S_ + s1) * HQ_ + h) * HD_ + 2 * (lane & 3);
#pragma unroll
    for (int t = 0; t < 16; t++) {
        *(__half2*)(Oh + base0 + 8 * t) =
            __floats2half2_rn(o[t][0] * inv0, o[t][1] * inv0);
        *(__half2*)(Oh + base1 + 8 * t) =
            __floats2half2_rn(o[t][2] * inv1, o[t][3] * inv1);
    }
}

// ---------------------------------------------------------------------------
extern "C" void kernel_launch(void* const* d_in, const int* in_sizes, int n_in,
                              void* d_out, int out_size)
{
    const float* x  = (const float*)d_in[0];
    const float* wq = (const float*)d_in[1];
    const float* wk = (const float*)d_in[2];
    const float* wv = (const float*)d_in[3];
    const float* wo = (const float*)d_in[4];
    const float* fc = (const float*)d_in[5];
    const float* fs = (const float*)d_in[6];
    float* out = (float*)d_out;

    __half *xh, *wqkvh, *woh, *qh, *kh, *vth, *ah;
    cudaGetSymbolAddress((void**)&xh, g_xh);
    cudaGetSymbolAddress((void**)&wqkvh, g_wqkvh);
    cudaGetSymbolAddress((void**)&woh, g_woh);
    cudaGetSymbolAddress((void**)&qh, g_qh);
    cudaGetSymbolAddress((void**)&kh, g_kh);
    cudaGetSymbolAddress((void**)&vth, g_vth);
    cudaGetSymbolAddress((void**)&ah, g_ah);

    const int M = B_ * S_;  // 4096

    // converts
    int n4x = (B_ * S_ * D_) / 4;
    conv_kernel<<<(n4x + 255) / 256, 256>>>(x, xh, n4x);
    int n4q = (HQ_ * HD_ * D_) / 4;
    conv_kernel<<<(n4q + 255) / 256, 256>>>(wq, wqkvh, n4q);
    int n4k = (HKV_ * HD_ * D_) / 4;
    size_t offk = (size_t)HQ_ * HD_ * D_;
    size_t offv = offk + (size_t)HKV_ * HD_ * D_;
    conv_kernel<<<(n4k + 255) / 256, 256>>>(wk, wqkvh + offk, n4k);
    conv_kernel<<<(n4k + 255) / 256, 256>>>(wv, wqkvh + offv, n4k);
    int n4o = (D_ * HQ_ * HD_) / 4;
    conv_kernel<<<(n4o + 255) / 256, 256>>>(wo, woh, n4o);

    cudaFuncSetAttribute(gemm_fp16, cudaFuncAttributeMaxDynamicSharedMemorySize, GSMEM);

    // fused QKV projection (rope + layout in epilogue)
    gemm_fp16<<<dim3(NQKV / 128, M / 128), 256, GSMEM>>>(
        xh, wqkvh, nullptr, qh, kh, vth, M, NQKV, D_, 3, fc, fs);

    // tensor-core attention
    cudaFuncSetAttribute(attn_mma4, cudaFuncAttributeMaxDynamicSharedMemorySize, ATT_SMEM);
    attn_mma4<<<dim3(S_ / QT, B_ * HQ_), 256, ATT_SMEM>>>(qh, kh, vth, ah);

    // output projection -> d_out (fp32)
    gemm_fp16<<<dim3(D_ / 128, M / 128), 256, GSMEM>>>(
        ah, woh, out, nullptr, nullptr, nullptr, M, D_, D_, 0, fc, fs);
}

// round 12
// speedup vs baseline: 6.9579x; 1.0051x over previous
#include <cuda_runtime.h>
#include <cuda_fp16.h>
#include <cstdint>
#include <math.h>

#define B_   2
#define S_   2048
#define D_   4096
#define HQ_  32
#define HKV_ 8
#define HD_  128

// ---------------- scratch (static device globals; no allocations) ----------
__device__ __half g_xh[(size_t)B_ * S_ * D_];                  // x fp16
#define NQKV (HQ_ * HD_ + 2 * HKV_ * HD_)   // 6144
__device__ __half g_wqkvh[(size_t)NQKV * D_];                  // stacked qkv weights
__device__ __half g_woh[(size_t)D_ * HQ_ * HD_];
// rope'd Q, K, transposed V (all fp16)
__device__ __half g_qh[(size_t)B_ * HQ_ * S_ * HD_];   // [B,HQ,S,HD]
__device__ __half g_kh[(size_t)B_ * HKV_ * S_ * HD_];  // [B,HKV,S,HD]
__device__ __half g_vth[(size_t)B_ * HKV_ * HD_ * S_]; // [B,HKV,HD,S]
// attention output (fp16, [B,S,HQ,HD])
__device__ __half g_ah[(size_t)B_ * S_ * HQ_ * HD_];

// ---------------- PTX helpers (family-portable only) -----------------------
__device__ __forceinline__ uint32_t smem_u32(const void* p) {
    uint32_t a;
    asm("{ .reg .u64 t; cvta.to.shared.u64 t, %1; cvt.u32.u64 %0, t; }" : "=r"(a) : "l"(p));
    return a;
}
__device__ __forceinline__ void cp16(uint32_t s, const void* g) {
    asm volatile("cp.async.cg.shared.global [%0], [%1], 16;" :: "r"(s), "l"(g));
}
__device__ __forceinline__ void cp_commit() {
    asm volatile("cp.async.commit_group;" ::: "memory");
}
__device__ __forceinline__ void ldm_x4(uint32_t a, uint32_t& r0, uint32_t& r1,
                                       uint32_t& r2, uint32_t& r3) {
    asm volatile("ldmatrix.sync.aligned.m8n8.x4.shared.b16 {%0,%1,%2,%3}, [%4];"
                 : "=r"(r0), "=r"(r1), "=r"(r2), "=r"(r3) : "r"(a));
}
__device__ __forceinline__ void mma_f16(float& d0, float& d1, float& d2, float& d3,
                                        uint32_t a0, uint32_t a1, uint32_t a2, uint32_t a3,
                                        uint32_t b0, uint32_t b1) {
    asm volatile("mma.sync.aligned.m16n8k16.row.col.f32.f16.f16.f32 "
                 "{%0,%1,%2,%3}, {%4,%5,%6,%7}, {%8,%9}, {%0,%1,%2,%3};"
                 : "+f"(d0), "+f"(d1), "+f"(d2), "+f"(d3)
                 : "r"(a0), "r"(a1), "r"(a2), "r"(a3), "r"(b0), "r"(b1));
}
__device__ __forceinline__ uint32_t packh(float lo, float hi) {
    __half2 t = __floats2half2_rn(lo, hi);
    return *(uint32_t*)&t;
}

// ---------------------------------------------------------------------------
// merged fp32 -> fp16 convert: one launch for x, wq, wk, wv, wo.
// Each block handles 512 float4 chunks (256 threads x 2), block-aligned ranges.
// f4 range sizes: x 4194304 | wq 4194304 | wk 1048576 | wv 1048576 | wo 4194304
// ---------------------------------------------------------------------------
#define N4X 4194304L
#define N4Q 4194304L
#define N4K 1048576L
#define N4O 4194304L
#define CONV_BLOCKS ((N4X + N4Q + 2 * N4K + N4O) / 512)   // 28672

__global__ void conv_all(const float* __restrict__ x,  const float* __restrict__ wq,
                         const float* __restrict__ wk, const float* __restrict__ wv,
                         const float* __restrict__ wo,
                         __half* __restrict__ xh, __half* __restrict__ wqkvh,
                         __half* __restrict__ woh)
{
    long base = (long)blockIdx.x * 512;
    const float* src;
    __half* dst;
    long off;
    if (base < N4X) {
        src = x; dst = xh; off = base;
    } else if (base < N4X + N4Q) {
        src = wq; dst = wqkvh; off = base - N4X;
    } else if (base < N4X + N4Q + N4K) {
        src = wk; dst = wqkvh + (size_t)HQ_ * HD_ * D_; off = base - (N4X + N4Q);
    } else if (base < N4X + N4Q + 2 * N4K) {
        src = wv; dst = wqkvh + (size_t)(HQ_ + HKV_) * HD_ * D_;
        off = base - (N4X + N4Q + N4K);
    } else {
        src = wo; dst = woh; off = base - (N4X + N4Q + 2 * N4K);
    }
    long i0 = off + threadIdx.x;
    long i1 = i0 + 256;
    float4 v0 = ((const float4*)src)[i0];
    float4 v1 = ((const float4*)src)[i1];
    __half2* p0 = (__half2*)(dst + 4 * i0);
    __half2* p1 = (__half2*)(dst + 4 * i1);
    p0[0] = __floats2half2_rn(v0.x, v0.y);
    p0[1] = __floats2half2_rn(v0.z, v0.w);
    p1[0] = __floats2half2_rn(v1.x, v1.y);
    p1[1] = __floats2half2_rn(v1.z, v1.w);
}

// ---------------------------------------------------------------------------
// fp16 GEMM (NT): C = A*B^T, fp32 accum via mma.sync.
// CTA 128x128, K-chunk 32, 8 warps, 2 CTAs/SM, 4-stage cp.async pipeline,
// one __syncthreads per iteration.
// modes: 0 = fp32 C; 3 = fused QKV epilogue (rope Q/K, V transposed w/
//        smem-transpose coalesced stores).
// ---------------------------------------------------------------------------
#define RSTR   40
#define TILE_B (128 * RSTR * 2)     // 10240 B
#define STG_B  (2 * TILE_B)         // Ah, Bh  (20480 B)
#define NSTG   4
#define GSMEM  (NSTG * STG_B)       // 81920 B
#define VTP    136                  // padded m-stride for V transpose tile

__global__ __launch_bounds__(256, 2) void gemm_fp16(
    const __half* __restrict__ Ah, const __half* __restrict__ Bh,
    float* __restrict__ Cf,
    __half* __restrict__ Qh, __half* __restrict__ Kh, __half* __restrict__ Vh,
    int M, int N, int K, int mode,
    const float* __restrict__ fc, const float* __restrict__ fs)
{
    extern __shared__ char smem[];
    const uint32_t sb = smem_u32(smem);
    const int tid = threadIdx.x;
    const int lane = tid & 31;
    const int wid = tid >> 5;
    const int wm = wid >> 2;
    const int wn = wid & 3;
    const int bm = blockIdx.y * 128;
    const int bn = blockIdx.x * 128;

    float acc[4][4][4];
#pragma unroll
    for (int i = 0; i < 4; i++)
#pragma unroll
        for (int j = 0; j < 4; j++)
#pragma unroll
            for (int c = 0; c < 4; c++) acc[i][j][c] = 0.f;

    const int iters = K >> 5;
    const int row0 = tid >> 2;
    const int col0 = tid & 3;

#define PREFETCH(it_) do {                                                    \
    if ((it_) < iters) {                                                      \
        const uint32_t sob_ = sb + ((it_) & (NSTG - 1)) * STG_B;              \
        const int k0_ = (it_) << 5;                                           \
        _Pragma("unroll")                                                     \
        for (int j_ = 0; j_ < 2; j_++) {                                      \
            int row_ = row0 + j_ * 64;                                        \
            uint32_t so_ = sob_ + row_ * (RSTR * 2) + col0 * 16;              \
            size_t ga_ = (size_t)(bm + row_) * K + k0_ + col0 * 8;            \
            size_t gb_ = (size_t)(bn + row_) * K + k0_ + col0 * 8;            \
            cp16(so_ + 0 * TILE_B, Ah + ga_);                                 \
            cp16(so_ + 1 * TILE_B, Bh + gb_);                                 \
        }                                                                     \
    }                                                                         \
    cp_commit();                                                              \
} while (0)

    PREFETCH(0);
    PREFETCH(1);
    PREFETCH(2);

    for (int it = 0; it < iters; it++) {
        asm volatile("cp.async.wait_group 2;" ::: "memory");
        __syncthreads();
        PREFETCH(it + 3);   // writes buffer (it-1)%4 — safe after the barrier

        const uint32_t base = sb + (it & (NSTG - 1)) * STG_B;
        const uint32_t a_h = base;
        const uint32_t b_h = base + TILE_B;

#pragma unroll
        for (int kk = 0; kk < 2; kk++) {
            const int kc = kk * 16 + (lane >> 4) * 8;
            uint32_t a[4][4], bhf[4][2];
#pragma unroll
            for (int nq = 0; nq < 2; nq++) {
                int row = wn * 32 + nq * 16 + (lane & 15);
                uint32_t off = row * (RSTR * 2) + kc * 2;
                uint32_t r0, r1, r2, r3;
                ldm_x4(b_h + off, r0, r1, r2, r3);
                bhf[nq * 2][0] = r0; bhf[nq * 2][1] = r2;
                bhf[nq * 2 + 1][0] = r1; bhf[nq * 2 + 1][1] = r3;
            }
#pragma unroll
            for (int mf = 0; mf < 4; mf++) {
                int row = wm * 64 + mf * 16 + (lane & 15);
                ldm_x4(a_h + row * (RSTR * 2) + kc * 2,
                       a[mf][0], a[mf][1], a[mf][2], a[mf][3]);
            }
#pragma unroll
            for (int mf = 0; mf < 4; mf++)
#pragma unroll
                for (int nf = 0; nf < 4; nf++)
                    mma_f16(acc[mf][nf][0], acc[mf][nf][1], acc[mf][nf][2], acc[mf][nf][3],
                            a[mf][0], a[mf][1], a[mf][2], a[mf][3],
                            bhf[nf][0], bhf[nf][1]);
        }
    }
#undef PREFETCH

    const int qr = lane >> 2;
    const int qc = lane & 3;

    // ---- V tile: smem transpose then coalesced stores along S ----
    if (mode == 3 && bn >= HQ_ * HD_ + HKV_ * HD_) {
        __syncthreads();                        // smem stage buffers now free
        __half* T = (__half*)smem;              // T[n_local (128)][VTP]
#pragma unroll
        for (int mf = 0; mf < 4; mf++)
#pragma unroll
            for (int half_ = 0; half_ < 2; half_++) {
                int ml = wm * 64 + mf * 16 + qr + half_ * 8;
#pragma unroll
                for (int nf = 0; nf < 4; nf++) {
                    int nl = wn * 32 + nf * 8 + 2 * qc;
                    float2 w = half_ ? make_float2(acc[mf][nf][2], acc[mf][nf][3])
                                     : make_float2(acc[mf][nf][0], acc[mf][nf][1]);
                    T[nl * VTP + ml] = __float2half_rn(w.x);
                    T[(nl + 1) * VTP + ml] = __float2half_rn(w.y);
                }
            }
        __syncthreads();
        int nv0 = bn - (HQ_ * HD_ + HKV_ * HD_);
        int h = nv0 >> 7;
        int b = bm >> 11;
        int s0 = bm & (S_ - 1);
        int r = tid >> 1;                       // d (n_local) 0..127
        int cpart = (tid & 1) * 64;             // half-row of 64 halves
        __half* dst = Vh + (((size_t)b * HKV_ + h) * HD_ + r) * S_ + s0 + cpart;
        const uint4* srcp = (const uint4*)(T + r * VTP + cpart);
#pragma unroll
        for (int u = 0; u < 8; u++)
            ((uint4*)dst)[u] = srcp[u];
        return;
    }

#pragma unroll
    for (int mf = 0; mf < 4; mf++) {
#pragma unroll
        for (int half_ = 0; half_ < 2; half_++) {
            int m = bm + wm * 64 + mf * 16 + qr + half_ * 8;
            if (mode == 0) {
                float* dst = Cf + (size_t)m * N + bn;
#pragma unroll
                for (int nf = 0; nf < 4; nf++) {
                    int n = wn * 32 + nf * 8 + 2 * qc;
                    float2 w = half_ ? make_float2(acc[mf][nf][2], acc[mf][nf][3])
                                     : make_float2(acc[mf][nf][0], acc[mf][nf][1]);
                    *(float2*)(dst + n) = w;
                }
            } else {
                int b = m >> 11;
                int s = m & (S_ - 1);
#pragma unroll
                for (int nf = 0; nf < 4; nf++) {
                    int n = bn + wn * 32 + nf * 8 + 2 * qc;
                    float2 w = half_ ? make_float2(acc[mf][nf][2], acc[mf][nf][3])
                                     : make_float2(acc[mf][nf][0], acc[mf][nf][1]);
                    if (n < HQ_ * HD_) {                    // Q: rope
                        int h = n >> 7;
                        int d = n & (HD_ - 1);
                        int i = d >> 1;
                        float c = fc[s * (HD_ / 2) + i];
                        float sn = fs[s * (HD_ / 2) + i];
                        float x0 = w.x * c - w.y * sn;
                        float x1 = w.x * sn + w.y * c;
                        size_t off = (((size_t)b * HQ_ + h) * S_ + s) * HD_ + d;
                        *(__half2*)(Qh + off) = __floats2half2_rn(x0, x1);
                    } else {                                 // K: rope
                        int nk = n - HQ_ * HD_;
                        int h = nk >> 7;
                        int d = nk & (HD_ - 1);
                        int i = d >> 1;
                        float c = fc[s * (HD_ / 2) + i];
                        float sn = fs[s * (HD_ / 2) + i];
                        float x0 = w.x * c - w.y * sn;
                        float x1 = w.x * sn + w.y * c;
                        size_t off = (((size_t)b * HKV_ + h) * S_ + s) * HD_ + d;
                        *(__half2*)(Kh + off) = __floats2half2_rn(x0, x1);
                    }
                }
            }
        }
    }
}

// ---------------------------------------------------------------------------
// Tensor-core flash attention (fp16 operands, fp32 accum).
// Grid (S/128, B*HQ), block 256 (8 warps), 2 CTAs/SM.
// KT=32, 4-stage KV pipeline, ONE __syncthreads per iteration.
// smem = 34816 + 4*18944 = 110592 B.
// ---------------------------------------------------------------------------
#define QT 128
#define KT 32
#define QROW_B 272                 // 128 halves + 8 pad
#define VROW_B 80                  // 32 halves + 8 pad
#define QTILE_B (QT * QROW_B)      // 34816
#define KTILE_B (KT * QROW_B)      // 8704
#define VTILE_B (128 * VROW_B)     // 10240
#define KVSTG_B (KTILE_B + VTILE_B)           // 18944
#define OFF_KV  QTILE_B                       // 34816
#define ATT_SMEM (OFF_KV + 4 * KVSTG_B)       // 110592

__global__ __launch_bounds__(256, 2) void attn_mma4(
    const __half* __restrict__ Qh_g,
    const __half* __restrict__ Kh_g,
    const __half* __restrict__ Vh_g,
    __half* __restrict__ Oh)
{
    extern __shared__ char smem[];
    const uint32_t sb = smem_u32(smem);
    const int bh = blockIdx.y;
    const int b = bh >> 5;
    const int h = bh & (HQ_ - 1);
    const int kvh = h >> 2;
    const int q0 = blockIdx.x * QT;
    const int tid = threadIdx.x;
    const int lane = tid & 31;
    const int warp = tid >> 5;

    const __half* qh = Qh_g + (((size_t)b * HQ_ + h) * S_ + q0) * HD_;
    const __half* kh = Kh_g + ((size_t)b * HKV_ + kvh) * S_ * HD_;
    const __half* vh = Vh_g + ((size_t)b * HKV_ + kvh) * HD_ * S_;

    const int T = S_ / KT;   // 64

    // stage Q (its own commit group — retires before KV group 0)
#pragma unroll
    for (int i = 0; i < 8; i++) {
        int lin = tid + i * 256;
        int r = lin >> 4, c = lin & 15;
        cp16(sb + r * QROW_B + c * 16, qh + (size_t)r * HD_ + c * 8);
    }
    cp_commit();

#define STAGE_KV(t_) do {                                                     \
    if ((t_) < T) {                                                           \
        int t0_ = (t_) * KT;                                                  \
        uint32_t kb_ = sb + OFF_KV + ((t_) & 3) * KVSTG_B;                    \
        uint32_t vb_ = kb_ + KTILE_B;                                         \
        _Pragma("unroll")                                                     \
        for (int i_ = 0; i_ < 2; i_++) {                                      \
            int lin_ = tid + i_ * 256;                                        \
            int r_ = lin_ >> 4, c_ = lin_ & 15;                               \
            cp16(kb_ + r_ * QROW_B + c_ * 16, kh + (size_t)(t0_ + r_) * HD_ + c_ * 8); \
            int d_ = lin_ >> 2, c2_ = lin_ & 3;                               \
            cp16(vb_ + d_ * VROW_B + c2_ * 16, vh + (size_t)d_ * S_ + t0_ + c2_ * 8); \
        }                                                                     \
    }                                                                         \
    cp_commit();                                                              \
} while (0)

    STAGE_KV(0);
    STAGE_KV(1);
    STAGE_KV(2);

    float o[16][4];
#pragma unroll
    for (int t = 0; t < 16; t++)
#pragma unroll
        for (int c = 0; c < 4; c++) o[t][c] = 0.f;
    float m0 = -1e30f, m1 = -1e30f, l0v = 0.f, l1v = 0.f;

    const float scale = 0.08838834764831845f;   // 1/sqrt(128)
    const uint32_t qrow_off = (warp * 16 + (lane & 15)) * QROW_B;
    const uint32_t kcol_off = (lane >> 4) * 16;

    for (int t = 0; t < T; t++) {
        asm volatile("cp.async.wait_group 2;" ::: "memory");
        __syncthreads();
        STAGE_KV(t + 3);   // writes buffer (t-1)&3 — safe after the barrier

        const uint32_t ukh = sb + OFF_KV + (t & 3) * KVSTG_B;
        const uint32_t uvh = ukh + KTILE_B;

        // ---- S = Q K^T ----
        float sc[4][4];
#pragma unroll
        for (int j = 0; j < 4; j++)
#pragma unroll
            for (int c = 0; c < 4; c++) sc[j][c] = 0.f;

#pragma unroll
        for (int ks = 0; ks < 8; ks++) {
            const uint32_t kb_off = ks * 32 + kcol_off;
            uint32_t qa[4];
            ldm_x4(sb + qrow_off + kb_off, qa[0], qa[1], qa[2], qa[3]);
#pragma unroll
            for (int np = 0; np < 2; np++) {
                uint32_t roff = (np * 16 + (lane & 15)) * QROW_B + kb_off;
                uint32_t r0, r1, r2, r3;
                ldm_x4(ukh + roff, r0, r1, r2, r3);
                mma_f16(sc[2*np][0], sc[2*np][1], sc[2*np][2], sc[2*np][3],
                        qa[0], qa[1], qa[2], qa[3], r0, r2);
                mma_f16(sc[2*np+1][0], sc[2*np+1][1], sc[2*np+1][2], sc[2*np+1][3],
                        qa[0], qa[1], qa[2], qa[3], r1, r3);
            }
        }

        // ---- online softmax ----
        float mx0 = -1e30f, mx1 = -1e30f;
#pragma unroll
        for (int j = 0; j < 4; j++) {
#pragma unroll
            for (int c = 0; c < 4; c++) sc[j][c] *= scale;
            mx0 = fmaxf(mx0, fmaxf(sc[j][0], sc[j][1]));
            mx1 = fmaxf(mx1, fmaxf(sc[j][2], sc[j][3]));
        }
        mx0 = fmaxf(mx0, __shfl_xor_sync(0xffffffffu, mx0, 1));
        mx0 = fmaxf(mx0, __shfl_xor_sync(0xffffffffu, mx0, 2));
        mx1 = fmaxf(mx1, __shfl_xor_sync(0xffffffffu, mx1, 1));
        mx1 = fmaxf(mx1, __shfl_xor_sync(0xffffffffu, mx1, 2));
        float mn0 = fmaxf(m0, mx0), mn1 = fmaxf(m1, mx1);
        float al0 = __expf(m0 - mn0), al1 = __expf(m1 - mn1);
        m0 = mn0; m1 = mn1;
        float rs0 = 0.f, rs1 = 0.f;
#pragma unroll
        for (int j = 0; j < 4; j++) {
            sc[j][0] = __expf(sc[j][0] - m0);
            sc[j][1] = __expf(sc[j][1] - m0);
            sc[j][2] = __expf(sc[j][2] - m1);
            sc[j][3] = __expf(sc[j][3] - m1);
            rs0 += sc[j][0] + sc[j][1];
            rs1 += sc[j][2] + sc[j][3];
        }
        rs0 += __shfl_xor_sync(0xffffffffu, rs0, 1);
        rs0 += __shfl_xor_sync(0xffffffffu, rs0, 2);
        rs1 += __shfl_xor_sync(0xffffffffu, rs1, 1);
        rs1 += __shfl_xor_sync(0xffffffffu, rs1, 2);
        l0v = l0v * al0 + rs0;
        l1v = l1v * al1 + rs1;
#pragma unroll
        for (int tt = 0; tt < 16; tt++) {
            o[tt][0] *= al0; o[tt][1] *= al0;
            o[tt][2] *= al1; o[tt][3] *= al1;
        }

        // ---- O += P V ----
#pragma unroll
        for (int kb = 0; kb < 2; kb++) {
            uint32_t ph0 = packh(sc[2*kb][0],   sc[2*kb][1]);
            uint32_t ph1 = packh(sc[2*kb][2],   sc[2*kb][3]);
            uint32_t ph2 = packh(sc[2*kb+1][0], sc[2*kb+1][1]);
            uint32_t ph3 = packh(sc[2*kb+1][2], sc[2*kb+1][3]);
            const uint32_t kb_off = kb * 32 + kcol_off;
#pragma unroll
            for (int np = 0; np < 8; np++) {
                uint32_t roff = (np * 16 + (lane & 15)) * VROW_B + kb_off;
                uint32_t r0, r1, r2, r3;
                ldm_x4(uvh + roff, r0, r1, r2, r3);
                mma_f16(o[2*np][0], o[2*np][1], o[2*np][2], o[2*np][3],
                        ph0, ph1, ph2, ph3, r0, r2);
                mma_f16(o[2*np+1][0], o[2*np+1][1], o[2*np+1][2], o[2*np+1][3],
                        ph0, ph1, ph2, ph3, r1, r3);
            }
        }
    }
#undef STAGE_KV

    // epilogue: normalize, write fp16 [B,S,HQ,HD]
    float inv0 = 1.0f / l0v, inv1 = 1.0f / l1v;
    int s0 = q0 + warp * 16 + (lane >> 2);
    int s1 = s0 + 8;
    size_t base0 = (((size_t)b * S_ + s0) * HQ_ + h) * HD_ + 2 * (lane & 3);
    size_t base1 = (((size_t)b * S_ + s1) * HQ_ + h) * HD_ + 2 * (lane & 3);
#pragma unroll
    for (int t = 0; t < 16; t++) {
        *(__half2*)(Oh + base0 + 8 * t) =
            __floats2half2_rn(o[t][0] * inv0, o[t][1] * inv0);
        *(__half2*)(Oh + base1 + 8 * t) =
            __floats2half2_rn(o[t][2] * inv1, o[t][3] * inv1);
    }
}

// ---------------------------------------------------------------------------
extern "C" void kernel_launch(void* const* d_in, const int* in_sizes, int n_in,
                              void* d_out, int out_size)
{
    const float* x  = (const float*)d_in[0];
    const float* wq = (const float*)d_in[1];
    const float* wk = (const float*)d_in[2];
    const float* wv = (const float*)d_in[3];
    const float* wo = (const float*)d_in[4];
    const float* fc = (const float*)d_in[5];
    const float* fs = (const float*)d_in[6];
    float* out = (float*)d_out;

    __half *xh, *wqkvh, *woh, *qh, *kh, *vth, *ah;
    cudaGetSymbolAddress((void**)&xh, g_xh);
    cudaGetSymbolAddress((void**)&wqkvh, g_wqkvh);
    cudaGetSymbolAddress((void**)&woh, g_woh);
    cudaGetSymbolAddress((void**)&qh, g_qh);
    cudaGetSymbolAddress((void**)&kh, g_kh);
    cudaGetSymbolAddress((void**)&vth, g_vth);
    cudaGetSymbolAddress((void**)&ah, g_ah);

    const int M = B_ * S_;  // 4096

    // merged converts (one launch)
    conv_all<<<(unsigned)CONV_BLOCKS, 256>>>(x, wq, wk, wv, wo, xh, wqkvh, woh);

    cudaFuncSetAttribute(gemm_fp16, cudaFuncAttributeMaxDynamicSharedMemorySize, GSMEM);

    // fused QKV projection (rope + layout in epilogue; V via smem transpose)
    gemm_fp16<<<dim3(NQKV / 128, M / 128), 256, GSMEM>>>(
        xh, wqkvh, nullptr, qh, kh, vth, M, NQKV, D_, 3, fc, fs);

    // tensor-core attention
    cudaFuncSetAttribute(attn_mma4, cudaFuncAttributeMaxDynamicSharedMemorySize, ATT_SMEM);
    attn_mma4<<<dim3(S_ / QT, B_ * HQ_), 256, ATT_SMEM>>>(qh, kh, vth, ah);

    // output projection -> d_out (fp32)
    gemm_fp16<<<dim3(D_ / 128, M / 128), 256, GSMEM>>>(
        ah, woh, out, nullptr, nullptr, nullptr, M, D_, D_, 0, fc, fs);
}

// round 13
// speedup vs baseline: 7.3578x; 1.0575x over previous
#include <cuda_runtime.h>
#include <cuda_fp16.h>
#include <cstdint>
#include <math.h>

#define B_   2
#define S_   2048
#define D_   4096
#define HQ_  32
#define HKV_ 8
#define HD_  128

// ---------------- scratch (static device globals; no allocations) ----------
__device__ __half g_xh[(size_t)B_ * S_ * D_];                  // x fp16
#define NQKV (HQ_ * HD_ + 2 * HKV_ * HD_)   // 6144
__device__ __half g_wqkvh[(size_t)NQKV * D_];                  // stacked qkv weights
__device__ __half g_woh[(size_t)D_ * HQ_ * HD_];
// rope'd Q, K, transposed V (all fp16)
__device__ __half g_qh[(size_t)B_ * HQ_ * S_ * HD_];   // [B,HQ,S,HD]
__device__ __half g_kh[(size_t)B_ * HKV_ * S_ * HD_];  // [B,HKV,S,HD]
__device__ __half g_vth[(size_t)B_ * HKV_ * HD_ * S_]; // [B,HKV,HD,S]
// attention output (fp16, [B,S,HQ,HD])
__device__ __half g_ah[(size_t)B_ * S_ * HQ_ * HD_];

// ---------------- PTX helpers (family-portable only) -----------------------
__device__ __forceinline__ uint32_t smem_u32(const void* p) {
    uint32_t a;
    asm("{ .reg .u64 t; cvta.to.shared.u64 t, %1; cvt.u32.u64 %0, t; }" : "=r"(a) : "l"(p));
    return a;
}
__device__ __forceinline__ void cp16(uint32_t s, const void* g) {
    asm volatile("cp.async.cg.shared.global [%0], [%1], 16;" :: "r"(s), "l"(g));
}
__device__ __forceinline__ void cp_commit() {
    asm volatile("cp.async.commit_group;" ::: "memory");
}
__device__ __forceinline__ void ldm_x4(uint32_t a, uint32_t& r0, uint32_t& r1,
                                       uint32_t& r2, uint32_t& r3) {
    asm volatile("ldmatrix.sync.aligned.m8n8.x4.shared.b16 {%0,%1,%2,%3}, [%4];"
                 : "=r"(r0), "=r"(r1), "=r"(r2), "=r"(r3) : "r"(a));
}
__device__ __forceinline__ void mma_f16(float& d0, float& d1, float& d2, float& d3,
                                        uint32_t a0, uint32_t a1, uint32_t a2, uint32_t a3,
                                        uint32_t b0, uint32_t b1) {
    asm volatile("mma.sync.aligned.m16n8k16.row.col.f32.f16.f16.f32 "
                 "{%0,%1,%2,%3}, {%4,%5,%6,%7}, {%8,%9}, {%0,%1,%2,%3};"
                 : "+f"(d0), "+f"(d1), "+f"(d2), "+f"(d3)
                 : "r"(a0), "r"(a1), "r"(a2), "r"(a3), "r"(b0), "r"(b1));
}
__device__ __forceinline__ uint32_t packh(float lo, float hi) {
    __half2 t = __floats2half2_rn(lo, hi);
    return *(uint32_t*)&t;
}

// ---------------------------------------------------------------------------
// merged fp32 -> fp16 convert: one launch for x, wq, wk, wv, wo.
// ---------------------------------------------------------------------------
#define N4X 4194304L
#define N4Q 4194304L
#define N4K 1048576L
#define N4O 4194304L
#define CONV_BLOCKS ((N4X + N4Q + 2 * N4K + N4O) / 512)   // 28672

__global__ void conv_all(const float* __restrict__ x,  const float* __restrict__ wq,
                         const float* __restrict__ wk, const float* __restrict__ wv,
                         const float* __restrict__ wo,
                         __half* __restrict__ xh, __half* __restrict__ wqkvh,
                         __half* __restrict__ woh)
{
    long base = (long)blockIdx.x * 512;
    const float* src;
    __half* dst;
    long off;
    if (base < N4X) {
        src = x; dst = xh; off = base;
    } else if (base < N4X + N4Q) {
        src = wq; dst = wqkvh; off = base - N4X;
    } else if (base < N4X + N4Q + N4K) {
        src = wk; dst = wqkvh + (size_t)HQ_ * HD_ * D_; off = base - (N4X + N4Q);
    } else if (base < N4X + N4Q + 2 * N4K) {
        src = wv; dst = wqkvh + (size_t)(HQ_ + HKV_) * HD_ * D_;
        off = base - (N4X + N4Q + N4K);
    } else {
        src = wo; dst = woh; off = base - (N4X + N4Q + 2 * N4K);
    }
    long i0 = off + threadIdx.x;
    long i1 = i0 + 256;
    float4 v0 = ((const float4*)src)[i0];
    float4 v1 = ((const float4*)src)[i1];
    __half2* p0 = (__half2*)(dst + 4 * i0);
    __half2* p1 = (__half2*)(dst + 4 * i1);
    p0[0] = __floats2half2_rn(v0.x, v0.y);
    p0[1] = __floats2half2_rn(v0.z, v0.w);
    p1[0] = __floats2half2_rn(v1.x, v1.y);
    p1[1] = __floats2half2_rn(v1.z, v1.w);
}

// ---------------------------------------------------------------------------
// fp16 GEMM (NT): C = A*B^T, fp32 accum via mma.sync.
// CTA 128x128, K-chunk 64 (4 kk blocks), 8 warps, 2 CTAs/SM,
// 3-stage cp.async pipeline, one __syncthreads per 64-K iteration.
// modes: 0 = fp32 C; 3 = fused QKV epilogue (rope Q/K, V transposed w/
//        smem-transpose coalesced stores).
// ---------------------------------------------------------------------------
#define KCH    64
#define RSTR   72                   // halves per smem row (64 data + 8 pad)
#define TILE_B (128 * RSTR * 2)     // 18432 B
#define STG_B  (2 * TILE_B)         // Ah, Bh  (36864 B)
#define NSTG   3
#define GSMEM  (NSTG * STG_B)       // 110592 B
#define VTP    136                  // padded m-stride for V transpose tile

__global__ __launch_bounds__(256, 2) void gemm_fp16(
    const __half* __restrict__ Ah, const __half* __restrict__ Bh,
    float* __restrict__ Cf,
    __half* __restrict__ Qh, __half* __restrict__ Kh, __half* __restrict__ Vh,
    int M, int N, int K, int mode,
    const float* __restrict__ fc, const float* __restrict__ fs)
{
    extern __shared__ char smem[];
    const uint32_t sb = smem_u32(smem);
    const int tid = threadIdx.x;
    const int lane = tid & 31;
    const int wid = tid >> 5;
    const int wm = wid >> 2;
    const int wn = wid & 3;
    const int bm = blockIdx.y * 128;
    const int bn = blockIdx.x * 128;

    float acc[4][4][4];
#pragma unroll
    for (int i = 0; i < 4; i++)
#pragma unroll
        for (int j = 0; j < 4; j++)
#pragma unroll
            for (int c = 0; c < 4; c++) acc[i][j][c] = 0.f;

    const int iters = K / KCH;
    const int row0 = tid >> 3;      // 0..31 (row within 128, stepped by 32)
    const int col0 = tid & 7;       // 0..7  (16B chunk within 128B row)

    // stage buffer s: [A tile][B tile], row stride RSTR*2 bytes.
#define PREFETCH(it_) do {                                                    \
    if ((it_) < iters) {                                                      \
        const uint32_t sob_ = sb + ((it_) % NSTG) * STG_B;                    \
        const int k0_ = (it_) * KCH;                                          \
        _Pragma("unroll")                                                     \
        for (int j_ = 0; j_ < 4; j_++) {                                      \
            int row_ = row0 + j_ * 32;                                        \
            uint32_t so_ = sob_ + row_ * (RSTR * 2) + col0 * 16;              \
            size_t ga_ = (size_t)(bm + row_) * K + k0_ + col0 * 8;            \
            size_t gb_ = (size_t)(bn + row_) * K + k0_ + col0 * 8;            \
            cp16(so_ + 0 * TILE_B, Ah + ga_);                                 \
            cp16(so_ + 1 * TILE_B, Bh + gb_);                                 \
        }                                                                     \
    }                                                                         \
    cp_commit();                                                              \
} while (0)

    PREFETCH(0);
    PREFETCH(1);

    for (int it = 0; it < iters; it++) {
        asm volatile("cp.async.wait_group 1;" ::: "memory");
        __syncthreads();
        PREFETCH(it + 2);   // writes buffer (it-1)%3 — safe after the barrier

        const uint32_t base = sb + (it % NSTG) * STG_B;
        const uint32_t a_h = base;
        const uint32_t b_h = base + TILE_B;

#pragma unroll
        for (int kk = 0; kk < 4; kk++) {
            const int kc = kk * 16 + (lane >> 4) * 8;
            uint32_t a[4][4], bhf[4][2];
#pragma unroll
            for (int nq = 0; nq < 2; nq++) {
                int row = wn * 32 + nq * 16 + (lane & 15);
                uint32_t off = row * (RSTR * 2) + kc * 2;
                uint32_t r0, r1, r2, r3;
                ldm_x4(b_h + off, r0, r1, r2, r3);
                bhf[nq * 2][0] = r0; bhf[nq * 2][1] = r2;
                bhf[nq * 2 + 1][0] = r1; bhf[nq * 2 + 1][1] = r3;
            }
#pragma unroll
            for (int mf = 0; mf < 4; mf++) {
                int row = wm * 64 + mf * 16 + (lane & 15);
                ldm_x4(a_h + row * (RSTR * 2) + kc * 2,
                       a[mf][0], a[mf][1], a[mf][2], a[mf][3]);
            }
#pragma unroll
            for (int mf = 0; mf < 4; mf++)
#pragma unroll
                for (int nf = 0; nf < 4; nf++)
                    mma_f16(acc[mf][nf][0], acc[mf][nf][1], acc[mf][nf][2], acc[mf][nf][3],
                            a[mf][0], a[mf][1], a[mf][2], a[mf][3],
                            bhf[nf][0], bhf[nf][1]);
        }
    }
#undef PREFETCH

    const int qr = lane >> 2;
    const int qc = lane & 3;

    // ---- V tile: smem transpose then coalesced stores along S ----
    if (mode == 3 && bn >= HQ_ * HD_ + HKV_ * HD_) {
        __syncthreads();                        // smem stage buffers now free
        __half* T = (__half*)smem;              // T[n_local (128)][VTP]
#pragma unroll
        for (int mf = 0; mf < 4; mf++)
#pragma unroll
            for (int half_ = 0; half_ < 2; half_++) {
                int ml = wm * 64 + mf * 16 + qr + half_ * 8;
#pragma unroll
                for (int nf = 0; nf < 4; nf++) {
                    int nl = wn * 32 + nf * 8 + 2 * qc;
                    float2 w = half_ ? make_float2(acc[mf][nf][2], acc[mf][nf][3])
                                     : make_float2(acc[mf][nf][0], acc[mf][nf][1]);
                    T[nl * VTP + ml] = __float2half_rn(w.x);
                    T[(nl + 1) * VTP + ml] = __float2half_rn(w.y);
                }
            }
        __syncthreads();
        int nv0 = bn - (HQ_ * HD_ + HKV_ * HD_);
        int h = nv0 >> 7;
        int b = bm >> 11;
        int s0 = bm & (S_ - 1);
        int r = tid >> 1;                       // d (n_local) 0..127
        int cpart = (tid & 1) * 64;             // half-row of 64 halves
        __half* dst = Vh + (((size_t)b * HKV_ + h) * HD_ + r) * S_ + s0 + cpart;
        const uint4* srcp = (const uint4*)(T + r * VTP + cpart);
#pragma unroll
        for (int u = 0; u < 8; u++)
            ((uint4*)dst)[u] = srcp[u];
        return;
    }

#pragma unroll
    for (int mf = 0; mf < 4; mf++) {
#pragma unroll
        for (int half_ = 0; half_ < 2; half_++) {
            int m = bm + wm * 64 + mf * 16 + qr + half_ * 8;
            if (mode == 0) {
                float* dst = Cf + (size_t)m * N + bn;
#pragma unroll
                for (int nf = 0; nf < 4; nf++) {
                    int n = wn * 32 + nf * 8 + 2 * qc;
                    float2 w = half_ ? make_float2(acc[mf][nf][2], acc[mf][nf][3])
                                     : make_float2(acc[mf][nf][0], acc[mf][nf][1]);
                    *(float2*)(dst + n) = w;
                }
            } else {
                int b = m >> 11;
                int s = m & (S_ - 1);
#pragma unroll
                for (int nf = 0; nf < 4; nf++) {
                    int n = bn + wn * 32 + nf * 8 + 2 * qc;
                    float2 w = half_ ? make_float2(acc[mf][nf][2], acc[mf][nf][3])
                                     : make_float2(acc[mf][nf][0], acc[mf][nf][1]);
                    if (n < HQ_ * HD_) {                    // Q: rope
                        int h = n >> 7;
                        int d = n & (HD_ - 1);
                        int i = d >> 1;
                        float c = fc[s * (HD_ / 2) + i];
                        float sn = fs[s * (HD_ / 2) + i];
                        float x0 = w.x * c - w.y * sn;
                        float x1 = w.x * sn + w.y * c;
                        size_t off = (((size_t)b * HQ_ + h) * S_ + s) * HD_ + d;
                        *(__half2*)(Qh + off) = __floats2half2_rn(x0, x1);
                    } else {                                 // K: rope
                        int nk = n - HQ_ * HD_;
                        int h = nk >> 7;
                        int d = nk & (HD_ - 1);
                        int i = d >> 1;
                        float c = fc[s * (HD_ / 2) + i];
                        float sn = fs[s * (HD_ / 2) + i];
                        float x0 = w.x * c - w.y * sn;
                        float x1 = w.x * sn + w.y * c;
                        size_t off = (((size_t)b * HKV_ + h) * S_ + s) * HD_ + d;
                        *(__half2*)(Kh + off) = __floats2half2_rn(x0, x1);
                    }
                }
            }
        }
    }
}

// ---------------------------------------------------------------------------
// Tensor-core flash attention (fp16 operands, fp32 accum) — unchanged.
// Grid (S/128, B*HQ), block 256 (8 warps), 2 CTAs/SM.
// KT=32, 4-stage KV pipeline, ONE __syncthreads per iteration.
// ---------------------------------------------------------------------------
#define QT 128
#define KT 32
#define QROW_B 272                 // 128 halves + 8 pad
#define VROW_B 80                  // 32 halves + 8 pad
#define QTILE_B (QT * QROW_B)      // 34816
#define KTILE_B (KT * QROW_B)      // 8704
#define VTILE_B (128 * VROW_B)     // 10240
#define KVSTG_B (KTILE_B + VTILE_B)           // 18944
#define OFF_KV  QTILE_B                       // 34816
#define ATT_SMEM (OFF_KV + 4 * KVSTG_B)       // 110592

__global__ __launch_bounds__(256, 2) void attn_mma4(
    const __half* __restrict__ Qh_g,
    const __half* __restrict__ Kh_g,
    const __half* __restrict__ Vh_g,
    __half* __restrict__ Oh)
{
    extern __shared__ char smem[];
    const uint32_t sb = smem_u32(smem);
    const int bh = blockIdx.y;
    const int b = bh >> 5;
    const int h = bh & (HQ_ - 1);
    const int kvh = h >> 2;
    const int q0 = blockIdx.x * QT;
    const int tid = threadIdx.x;
    const int lane = tid & 31;
    const int warp = tid >> 5;

    const __half* qh = Qh_g + (((size_t)b * HQ_ + h) * S_ + q0) * HD_;
    const __half* kh = Kh_g + ((size_t)b * HKV_ + kvh) * S_ * HD_;
    const __half* vh = Vh_g + ((size_t)b * HKV_ + kvh) * HD_ * S_;

    const int T = S_ / KT;   // 64

    // stage Q (its own commit group)
#pragma unroll
    for (int i = 0; i < 8; i++) {
        int lin = tid + i * 256;
        int r = lin >> 4, c = lin & 15;
        cp16(sb + r * QROW_B + c * 16, qh + (size_t)r * HD_ + c * 8);
    }
    cp_commit();

#define STAGE_KV(t_) do {                                                     \
    if ((t_) < T) {                                                           \
        int t0_ = (t_) * KT;                                                  \
        uint32_t kb_ = sb + OFF_KV + ((t_) & 3) * KVSTG_B;                    \
        uint32_t vb_ = kb_ + KTILE_B;                                         \
        _Pragma("unroll")                                                     \
        for (int i_ = 0; i_ < 2; i_++) {                                      \
            int lin_ = tid + i_ * 256;                                        \
            int r_ = lin_ >> 4, c_ = lin_ & 15;                               \
            cp16(kb_ + r_ * QROW_B + c_ * 16, kh + (size_t)(t0_ + r_) * HD_ + c_ * 8); \
            int d_ = lin_ >> 2, c2_ = lin_ & 3;                               \
            cp16(vb_ + d_ * VROW_B + c2_ * 16, vh + (size_t)d_ * S_ + t0_ + c2_ * 8); \
        }                                                                     \
    }                                                                         \
    cp_commit();                                                              \
} while (0)

    STAGE_KV(0);
    STAGE_KV(1);
    STAGE_KV(2);

    float o[16][4];
#pragma unroll
    for (int t = 0; t < 16; t++)
#pragma unroll
        for (int c = 0; c < 4; c++) o[t][c] = 0.f;
    float m0 = -1e30f, m1 = -1e30f, l0v = 0.f, l1v = 0.f;

    const float scale = 0.08838834764831845f;   // 1/sqrt(128)
    const uint32_t qrow_off = (warp * 16 + (lane & 15)) * QROW_B;
    const uint32_t kcol_off = (lane >> 4) * 16;

    for (int t = 0; t < T; t++) {
        asm volatile("cp.async.wait_group 2;" ::: "memory");
        __syncthreads();
        STAGE_KV(t + 3);

        const uint32_t ukh = sb + OFF_KV + (t & 3) * KVSTG_B;
        const uint32_t uvh = ukh + KTILE_B;

        // ---- S = Q K^T ----
        float sc[4][4];
#pragma unroll
        for (int j = 0; j < 4; j++)
#pragma unroll
            for (int c = 0; c < 4; c++) sc[j][c] = 0.f;

#pragma unroll
        for (int ks = 0; ks < 8; ks++) {
            const uint32_t kb_off = ks * 32 + kcol_off;
            uint32_t qa[4];
            ldm_x4(sb + qrow_off + kb_off, qa[0], qa[1], qa[2], qa[3]);
#pragma unroll
            for (int np = 0; np < 2; np++) {
                uint32_t roff = (np * 16 + (lane & 15)) * QROW_B + kb_off;
                uint32_t r0, r1, r2, r3;
                ldm_x4(ukh + roff, r0, r1, r2, r3);
                mma_f16(sc[2*np][0], sc[2*np][1], sc[2*np][2], sc[2*np][3],
                        qa[0], qa[1], qa[2], qa[3], r0, r2);
                mma_f16(sc[2*np+1][0], sc[2*np+1][1], sc[2*np+1][2], sc[2*np+1][3],
                        qa[0], qa[1], qa[2], qa[3], r1, r3);
            }
        }

        // ---- online softmax ----
        float mx0 = -1e30f, mx1 = -1e30f;
#pragma unroll
        for (int j = 0; j < 4; j++) {
#pragma unroll
            for (int c = 0; c < 4; c++) sc[j][c] *= scale;
            mx0 = fmaxf(mx0, fmaxf(sc[j][0], sc[j][1]));
            mx1 = fmaxf(mx1, fmaxf(sc[j][2], sc[j][3]));
        }
        mx0 = fmaxf(mx0, __shfl_xor_sync(0xffffffffu, mx0, 1));
        mx0 = fmaxf(mx0, __shfl_xor_sync(0xffffffffu, mx0, 2));
        mx1 = fmaxf(mx1, __shfl_xor_sync(0xffffffffu, mx1, 1));
        mx1 = fmaxf(mx1, __shfl_xor_sync(0xffffffffu, mx1, 2));
        float mn0 = fmaxf(m0, mx0), mn1 = fmaxf(m1, mx1);
        float al0 = __expf(m0 - mn0), al1 = __expf(m1 - mn1);
        m0 = mn0; m1 = mn1;
        float rs0 = 0.f, rs1 = 0.f;
#pragma unroll
        for (int j = 0; j < 4; j++) {
            sc[j][0] = __expf(sc[j][0] - m0);
            sc[j][1] = __expf(sc[j][1] - m0);
            sc[j][2] = __expf(sc[j][2] - m1);
            sc[j][3] = __expf(sc[j][3] - m1);
            rs0 += sc[j][0] + sc[j][1];
            rs1 += sc[j][2] + sc[j][3];
        }
        rs0 += __shfl_xor_sync(0xffffffffu, rs0, 1);
        rs0 += __shfl_xor_sync(0xffffffffu, rs0, 2);
        rs1 += __shfl_xor_sync(0xffffffffu, rs1, 1);
        rs1 += __shfl_xor_sync(0xffffffffu, rs1, 2);
        l0v = l0v * al0 + rs0;
        l1v = l1v * al1 + rs1;
#pragma unroll
        for (int tt = 0; tt < 16; tt++) {
            o[tt][0] *= al0; o[tt][1] *= al0;
            o[tt][2] *= al1; o[tt][3] *= al1;
        }

        // ---- O += P V ----
#pragma unroll
        for (int kb = 0; kb < 2; kb++) {
            uint32_t ph0 = packh(sc[2*kb][0],   sc[2*kb][1]);
            uint32_t ph1 = packh(sc[2*kb][2],   sc[2*kb][3]);
            uint32_t ph2 = packh(sc[2*kb+1][0], sc[2*kb+1][1]);
            uint32_t ph3 = packh(sc[2*kb+1][2], sc[2*kb+1][3]);
            const uint32_t kb_off = kb * 32 + kcol_off;
#pragma unroll
            for (int np = 0; np < 8; np++) {
                uint32_t roff = (np * 16 + (lane & 15)) * VROW_B + kb_off;
                uint32_t r0, r1, r2, r3;
                ldm_x4(uvh + roff, r0, r1, r2, r3);
                mma_f16(o[2*np][0], o[2*np][1], o[2*np][2], o[2*np][3],
                        ph0, ph1, ph2, ph3, r0, r2);
                mma_f16(o[2*np+1][0], o[2*np+1][1], o[2*np+1][2], o[2*np+1][3],
                        ph0, ph1, ph2, ph3, r1, r3);
            }
        }
    }
#undef STAGE_KV

    // epilogue: normalize, write fp16 [B,S,HQ,HD]
    float inv0 = 1.0f / l0v, inv1 = 1.0f / l1v;
    int s0 = q0 + warp * 16 + (lane >> 2);
    int s1 = s0 + 8;
    size_t base0 = (((size_t)b * S_ + s0) * HQ_ + h) * HD_ + 2 * (lane & 3);
    size_t base1 = (((size_t)b * S_ + s1) * HQ_ + h) * HD_ + 2 * (lane & 3);
#pragma unroll
    for (int t = 0; t < 16; t++) {
        *(__half2*)(Oh + base0 + 8 * t) =
            __floats2half2_rn(o[t][0] * inv0, o[t][1] * inv0);
        *(__half2*)(Oh + base1 + 8 * t) =
            __floats2half2_rn(o[t][2] * inv1, o[t][3] * inv1);
    }
}

// ---------------------------------------------------------------------------
extern "C" void kernel_launch(void* const* d_in, const int* in_sizes, int n_in,
                              void* d_out, int out_size)
{
    const float* x  = (const float*)d_in[0];
    const float* wq = (const float*)d_in[1];
    const float* wk = (const float*)d_in[2];
    const float* wv = (const float*)d_in[3];
    const float* wo = (const float*)d_in[4];
    const float* fc = (const float*)d_in[5];
    const float* fs = (const float*)d_in[6];
    float* out = (float*)d_out;

    __half *xh, *wqkvh, *woh, *qh, *kh, *vth, *ah;
    cudaGetSymbolAddress((void**)&xh, g_xh);
    cudaGetSymbolAddress((void**)&wqkvh, g_wqkvh);
    cudaGetSymbolAddress((void**)&woh, g_woh);
    cudaGetSymbolAddress((void**)&qh, g_qh);
    cudaGetSymbolAddress((void**)&kh, g_kh);
    cudaGetSymbolAddress((void**)&vth, g_vth);
    cudaGetSymbolAddress((void**)&ah, g_ah);

    const int M = B_ * S_;  // 4096

    // merged converts (one launch)
    conv_all<<<(unsigned)CONV_BLOCKS, 256>>>(x, wq, wk, wv, wo, xh, wqkvh, woh);

    cudaFuncSetAttribute(gemm_fp16, cudaFuncAttributeMaxDynamicSharedMemorySize, GSMEM);

    // fused QKV projection (rope + layout in epilogue; V via smem transpose)
    gemm_fp16<<<dim3(NQKV / 128, M / 128), 256, GSMEM>>>(
        xh, wqkvh, nullptr, qh, kh, vth, M, NQKV, D_, 3, fc, fs);

    // tensor-core attention
    cudaFuncSetAttribute(attn_mma4, cudaFuncAttributeMaxDynamicSharedMemorySize, ATT_SMEM);
    attn_mma4<<<dim3(S_ / QT, B_ * HQ_), 256, ATT_SMEM>>>(qh, kh, vth, ah);

    // output projection -> d_out (fp32)
    gemm_fp16<<<dim3(D_ / 128, M / 128), 256, GSMEM>>>(
        ah, woh, out, nullptr, nullptr, nullptr, M, D_, D_, 0, fc, fs);
}